// round 5
// baseline (speedup 1.0000x reference)
#include <cuda_runtime.h>
#include <math.h>

#define B_ 2
#define T_ 4096
#define C_ 192
#define NTOT (B_*T_*C_)

// ---------------- scratch ----------------
__device__ float g_Wf[384*576];
__device__ float g_Wp[192*32];
__device__ float g_P[B_*T_*32];
__device__ float g_gb[B_*4*T_];
__device__ float g_peak[NTOT];
__device__ float g_kT[NTOT];
__device__ float g_vT[NTOT];
__device__ float g_yT[NTOT];
__device__ float g_sr[NTOT];

__constant__ float c_prfx[16] = {-2,-2,-2,-2, -2,-1,0,1,  2,2,2,2,  -1,0,1,2};
__constant__ float c_prfy[16] = {-2,-1,0,1,   2,2,2,2,  -1,0,1,2,  -2,-2,-2,-2};

__device__ __forceinline__ unsigned f2tf32(float x) {
    unsigned r;
    asm("cvt.rna.tf32.f32 %0, %1;" : "=r"(r) : "f"(x));
    return r;
}

__device__ __forceinline__ void split_tf32(float x, unsigned& hi, unsigned& lo) {
    unsigned h = f2tf32(x);
    hi = h;
    lo = f2tf32(x - __uint_as_float(h));
}

__device__ __forceinline__ void mma8(float* d, unsigned a0, unsigned a1, unsigned a2, unsigned a3,
                                     unsigned b0, unsigned b1) {
    asm volatile(
        "mma.sync.aligned.m16n8k8.row.col.f32.tf32.tf32.f32 "
        "{%0,%1,%2,%3}, {%4,%5,%6,%7}, {%8,%9}, {%0,%1,%2,%3};\n"
        : "+f"(d[0]), "+f"(d[1]), "+f"(d[2]), "+f"(d[3])
        : "r"(a0), "r"(a1), "r"(a2), "r"(a3), "r"(b0), "r"(b1));
}

// ---------------- weight prep: fused mix-weights + conv weights ----------------
__global__ void wprep_kernel(const float* __restrict__ mk, const float* __restrict__ mv,
                             const float* __restrict__ mr,
                             const float* __restrict__ Wk, const float* __restrict__ Wv,
                             const float* __restrict__ Wr,
                             const float* __restrict__ cvw, const float* __restrict__ chw) {
    int i = blockIdx.x * 256 + threadIdx.x;
    if (i < 384*576) {
        int row = i / 576, n = i % 576;
        int c = row % 192;
        bool second = row >= 192;
        const float* W; float m; int nn;
        if (n < 192)      { W = Wk; m = mk[c]; nn = n; }
        else if (n < 384) { W = Wv; m = mv[c]; nn = n - 192; }
        else              { W = Wr; m = mr[c]; nn = n - 384; }
        g_Wf[i] = (second ? (1.f - m) : m) * W[c*192 + nn];
    } else {
        int j = i - 384*576;
        if (j < 192*32) {
            int c = j / 32, n = j % 32;
            float v = 0.f;
            if (n < 14)      v = cvw[(n/7)*C_*7 + c*7 + (n%7)];
            else if (n < 28) { int n2 = n - 14; v = chw[(n2/7)*C_*7 + c*7 + (n2%7)]; }
            g_Wp[j] = v;
        }
    }
}

// ---------------- conv taps fp32 exact: P[8192][28] = x @ Wp ----------------
__global__ __launch_bounds__(256) void convP_kernel(const float* __restrict__ x) {
    __shared__ float xs[8][193];
    int tid = threadIdx.x;
    int tok0 = blockIdx.x * 8;
    for (int i = tid; i < 8*192; i += 256) {
        int r = i / 192, c = i % 192;
        xs[r][c] = x[(size_t)(tok0 + r)*C_ + c];
    }
    __syncthreads();
    int r = tid >> 5, n = tid & 31;
    if (n < 28) {
        float acc = 0.f;
#pragma unroll 8
        for (int c = 0; c < 192; c++)
            acc = fmaf(xs[r][c], g_Wp[c*32 + n], acc);
        g_P[(size_t)(tok0 + r)*32 + n] = acc;
    }
}

// ---------------- combine conv taps -> gb (fp32 exact) ----------------
__global__ void gb_combine_kernel(const float* __restrict__ cvb, const float* __restrict__ bns_v,
                                  const float* __restrict__ bnb_v, const float* __restrict__ chb,
                                  const float* __restrict__ bns_h, const float* __restrict__ bnb_h) {
    int i = blockIdx.x * 256 + threadIdx.x;
    int b = i >> 12, tt = i & 4095;
    int hh = tt >> 6, ww = tt & 63;
    const float* Pb = g_P + (size_t)b * T_ * 32;
    float gv0 = 0.f, gv1 = 0.f, gh0 = 0.f, gh1 = 0.f;
#pragma unroll
    for (int r = 0; r < 7; r++) {
        int hy = hh + r - 3;
        if (hy >= 0 && hy < 64) {
            const float* p = &Pb[(size_t)(hy*64 + ww)*32];
            gv0 += p[r]; gv1 += p[7 + r];
        }
        int wy = ww + r - 3;
        if (wy >= 0 && wy < 64) {
            const float* p = &Pb[(size_t)(hh*64 + wy)*32];
            gh0 += p[14 + r]; gh1 += p[21 + r];
        }
    }
    const float inv = rsqrtf(1.f + 1e-5f);
    float vals[4] = {gv0, gv1, gh0, gh1};
    float biases[4] = {cvb[0], cvb[1], chb[0], chb[1]};
    float scales[4] = {bns_v[0], bns_v[1], bns_h[0], bns_h[1]};
    float shifts[4] = {bnb_v[0], bnb_v[1], bnb_h[0], bnb_h[1]};
#pragma unroll
    for (int j = 0; j < 4; j++) {
        float val = (vals[j] + biases[j]) * (scales[j] * inv) + shifts[j];
        g_gb[((size_t)b*4 + j)*T_ + tt] = 2.f / (1.f + expf(-val));
    }
}

// ---------------- adaptive peak: peak = x - mean_16(ring gather) ----------------
__global__ __launch_bounds__(96) void peak_kernel(const float* __restrict__ x) {
    int bi = blockIdx.x;
    int b = bi >> 9;
    int tb = (bi & 511) * 8;
    int hh = tb >> 6, wwb = tb & 63;
    __shared__ int   s_lt[8][16], s_rb[8][16];
    __shared__ float s_wlt[8][16], s_wrb[8][16];
    int tid = threadIdx.x;
    const float* gbp = g_gb + (size_t)b*4*T_;
    for (int item = tid; item < 128; item += 96) {
        int j = item >> 4, o = item & 15;
        int tt = tb + j, ww = wwb + j;
        int blk = o >> 2;
        float mx = 0.f, my = 0.f;
        if (blk == 0)      mx = -gbp[tt];
        else if (blk == 1) my =  gbp[3*T_ + tt];
        else if (blk == 2) mx =  gbp[T_ + tt];
        else               my = -gbp[2*T_ + tt];
        float px = (float)(hh + 2) + c_prfx[o] + mx;
        float py = (float)(ww + 2) + c_prfy[o] + my;
        float flx = floorf(px), fly = floorf(py);
        float qltx = fminf(fmaxf(flx,     0.f), 67.f);
        float qlty = fminf(fmaxf(fly,     0.f), 67.f);
        float qrbx = fminf(fmaxf(flx+1.f, 0.f), 67.f);
        float qrby = fminf(fmaxf(fly+1.f, 0.f), 67.f);
        float pxc  = fminf(fmaxf(px,      0.f), 67.f);
        float pyc  = fminf(fmaxf(py,      0.f), 67.f);
        float glt = (1.f + (qltx - pxc)) * (1.f + (qlty - pyc));
        float grb = (1.f - (qrbx - pxc)) * (1.f - (qrby - pyc));
        int rlt = min(max((int)qltx - 2, 0), 63);
        int clt = min(max((int)qlty - 2, 0), 63);
        int rrb = min(max((int)qrbx - 2, 0), 63);
        int crb = min(max((int)qrby - 2, 0), 63);
        s_lt[j][o] = rlt*64 + clt;  s_rb[j][o] = rrb*64 + crb;
        s_wlt[j][o] = glt;          s_wrb[j][o] = grb;
    }
    __syncthreads();
    const float* xb = x + (size_t)b * T_ * C_;
    int c2 = tid * 2;
#pragma unroll 4
    for (int j = 0; j < 8; j++) {
        float acc0 = 0.f, acc1 = 0.f;
#pragma unroll
        for (int o = 0; o < 16; o++) {
            float2 a = *(const float2*)&xb[(size_t)s_lt[j][o]*C_ + c2];
            float2 bvl = *(const float2*)&xb[(size_t)s_rb[j][o]*C_ + c2];
            float wl = s_wlt[j][o], wr = s_wrb[j][o];
            acc0 += wl*a.x + wr*bvl.x;
            acc1 += wl*a.y + wr*bvl.y;
        }
        size_t idx = ((size_t)b*T_ + tb + j)*C_ + c2;
        float2 xc = *(const float2*)&x[idx];
        *(float2*)&g_peak[idx] = make_float2(xc.x - acc0*(1.f/16.f), xc.y - acc1*(1.f/16.f));
    }
}

// ---------------- fused front GEMM (3xTF32): [k|v|r] = [x | qshift(x)] @ Wf ----------------
#define AS_STRIDE 36
#define BS_STRIDE 68

__device__ __forceinline__ float4 loadAx(const float* __restrict__ x, int gt, int hh, int ww, int k) {
    if (k < 192) return *(const float4*)&x[(size_t)gt*C_ + k];
    int c = k - 192;
    int g = c / 48;
    int src; bool ok;
    if (g == 0)      { ok = (ww >= 1);  src = gt - 1; }
    else if (g == 1) { ok = (ww <= 62); src = gt + 1; }
    else if (g == 2) { ok = (hh >= 1);  src = gt - 64; }
    else             { ok = (hh <= 62); src = gt + 64; }
    if (!ok) return make_float4(0.f, 0.f, 0.f, 0.f);
    return *(const float4*)&x[(size_t)src*C_ + c];
}

__global__ __launch_bounds__(128) void gemm1_kernel(const float* __restrict__ x) {
    __shared__ float As[2][64 * AS_STRIDE];
    __shared__ float Bs[2][32 * BS_STRIDE];

    int tid = threadIdx.x;
    int warp = tid >> 5, lane = tid & 31;
    int bm = blockIdx.x * 64;
    int bn = blockIdx.y * 64;
    int cls = blockIdx.y / 3;            // 0:k 1:v 2:r
    int nloc = bn - cls * 192;
    int wm = (warp >> 1) * 32;
    int wn = (warp & 1) * 32;
    int gid = lane >> 2, tig = lane & 3;

    int ar = tid >> 3;
    int ac = (tid & 7) * 4;
    int br = tid >> 4;
    int bc = (tid & 15) * 4;

    int gtr[4], hr[4], wr[4];
#pragma unroll
    for (int i = 0; i < 4; i++) {
        int gt = bm + ar + i*16;
        gtr[i] = gt;
        int tt = gt & 4095;
        hr[i] = tt >> 6; wr[i] = tt & 63;
    }

    float acc[2][4][4] = {};

    float4 pa[4], pb[4];
#pragma unroll
    for (int i = 0; i < 4; i++) pa[i] = loadAx(x, gtr[i], hr[i], wr[i], ac);
#pragma unroll
    for (int i = 0; i < 4; i++) pb[i] = *(const float4*)&g_Wf[(size_t)(br + i*8)*576 + bn + bc];

#pragma unroll
    for (int i = 0; i < 4; i++)
        *(float4*)&As[0][(ar + i*16)*AS_STRIDE + ac] = pa[i];
#pragma unroll
    for (int i = 0; i < 4; i++)
        *(float4*)&Bs[0][(br + i*8)*BS_STRIDE + bc] = pb[i];
    __syncthreads();

    for (int kc = 0; kc < 12; kc++) {
        int cur = kc & 1;
        if (kc < 11) {
            int k0 = (kc + 1) * 32;
#pragma unroll
            for (int i = 0; i < 4; i++) pa[i] = loadAx(x, gtr[i], hr[i], wr[i], k0 + ac);
#pragma unroll
            for (int i = 0; i < 4; i++) pb[i] = *(const float4*)&g_Wf[(size_t)(k0 + br + i*8)*576 + bn + bc];
        }
        const float* as = As[cur];
        const float* bs = Bs[cur];
#pragma unroll
        for (int ks = 0; ks < 4; ks++) {
            int kk0 = ks * 8;
            unsigned ah[2][4], al[2][4], bh[4][2], bl[4][2];
#pragma unroll
            for (int mi = 0; mi < 2; mi++) {
                int rbase = (wm + mi*16 + gid) * AS_STRIDE;
                split_tf32(as[rbase + kk0 + tig],                 ah[mi][0], al[mi][0]);
                split_tf32(as[rbase + 8*AS_STRIDE + kk0 + tig],   ah[mi][1], al[mi][1]);
                split_tf32(as[rbase + kk0 + tig + 4],             ah[mi][2], al[mi][2]);
                split_tf32(as[rbase + 8*AS_STRIDE + kk0 + tig+4], ah[mi][3], al[mi][3]);
            }
#pragma unroll
            for (int ni = 0; ni < 4; ni++) {
                int col = wn + ni*8 + gid;
                split_tf32(bs[(kk0 + tig)*BS_STRIDE + col],     bh[ni][0], bl[ni][0]);
                split_tf32(bs[(kk0 + tig + 4)*BS_STRIDE + col], bh[ni][1], bl[ni][1]);
            }
#pragma unroll
            for (int mi = 0; mi < 2; mi++)
#pragma unroll
                for (int ni = 0; ni < 4; ni++) {
                    mma8(acc[mi][ni], ah[mi][0], ah[mi][1], ah[mi][2], ah[mi][3],
                         bl[ni][0], bl[ni][1]);
                    mma8(acc[mi][ni], al[mi][0], al[mi][1], al[mi][2], al[mi][3],
                         bh[ni][0], bh[ni][1]);
                    mma8(acc[mi][ni], ah[mi][0], ah[mi][1], ah[mi][2], ah[mi][3],
                         bh[ni][0], bh[ni][1]);
                }
        }
        if (kc < 11) {
            __syncthreads();
            int nxt = cur ^ 1;
#pragma unroll
            for (int i = 0; i < 4; i++)
                *(float4*)&As[nxt][(ar + i*16)*AS_STRIDE + ac] = pa[i];
#pragma unroll
            for (int i = 0; i < 4; i++)
                *(float4*)&Bs[nxt][(br + i*8)*BS_STRIDE + bc] = pb[i];
            __syncthreads();
        }
    }

    if (cls == 2) {
#pragma unroll
        for (int mi = 0; mi < 2; mi++) {
            int r0 = bm + wm + mi*16 + gid;
#pragma unroll
            for (int ni = 0; ni < 4; ni++) {
                int c0 = nloc + wn + ni*8 + tig*2;
                float v0 = 1.f/(1.f+expf(-acc[mi][ni][0]));
                float v1 = 1.f/(1.f+expf(-acc[mi][ni][1]));
                float v2 = 1.f/(1.f+expf(-acc[mi][ni][2]));
                float v3 = 1.f/(1.f+expf(-acc[mi][ni][3]));
                *(float2*)&g_sr[(size_t)r0*C_ + c0]     = make_float2(v0, v1);
                *(float2*)&g_sr[(size_t)(r0+8)*C_ + c0] = make_float2(v2, v3);
            }
        }
        return;
    }

    if (cls == 1) {
#pragma unroll
        for (int mi = 0; mi < 2; mi++) {
            int r0 = bm + wm + mi*16 + gid;
#pragma unroll
            for (int ni = 0; ni < 4; ni++) {
                int cg = nloc + wn + ni*8 + tig*2;
                float2 p0 = *(const float2*)&g_peak[(size_t)r0*C_ + cg];
                float2 p1 = *(const float2*)&g_peak[(size_t)(r0+8)*C_ + cg];
                acc[mi][ni][0] += p0.x; acc[mi][ni][1] += p0.y;
                acc[mi][ni][2] += p1.x; acc[mi][ni][3] += p1.y;
            }
        }
    }

    // transpose-write to kT / vT
    __syncthreads();
    float* st = &As[0][0];    // 64 x 65 stage
#pragma unroll
    for (int mi = 0; mi < 2; mi++) {
        int r = wm + mi*16 + gid;
#pragma unroll
        for (int ni = 0; ni < 4; ni++) {
            int cc = wn + ni*8 + tig*2;
            st[r*65 + cc]       = acc[mi][ni][0];
            st[r*65 + cc + 1]   = acc[mi][ni][1];
            st[(r+8)*65 + cc]   = acc[mi][ni][2];
            st[(r+8)*65 + cc+1] = acc[mi][ni][3];
        }
    }
    __syncthreads();
    float* dst = (cls == 0) ? g_kT : g_vT;
    int bb = bm >> 12, trow = bm & 4095;
    int f4 = tid & 15, rsub = tid >> 4;
#pragma unroll
    for (int q = 0; q < 8; q++) {
        int cr = q*8 + rsub;
        int t0 = f4*4;
        float4 v;
        v.x = st[(t0+0)*65 + cr];
        v.y = st[(t0+1)*65 + cr];
        v.z = st[(t0+2)*65 + cr];
        v.w = st[(t0+3)*65 + cr];
        *(float4*)&dst[((size_t)(bb*C_ + nloc + cr))*T_ + trow + t0] = v;
    }
}

// ---------------- bidirectional WKV scan ----------------
struct Agg { float a, b, dl; };
__device__ __forceinline__ Agg combine(Agg p, Agg s) {
    Agg r;
    r.a  = fmaf(s.dl, p.a, s.a);
    r.b  = fmaf(s.dl, p.b, s.b);
    r.dl = p.dl * s.dl;
    return r;
}
__device__ __forceinline__ Agg shfl_up_agg(Agg v, int off) {
    Agg r;
    r.a  = __shfl_up_sync(0xffffffffu, v.a,  off);
    r.b  = __shfl_up_sync(0xffffffffu, v.b,  off);
    r.dl = __shfl_up_sync(0xffffffffu, v.dl, off);
    return r;
}
__device__ __forceinline__ Agg shfl_dn_agg(Agg v, int off) {
    Agg r;
    r.a  = __shfl_down_sync(0xffffffffu, v.a,  off);
    r.b  = __shfl_down_sync(0xffffffffu, v.b,  off);
    r.dl = __shfl_down_sync(0xffffffffu, v.dl, off);
    return r;
}

__global__ __launch_bounds__(256) void wkv_kernel(const float* __restrict__ sd,
                                                  const float* __restrict__ sf) {
    __shared__ Agg warpAgg[8];
    __shared__ Agg warpPre[8];
    int bc = blockIdx.x;
    int c = bc % C_;
    float w  = sd[c] * (1.0f / T_);
    float u  = sf[c] * (1.0f / T_);
    float d  = expf(-w);
    float eu = expf(u);
    float d2 = d*d, d4 = d2*d2, d8 = d4*d4, d16 = d8*d8;
    int tid = threadIdx.x;
    int lane = tid & 31, wid = tid >> 5;
    const float* kp = g_kT + (size_t)bc * T_;
    const float* vp = g_vT + (size_t)bc * T_;
    float* yp = g_yT + (size_t)bc * T_;
    int t0 = tid * 16;

    float ek[16], vv[16];
#pragma unroll
    for (int i = 0; i < 16; i++) {
        ek[i] = expf(kp[t0 + i]);
        vv[i] = vp[t0 + i];
    }

    Agg ag; ag.a = 0.f; ag.b = 0.f; ag.dl = d16;
#pragma unroll
    for (int i = 0; i < 16; i++) {
        ag.a = fmaf(d, ag.a, ek[i]);
        ag.b = fmaf(d, ag.b, ek[i]*vv[i]);
    }
    Agg inc = ag;
#pragma unroll
    for (int off = 1; off < 32; off <<= 1) {
        Agg o = shfl_up_agg(inc, off);
        if (lane >= off) inc = combine(o, inc);
    }
    if (lane == 31) warpAgg[wid] = inc;
    __syncthreads();
    if (tid == 0) {
        Agg run; run.a = 0.f; run.b = 0.f; run.dl = 1.f;
        for (int i = 0; i < 8; i++) { warpPre[i] = run; run = combine(run, warpAgg[i]); }
    }
    __syncthreads();
    Agg pl = shfl_up_agg(inc, 1);
    Agg ex = warpPre[wid];
    if (lane > 0) ex = combine(ex, pl);

    float af = ex.a, bf = ex.b;
    float saf[16], sbf[16];
#pragma unroll
    for (int i = 0; i < 16; i++) {
        saf[i] = af; sbf[i] = bf;
        af = fmaf(d, af, ek[i]);
        bf = fmaf(d, bf, ek[i]*vv[i]);
    }
    __syncthreads();

    Agg bg; bg.a = 0.f; bg.b = 0.f; bg.dl = d16;
#pragma unroll
    for (int i = 15; i >= 0; i--) {
        bg.a = fmaf(d, bg.a, ek[i]);
        bg.b = fmaf(d, bg.b, ek[i]*vv[i]);
    }
    Agg binc = bg;
#pragma unroll
    for (int off = 1; off < 32; off <<= 1) {
        Agg o = shfl_dn_agg(binc, off);
        if (lane < 32 - off) binc = combine(o, binc);
    }
    if (lane == 0) warpAgg[wid] = binc;
    __syncthreads();
    if (tid == 0) {
        Agg run; run.a = 0.f; run.b = 0.f; run.dl = 1.f;
        for (int i = 7; i >= 0; i--) { warpPre[i] = run; run = combine(run, warpAgg[i]); }
    }
    __syncthreads();
    Agg bpl = shfl_dn_agg(binc, 1);
    Agg bex = warpPre[wid];
    if (lane < 31) bex = combine(bex, bpl);

    float ab = bex.a, bb = bex.b;
#pragma unroll
    for (int i = 15; i >= 0; i--) {
        float es  = eu * ek[i];
        float num = sbf[i] + bb + es * vv[i];
        float den = saf[i] + ab + es;
        yp[t0 + i] = num / den;
        ab = fmaf(d, ab, ek[i]);
        bb = fmaf(d, bb, ek[i]*vv[i]);
    }
}

// ---------------- output GEMM (3xTF32): out = (sr .* y) @ Wo ----------------
#define A2_STRIDE 197

__global__ __launch_bounds__(128) void gemm2_kernel(const float* __restrict__ Wo,
                                                    float* __restrict__ out) {
    __shared__ float As2[32 * A2_STRIDE];
    __shared__ float Bs2[2][32 * BS_STRIDE];

    int tid = threadIdx.x;
    int warp = tid >> 5, lane = tid & 31;
    int gid = lane >> 2, tig = lane & 3;
    int bm = blockIdx.x * 32;
    int bn = blockIdx.y * 64;
    int wm = (warp >> 1) * 16;
    int wn = (warp & 1) * 32;
    int bb = bm >> 12, trow = bm & 4095;

    // stage A: yT (c,t) -> As2[t][c]
#pragma unroll
    for (int q = 0; q < 12; q++) {
        int f = q*128 + tid;
        int row = f >> 3;
        int t4 = (f & 7) * 4;
        float4 v = *(const float4*)&g_yT[((size_t)(bb*C_ + row))*T_ + trow + t4];
        As2[(t4+0)*A2_STRIDE + row] = v.x;
        As2[(t4+1)*A2_STRIDE + row] = v.y;
        As2[(t4+2)*A2_STRIDE + row] = v.z;
        As2[(t4+3)*A2_STRIDE + row] = v.w;
    }
    __syncthreads();
#pragma unroll
    for (int q = 0; q < 12; q++) {
        int f = q*128 + tid;
        int t = f / 48, c4 = (f % 48) * 4;
        float4 s = *(const float4*)&g_sr[((size_t)(bm + t))*C_ + c4];
        float* p = &As2[t*A2_STRIDE + c4];
        p[0] *= s.x; p[1] *= s.y; p[2] *= s.z; p[3] *= s.w;
    }

    int br = tid >> 4;
    int bc = (tid & 15) * 4;
    float acc[4][4] = {};

    float4 pb[4];
#pragma unroll
    for (int i = 0; i < 4; i++)
        pb[i] = *(const float4*)&Wo[(size_t)(br + i*8)*C_ + bn + bc];
#pragma unroll
    for (int i = 0; i < 4; i++)
        *(float4*)&Bs2[0][(br + i*8)*BS_STRIDE + bc] = pb[i];
    __syncthreads();

    for (int kc = 0; kc < 6; kc++) {
        int cur = kc & 1;
        if (kc < 5) {
            int k0 = (kc + 1) * 32;
#pragma unroll
            for (int i = 0; i < 4; i++)
                pb[i] = *(const float4*)&Wo[(size_t)(k0 + br + i*8)*C_ + bn + bc];
        }
        const float* bs = Bs2[cur];
        int k0 = kc * 32;
#pragma unroll
        for (int ks = 0; ks < 4; ks++) {
            int kk = k0 + ks*8;
            unsigned ah[4], al[4];
            split_tf32(As2[(wm+gid)*A2_STRIDE + kk + tig],       ah[0], al[0]);
            split_tf32(As2[(wm+gid+8)*A2_STRIDE + kk + tig],     ah[1], al[1]);
            split_tf32(As2[(wm+gid)*A2_STRIDE + kk + tig + 4],   ah[2], al[2]);
            split_tf32(As2[(wm+gid+8)*A2_STRIDE + kk + tig + 4], ah[3], al[3]);
#pragma unroll
            for (int ni = 0; ni < 4; ni++) {
                int col = wn + ni*8 + gid;
                unsigned bh0, bl0, bh1, bl1;
                split_tf32(bs[(ks*8 + tig)*BS_STRIDE + col],     bh0, bl0);
                split_tf32(bs[(ks*8 + tig + 4)*BS_STRIDE + col], bh1, bl1);
                mma8(acc[ni], ah[0], ah[1], ah[2], ah[3], bl0, bl1);
                mma8(acc[ni], al[0], al[1], al[2], al[3], bh0, bh1);
                mma8(acc[ni], ah[0], ah[1], ah[2], ah[3], bh0, bh1);
            }
        }
        if (kc < 5) {
            __syncthreads();
            int nxt = cur ^ 1;
#pragma unroll
            for (int i = 0; i < 4; i++)
                *(float4*)&Bs2[nxt][(br + i*8)*BS_STRIDE + bc] = pb[i];
            __syncthreads();
        }
    }

    int r0 = bm + wm + gid;
#pragma unroll
    for (int ni = 0; ni < 4; ni++) {
        int c0 = bn + wn + ni*8 + tig*2;
        *(float2*)&out[(size_t)r0*C_ + c0]     = make_float2(acc[ni][0], acc[ni][1]);
        *(float2*)&out[(size_t)(r0+8)*C_ + c0] = make_float2(acc[ni][2], acc[ni][3]);
    }
}

// ---------------- launch ----------------
extern "C" void kernel_launch(void* const* d_in, const int* in_sizes, int n_in,
                              void* d_out, int out_size) {
    const float* x = (const float*)d_in[0];
    int base = (in_sizes[1] == 1) ? 3 : 1;
    const float* mk    = (const float*)d_in[base + 0];
    const float* mv    = (const float*)d_in[base + 1];
    const float* mr    = (const float*)d_in[base + 2];
    const float* Wk    = (const float*)d_in[base + 3];
    const float* Wv    = (const float*)d_in[base + 4];
    const float* Wr    = (const float*)d_in[base + 5];
    const float* Wo    = (const float*)d_in[base + 6];
    const float* sd    = (const float*)d_in[base + 7];
    const float* sf    = (const float*)d_in[base + 8];
    const float* cvw   = (const float*)d_in[base + 9];
    const float* cvb   = (const float*)d_in[base + 10];
    const float* bns_v = (const float*)d_in[base + 11];
    const float* bnb_v = (const float*)d_in[base + 12];
    const float* chw   = (const float*)d_in[base + 13];
    const float* chb   = (const float*)d_in[base + 14];
    const float* bns_h = (const float*)d_in[base + 15];
    const float* bnb_h = (const float*)d_in[base + 16];

    wprep_kernel<<<888, 256>>>(mk, mv, mr, Wk, Wv, Wr, cvw, chw);
    convP_kernel<<<1024, 256>>>(x);
    gb_combine_kernel<<<32, 256>>>(cvb, bns_v, bnb_v, chb, bns_h, bnb_h);
    peak_kernel<<<1024, 96>>>(x);
    gemm1_kernel<<<dim3(128, 9), 128>>>(x);
    wkv_kernel<<<B_*C_, 256>>>(sd, sf);
    gemm2_kernel<<<dim3(256, 3), 128>>>(Wo, (float*)d_out);
}

// round 6
// speedup vs baseline: 1.2940x; 1.2940x over previous
#include <cuda_runtime.h>
#include <math.h>

#define B_ 2
#define T_ 4096
#define C_ 192
#define NTOT (B_*T_*C_)

// ---------------- scratch ----------------
__device__ float g_Wf[384*576];
__device__ float g_Wp[192*32];
__device__ float g_P[B_*T_*32];
__device__ float g_gb[B_*4*T_];
__device__ float g_peak[NTOT];
__device__ float g_kT[NTOT];
__device__ float g_vT[NTOT];
__device__ float g_yT[NTOT];
__device__ float g_sr[NTOT];

__constant__ float c_prfx[16] = {-2,-2,-2,-2, -2,-1,0,1,  2,2,2,2,  -1,0,1,2};
__constant__ float c_prfy[16] = {-2,-1,0,1,   2,2,2,2,  -1,0,1,2,  -2,-2,-2,-2};

__device__ __forceinline__ unsigned f2tf32(float x) {
    unsigned r;
    asm("cvt.rna.tf32.f32 %0, %1;" : "=r"(r) : "f"(x));
    return r;
}

__device__ __forceinline__ void mma8(float* d, unsigned a0, unsigned a1, unsigned a2, unsigned a3,
                                     unsigned b0, unsigned b1) {
    asm volatile(
        "mma.sync.aligned.m16n8k8.row.col.f32.tf32.tf32.f32 "
        "{%0,%1,%2,%3}, {%4,%5,%6,%7}, {%8,%9}, {%0,%1,%2,%3};\n"
        : "+f"(d[0]), "+f"(d[1]), "+f"(d[2]), "+f"(d[3])
        : "r"(a0), "r"(a1), "r"(a2), "r"(a3), "r"(b0), "r"(b1));
}

// ---------------- weight prep ----------------
__global__ void wprep_kernel(const float* __restrict__ mk, const float* __restrict__ mv,
                             const float* __restrict__ mr,
                             const float* __restrict__ Wk, const float* __restrict__ Wv,
                             const float* __restrict__ Wr,
                             const float* __restrict__ cvw, const float* __restrict__ chw) {
    int i = blockIdx.x * 256 + threadIdx.x;
    if (i < 384*576) {
        int row = i / 576, n = i % 576;
        int c = row % 192;
        bool second = row >= 192;
        const float* W; float m; int nn;
        if (n < 192)      { W = Wk; m = mk[c]; nn = n; }
        else if (n < 384) { W = Wv; m = mv[c]; nn = n - 192; }
        else              { W = Wr; m = mr[c]; nn = n - 384; }
        g_Wf[i] = (second ? (1.f - m) : m) * W[c*192 + nn];
    } else {
        int j = i - 384*576;
        if (j < 192*32) {
            int c = j / 32, n = j % 32;
            float v = 0.f;
            if (n < 14)      v = cvw[(n/7)*C_*7 + c*7 + (n%7)];
            else if (n < 28) { int n2 = n - 14; v = chw[(n2/7)*C_*7 + c*7 + (n2%7)]; }
            g_Wp[j] = v;
        }
    }
}

// ---------------- conv taps fp32 exact: P[8192][28] = x @ Wp ----------------
__global__ __launch_bounds__(256) void convP_kernel(const float* __restrict__ x) {
    __shared__ float xs[8][193];
    int tid = threadIdx.x;
    int tok0 = blockIdx.x * 8;
    for (int i = tid; i < 8*192; i += 256) {
        int r = i / 192, c = i % 192;
        xs[r][c] = x[(size_t)(tok0 + r)*C_ + c];
    }
    __syncthreads();
    int r = tid >> 5, n = tid & 31;
    if (n < 28) {
        float acc = 0.f;
#pragma unroll 8
        for (int c = 0; c < 192; c++)
            acc = fmaf(xs[r][c], g_Wp[c*32 + n], acc);
        g_P[(size_t)(tok0 + r)*32 + n] = acc;
    }
}

// ---------------- combine conv taps -> gb (fp32 exact) ----------------
__global__ void gb_combine_kernel(const float* __restrict__ cvb, const float* __restrict__ bns_v,
                                  const float* __restrict__ bnb_v, const float* __restrict__ chb,
                                  const float* __restrict__ bns_h, const float* __restrict__ bnb_h) {
    int i = blockIdx.x * 256 + threadIdx.x;
    int b = i >> 12, tt = i & 4095;
    int hh = tt >> 6, ww = tt & 63;
    const float* Pb = g_P + (size_t)b * T_ * 32;
    float gv0 = 0.f, gv1 = 0.f, gh0 = 0.f, gh1 = 0.f;
#pragma unroll
    for (int r = 0; r < 7; r++) {
        int hy = hh + r - 3;
        if (hy >= 0 && hy < 64) {
            const float* p = &Pb[(size_t)(hy*64 + ww)*32];
            gv0 += p[r]; gv1 += p[7 + r];
        }
        int wy = ww + r - 3;
        if (wy >= 0 && wy < 64) {
            const float* p = &Pb[(size_t)(hh*64 + wy)*32];
            gh0 += p[14 + r]; gh1 += p[21 + r];
        }
    }
    const float inv = rsqrtf(1.f + 1e-5f);
    float vals[4] = {gv0, gv1, gh0, gh1};
    float biases[4] = {cvb[0], cvb[1], chb[0], chb[1]};
    float scales[4] = {bns_v[0], bns_v[1], bns_h[0], bns_h[1]};
    float shifts[4] = {bnb_v[0], bnb_v[1], bnb_h[0], bnb_h[1]};
#pragma unroll
    for (int j = 0; j < 4; j++) {
        float val = (vals[j] + biases[j]) * (scales[j] * inv) + shifts[j];
        g_gb[((size_t)b*4 + j)*T_ + tt] = 2.f / (1.f + expf(-val));
    }
}

// ---------------- adaptive peak (float4, 16 tokens/block, 384 threads) ----------------
__global__ __launch_bounds__(384) void peak_kernel(const float* __restrict__ x) {
    int bi = blockIdx.x;                  // 512 blocks
    int b = bi >> 8;
    int tb = (bi & 255) * 16;
    int hh = tb >> 6, wwb = tb & 63;
    __shared__ int   s_lt[16][16], s_rb[16][16];
    __shared__ float s_wlt[16][16], s_wrb[16][16];
    int tid = threadIdx.x;
    const float* gbp = g_gb + (size_t)b*4*T_;
    if (tid < 256) {
        int j = tid >> 4, o = tid & 15;
        int tt = tb + j, ww = wwb + j;
        int blk = o >> 2;
        float mx = 0.f, my = 0.f;
        if (blk == 0)      mx = -gbp[tt];
        else if (blk == 1) my =  gbp[3*T_ + tt];
        else if (blk == 2) mx =  gbp[T_ + tt];
        else               my = -gbp[2*T_ + tt];
        float px = (float)(hh + 2) + c_prfx[o] + mx;
        float py = (float)(ww + 2) + c_prfy[o] + my;
        float flx = floorf(px), fly = floorf(py);
        float qltx = fminf(fmaxf(flx,     0.f), 67.f);
        float qlty = fminf(fmaxf(fly,     0.f), 67.f);
        float qrbx = fminf(fmaxf(flx+1.f, 0.f), 67.f);
        float qrby = fminf(fmaxf(fly+1.f, 0.f), 67.f);
        float pxc  = fminf(fmaxf(px,      0.f), 67.f);
        float pyc  = fminf(fmaxf(py,      0.f), 67.f);
        float glt = (1.f + (qltx - pxc)) * (1.f + (qlty - pyc));
        float grb = (1.f - (qrbx - pxc)) * (1.f - (qrby - pyc));
        int rlt = min(max((int)qltx - 2, 0), 63);
        int clt = min(max((int)qlty - 2, 0), 63);
        int rrb = min(max((int)qrbx - 2, 0), 63);
        int crb = min(max((int)qrby - 2, 0), 63);
        s_lt[j][o] = rlt*64 + clt;  s_rb[j][o] = rrb*64 + crb;
        s_wlt[j][o] = glt;          s_wrb[j][o] = grb;
    }
    __syncthreads();
    const float* xb = x + (size_t)b * T_ * C_;
    int slot = tid / 48;
    int c4 = (tid % 48) * 4;
#pragma unroll
    for (int rep = 0; rep < 2; rep++) {
        int j = slot + rep*8;
        float a0 = 0.f, a1 = 0.f, a2 = 0.f, a3 = 0.f;
#pragma unroll
        for (int o = 0; o < 16; o++) {
            float4 a = *(const float4*)&xb[(size_t)s_lt[j][o]*C_ + c4];
            float4 bv = *(const float4*)&xb[(size_t)s_rb[j][o]*C_ + c4];
            float wl = s_wlt[j][o], wr = s_wrb[j][o];
            a0 += wl*a.x + wr*bv.x;
            a1 += wl*a.y + wr*bv.y;
            a2 += wl*a.z + wr*bv.z;
            a3 += wl*a.w + wr*bv.w;
        }
        size_t idx = ((size_t)b*T_ + tb + j)*C_ + c4;
        float4 xc = *(const float4*)&x[idx];
        float4 outv;
        outv.x = xc.x - a0*(1.f/16.f);
        outv.y = xc.y - a1*(1.f/16.f);
        outv.z = xc.z - a2*(1.f/16.f);
        outv.w = xc.w - a3*(1.f/16.f);
        *(float4*)&g_peak[idx] = outv;
    }
}

// ---------------- fused front GEMM (1x tf32): [k|v|r] = [x | qshift(x)] @ Wf ----------------
#define AS_STRIDE 36
#define BS_STRIDE 68

__device__ __forceinline__ float4 loadAx(const float* __restrict__ x, int gt, int hh, int ww, int k) {
    if (k < 192) return *(const float4*)&x[(size_t)gt*C_ + k];
    int c = k - 192;
    int g = c / 48;
    int src; bool ok;
    if (g == 0)      { ok = (ww >= 1);  src = gt - 1; }
    else if (g == 1) { ok = (ww <= 62); src = gt + 1; }
    else if (g == 2) { ok = (hh >= 1);  src = gt - 64; }
    else             { ok = (hh <= 62); src = gt + 64; }
    if (!ok) return make_float4(0.f, 0.f, 0.f, 0.f);
    return *(const float4*)&x[(size_t)src*C_ + c];
}

__global__ __launch_bounds__(128) void gemm1_kernel(const float* __restrict__ x) {
    __shared__ unsigned As[2][64 * AS_STRIDE];
    __shared__ unsigned Bs[2][32 * BS_STRIDE];

    int tid = threadIdx.x;
    int warp = tid >> 5, lane = tid & 31;
    int bm = blockIdx.x * 64;
    int bn = blockIdx.y * 64;
    int cls = blockIdx.y / 3;            // 0:k 1:v 2:r
    int nloc = bn - cls * 192;
    int wm = (warp >> 1) * 32;
    int wn = (warp & 1) * 32;
    int gid = lane >> 2, tig = lane & 3;

    int ar = tid >> 3;
    int ac = (tid & 7) * 4;
    int br = tid >> 4;
    int bc = (tid & 15) * 4;

    int gtr[4], hr[4], wr[4];
#pragma unroll
    for (int i = 0; i < 4; i++) {
        int gt = bm + ar + i*16;
        gtr[i] = gt;
        int tt = gt & 4095;
        hr[i] = tt >> 6; wr[i] = tt & 63;
    }

    float acc[2][4][4] = {};

    float4 pa[4], pb[4];
#pragma unroll
    for (int i = 0; i < 4; i++) pa[i] = loadAx(x, gtr[i], hr[i], wr[i], ac);
#pragma unroll
    for (int i = 0; i < 4; i++) pb[i] = *(const float4*)&g_Wf[(size_t)(br + i*8)*576 + bn + bc];

#pragma unroll
    for (int i = 0; i < 4; i++) {
        unsigned* p = &As[0][(ar + i*16)*AS_STRIDE + ac];
        p[0]=f2tf32(pa[i].x); p[1]=f2tf32(pa[i].y); p[2]=f2tf32(pa[i].z); p[3]=f2tf32(pa[i].w);
    }
#pragma unroll
    for (int i = 0; i < 4; i++) {
        unsigned* p = &Bs[0][(br + i*8)*BS_STRIDE + bc];
        p[0]=f2tf32(pb[i].x); p[1]=f2tf32(pb[i].y); p[2]=f2tf32(pb[i].z); p[3]=f2tf32(pb[i].w);
    }
    __syncthreads();

    for (int kc = 0; kc < 12; kc++) {
        int cur = kc & 1;
        if (kc < 11) {
            int k0 = (kc + 1) * 32;
#pragma unroll
            for (int i = 0; i < 4; i++) pa[i] = loadAx(x, gtr[i], hr[i], wr[i], k0 + ac);
#pragma unroll
            for (int i = 0; i < 4; i++) pb[i] = *(const float4*)&g_Wf[(size_t)(k0 + br + i*8)*576 + bn + bc];
        }
        const unsigned* as = As[cur];
        const unsigned* bs = Bs[cur];
#pragma unroll
        for (int ks = 0; ks < 4; ks++) {
            int kk0 = ks * 8;
            unsigned afr[2][4], bfr[4][2];
#pragma unroll
            for (int mi = 0; mi < 2; mi++) {
                int rbase = (wm + mi*16 + gid) * AS_STRIDE;
                afr[mi][0] = as[rbase + kk0 + tig];
                afr[mi][1] = as[rbase + 8*AS_STRIDE + kk0 + tig];
                afr[mi][2] = as[rbase + kk0 + tig + 4];
                afr[mi][3] = as[rbase + 8*AS_STRIDE + kk0 + tig + 4];
            }
#pragma unroll
            for (int ni = 0; ni < 4; ni++) {
                int col = wn + ni*8 + gid;
                bfr[ni][0] = bs[(kk0 + tig)*BS_STRIDE + col];
                bfr[ni][1] = bs[(kk0 + tig + 4)*BS_STRIDE + col];
            }
#pragma unroll
            for (int mi = 0; mi < 2; mi++)
#pragma unroll
                for (int ni = 0; ni < 4; ni++)
                    mma8(acc[mi][ni], afr[mi][0], afr[mi][1], afr[mi][2], afr[mi][3],
                         bfr[ni][0], bfr[ni][1]);
        }
        if (kc < 11) {
            __syncthreads();
            int nxt = cur ^ 1;
#pragma unroll
            for (int i = 0; i < 4; i++) {
                unsigned* p = &As[nxt][(ar + i*16)*AS_STRIDE + ac];
                p[0]=f2tf32(pa[i].x); p[1]=f2tf32(pa[i].y); p[2]=f2tf32(pa[i].z); p[3]=f2tf32(pa[i].w);
            }
#pragma unroll
            for (int i = 0; i < 4; i++) {
                unsigned* p = &Bs[nxt][(br + i*8)*BS_STRIDE + bc];
                p[0]=f2tf32(pb[i].x); p[1]=f2tf32(pb[i].y); p[2]=f2tf32(pb[i].z); p[3]=f2tf32(pb[i].w);
            }
            __syncthreads();
        }
    }

    if (cls == 2) {
#pragma unroll
        for (int mi = 0; mi < 2; mi++) {
            int r0 = bm + wm + mi*16 + gid;
#pragma unroll
            for (int ni = 0; ni < 4; ni++) {
                int c0 = nloc + wn + ni*8 + tig*2;
                float v0 = 1.f/(1.f+expf(-acc[mi][ni][0]));
                float v1 = 1.f/(1.f+expf(-acc[mi][ni][1]));
                float v2 = 1.f/(1.f+expf(-acc[mi][ni][2]));
                float v3 = 1.f/(1.f+expf(-acc[mi][ni][3]));
                *(float2*)&g_sr[(size_t)r0*C_ + c0]     = make_float2(v0, v1);
                *(float2*)&g_sr[(size_t)(r0+8)*C_ + c0] = make_float2(v2, v3);
            }
        }
        return;
    }

    if (cls == 1) {
#pragma unroll
        for (int mi = 0; mi < 2; mi++) {
            int r0 = bm + wm + mi*16 + gid;
#pragma unroll
            for (int ni = 0; ni < 4; ni++) {
                int cg = nloc + wn + ni*8 + tig*2;
                float2 p0 = *(const float2*)&g_peak[(size_t)r0*C_ + cg];
                float2 p1 = *(const float2*)&g_peak[(size_t)(r0+8)*C_ + cg];
                acc[mi][ni][0] += p0.x; acc[mi][ni][1] += p0.y;
                acc[mi][ni][2] += p1.x; acc[mi][ni][3] += p1.y;
            }
        }
    }

    // transpose-write to kT / vT
    __syncthreads();
    float* st = (float*)As;    // 64 x 65 stage
#pragma unroll
    for (int mi = 0; mi < 2; mi++) {
        int r = wm + mi*16 + gid;
#pragma unroll
        for (int ni = 0; ni < 4; ni++) {
            int cc = wn + ni*8 + tig*2;
            st[r*65 + cc]       = acc[mi][ni][0];
            st[r*65 + cc + 1]   = acc[mi][ni][1];
            st[(r+8)*65 + cc]   = acc[mi][ni][2];
            st[(r+8)*65 + cc+1] = acc[mi][ni][3];
        }
    }
    __syncthreads();
    float* dst = (cls == 0) ? g_kT : g_vT;
    int bb = bm >> 12, trow = bm & 4095;
    int f4 = tid & 15, rsub = tid >> 4;
#pragma unroll
    for (int q = 0; q < 8; q++) {
        int cr = q*8 + rsub;
        int t0 = f4*4;
        float4 v;
        v.x = st[(t0+0)*65 + cr];
        v.y = st[(t0+1)*65 + cr];
        v.z = st[(t0+2)*65 + cr];
        v.w = st[(t0+3)*65 + cr];
        *(float4*)&dst[((size_t)(bb*C_ + nloc + cr))*T_ + trow + t0] = v;
    }
}

// ---------------- bidirectional WKV scan ----------------
struct Agg { float a, b, dl; };
__device__ __forceinline__ Agg combine(Agg p, Agg s) {
    Agg r;
    r.a  = fmaf(s.dl, p.a, s.a);
    r.b  = fmaf(s.dl, p.b, s.b);
    r.dl = p.dl * s.dl;
    return r;
}
__device__ __forceinline__ Agg shfl_up_agg(Agg v, int off) {
    Agg r;
    r.a  = __shfl_up_sync(0xffffffffu, v.a,  off);
    r.b  = __shfl_up_sync(0xffffffffu, v.b,  off);
    r.dl = __shfl_up_sync(0xffffffffu, v.dl, off);
    return r;
}
__device__ __forceinline__ Agg shfl_dn_agg(Agg v, int off) {
    Agg r;
    r.a  = __shfl_down_sync(0xffffffffu, v.a,  off);
    r.b  = __shfl_down_sync(0xffffffffu, v.b,  off);
    r.dl = __shfl_down_sync(0xffffffffu, v.dl, off);
    return r;
}

__global__ __launch_bounds__(256) void wkv_kernel(const float* __restrict__ sd,
                                                  const float* __restrict__ sf) {
    __shared__ Agg warpAgg[8];
    __shared__ Agg warpPre[8];
    int bc = blockIdx.x;
    int c = bc % C_;
    float w  = sd[c] * (1.0f / T_);
    float u  = sf[c] * (1.0f / T_);
    float d  = expf(-w);
    float eu = expf(u);
    float d2 = d*d, d4 = d2*d2, d8 = d4*d4, d16 = d8*d8;
    int tid = threadIdx.x;
    int lane = tid & 31, wid = tid >> 5;
    const float* kp = g_kT + (size_t)bc * T_;
    const float* vp = g_vT + (size_t)bc * T_;
    float* yp = g_yT + (size_t)bc * T_;
    int t0 = tid * 16;

    float ek[16], vv[16];
#pragma unroll
    for (int i = 0; i < 16; i++) {
        ek[i] = expf(kp[t0 + i]);
        vv[i] = vp[t0 + i];
    }

    Agg ag; ag.a = 0.f; ag.b = 0.f; ag.dl = d16;
#pragma unroll
    for (int i = 0; i < 16; i++) {
        ag.a = fmaf(d, ag.a, ek[i]);
        ag.b = fmaf(d, ag.b, ek[i]*vv[i]);
    }
    Agg inc = ag;
#pragma unroll
    for (int off = 1; off < 32; off <<= 1) {
        Agg o = shfl_up_agg(inc, off);
        if (lane >= off) inc = combine(o, inc);
    }
    if (lane == 31) warpAgg[wid] = inc;
    __syncthreads();
    if (tid == 0) {
        Agg run; run.a = 0.f; run.b = 0.f; run.dl = 1.f;
        for (int i = 0; i < 8; i++) { warpPre[i] = run; run = combine(run, warpAgg[i]); }
    }
    __syncthreads();
    Agg pl = shfl_up_agg(inc, 1);
    Agg ex = warpPre[wid];
    if (lane > 0) ex = combine(ex, pl);

    float af = ex.a, bf = ex.b;
    float saf[16], sbf[16];
#pragma unroll
    for (int i = 0; i < 16; i++) {
        saf[i] = af; sbf[i] = bf;
        af = fmaf(d, af, ek[i]);
        bf = fmaf(d, bf, ek[i]*vv[i]);
    }
    __syncthreads();

    Agg bg; bg.a = 0.f; bg.b = 0.f; bg.dl = d16;
#pragma unroll
    for (int i = 15; i >= 0; i--) {
        bg.a = fmaf(d, bg.a, ek[i]);
        bg.b = fmaf(d, bg.b, ek[i]*vv[i]);
    }
    Agg binc = bg;
#pragma unroll
    for (int off = 1; off < 32; off <<= 1) {
        Agg o = shfl_dn_agg(binc, off);
        if (lane < 32 - off) binc = combine(o, binc);
    }
    if (lane == 0) warpAgg[wid] = binc;
    __syncthreads();
    if (tid == 0) {
        Agg run; run.a = 0.f; run.b = 0.f; run.dl = 1.f;
        for (int i = 7; i >= 0; i--) { warpPre[i] = run; run = combine(run, warpAgg[i]); }
    }
    __syncthreads();
    Agg bpl = shfl_dn_agg(binc, 1);
    Agg bex = warpPre[wid];
    if (lane < 31) bex = combine(bex, bpl);

    float ab = bex.a, bb = bex.b;
#pragma unroll
    for (int i = 15; i >= 0; i--) {
        float es  = eu * ek[i];
        float num = sbf[i] + bb + es * vv[i];
        float den = saf[i] + ab + es;
        yp[t0 + i] = num / den;
        ab = fmaf(d, ab, ek[i]);
        bb = fmaf(d, bb, ek[i]*vv[i]);
    }
}

// ---------------- output GEMM (1x tf32): out = (sr .* y) @ Wo ----------------
#define A2_STRIDE 197

__global__ __launch_bounds__(128) void gemm2_kernel(const float* __restrict__ Wo,
                                                    float* __restrict__ out) {
    __shared__ unsigned As2[32 * A2_STRIDE];
    __shared__ unsigned Bs2[2][32 * BS_STRIDE];

    int tid = threadIdx.x;
    int warp = tid >> 5, lane = tid & 31;
    int gid = lane >> 2, tig = lane & 3;
    int bm = blockIdx.x * 32;
    int bn = blockIdx.y * 64;
    int wm = (warp >> 1) * 16;
    int wn = (warp & 1) * 32;
    int bb = bm >> 12, trow = bm & 4095;

#pragma unroll
    for (int q = 0; q < 12; q++) {
        int f = q*128 + tid;
        int row = f >> 3;
        int t4 = (f & 7) * 4;
        float4 v = *(const float4*)&g_yT[((size_t)(bb*C_ + row))*T_ + trow + t4];
        As2[(t4+0)*A2_STRIDE + row] = __float_as_uint(v.x);
        As2[(t4+1)*A2_STRIDE + row] = __float_as_uint(v.y);
        As2[(t4+2)*A2_STRIDE + row] = __float_as_uint(v.z);
        As2[(t4+3)*A2_STRIDE + row] = __float_as_uint(v.w);
    }
    __syncthreads();
#pragma unroll
    for (int q = 0; q < 12; q++) {
        int f = q*128 + tid;
        int t = f / 48, c4 = (f % 48) * 4;
        float4 s = *(const float4*)&g_sr[((size_t)(bm + t))*C_ + c4];
        unsigned* p = &As2[t*A2_STRIDE + c4];
        p[0] = f2tf32(__uint_as_float(p[0]) * s.x);
        p[1] = f2tf32(__uint_as_float(p[1]) * s.y);
        p[2] = f2tf32(__uint_as_float(p[2]) * s.z);
        p[3] = f2tf32(__uint_as_float(p[3]) * s.w);
    }

    int br = tid >> 4;
    int bc = (tid & 15) * 4;
    float acc[4][4] = {};

    float4 pb[4];
#pragma unroll
    for (int i = 0; i < 4; i++)
        pb[i] = *(const float4*)&Wo[(size_t)(br + i*8)*C_ + bn + bc];
#pragma unroll
    for (int i = 0; i < 4; i++) {
        unsigned* p = &Bs2[0][(br + i*8)*BS_STRIDE + bc];
        p[0]=f2tf32(pb[i].x); p[1]=f2tf32(pb[i].y); p[2]=f2tf32(pb[i].z); p[3]=f2tf32(pb[i].w);
    }
    __syncthreads();

    for (int kc = 0; kc < 6; kc++) {
        int cur = kc & 1;
        if (kc < 5) {
            int k0 = (kc + 1) * 32;
#pragma unroll
            for (int i = 0; i < 4; i++)
                pb[i] = *(const float4*)&Wo[(size_t)(k0 + br + i*8)*C_ + bn + bc];
        }
        const unsigned* bs = Bs2[cur];
        int k0 = kc * 32;
#pragma unroll
        for (int ks = 0; ks < 4; ks++) {
            int kk = k0 + ks*8;
            unsigned a0 = As2[(wm+gid)*A2_STRIDE + kk + tig];
            unsigned a1 = As2[(wm+gid+8)*A2_STRIDE + kk + tig];
            unsigned a2 = As2[(wm+gid)*A2_STRIDE + kk + tig + 4];
            unsigned a3 = As2[(wm+gid+8)*A2_STRIDE + kk + tig + 4];
#pragma unroll
            for (int ni = 0; ni < 4; ni++) {
                int col = wn + ni*8 + gid;
                unsigned b0 = bs[(ks*8 + tig)*BS_STRIDE + col];
                unsigned b1 = bs[(ks*8 + tig + 4)*BS_STRIDE + col];
                mma8(acc[ni], a0, a1, a2, a3, b0, b1);
            }
        }
        if (kc < 5) {
            __syncthreads();
            int nxt = cur ^ 1;
#pragma unroll
            for (int i = 0; i < 4; i++) {
                unsigned* p = &Bs2[nxt][(br + i*8)*BS_STRIDE + bc];
                p[0]=f2tf32(pb[i].x); p[1]=f2tf32(pb[i].y); p[2]=f2tf32(pb[i].z); p[3]=f2tf32(pb[i].w);
            }
            __syncthreads();
        }
    }

    int r0 = bm + wm + gid;
#pragma unroll
    for (int ni = 0; ni < 4; ni++) {
        int c0 = bn + wn + ni*8 + tig*2;
        *(float2*)&out[(size_t)r0*C_ + c0]     = make_float2(acc[ni][0], acc[ni][1]);
        *(float2*)&out[(size_t)(r0+8)*C_ + c0] = make_float2(acc[ni][2], acc[ni][3]);
    }
}

// ---------------- launch ----------------
extern "C" void kernel_launch(void* const* d_in, const int* in_sizes, int n_in,
                              void* d_out, int out_size) {
    const float* x = (const float*)d_in[0];
    int base = (in_sizes[1] == 1) ? 3 : 1;
    const float* mk    = (const float*)d_in[base + 0];
    const float* mv    = (const float*)d_in[base + 1];
    const float* mr    = (const float*)d_in[base + 2];
    const float* Wk    = (const float*)d_in[base + 3];
    const float* Wv    = (const float*)d_in[base + 4];
    const float* Wr    = (const float*)d_in[base + 5];
    const float* Wo    = (const float*)d_in[base + 6];
    const float* sd    = (const float*)d_in[base + 7];
    const float* sf    = (const float*)d_in[base + 8];
    const float* cvw   = (const float*)d_in[base + 9];
    const float* cvb   = (const float*)d_in[base + 10];
    const float* bns_v = (const float*)d_in[base + 11];
    const float* bnb_v = (const float*)d_in[base + 12];
    const float* chw   = (const float*)d_in[base + 13];
    const float* chb   = (const float*)d_in[base + 14];
    const float* bns_h = (const float*)d_in[base + 15];
    const float* bnb_h = (const float*)d_in[base + 16];

    wprep_kernel<<<888, 256>>>(mk, mv, mr, Wk, Wv, Wr, cvw, chw);
    convP_kernel<<<1024, 256>>>(x);
    gb_combine_kernel<<<32, 256>>>(cvb, bns_v, bnb_v, chb, bns_h, bnb_h);
    peak_kernel<<<512, 384>>>(x);
    gemm1_kernel<<<dim3(128, 9), 128>>>(x);
    wkv_kernel<<<B_*C_, 256>>>(sd, sf);
    gemm2_kernel<<<dim3(256, 3), 128>>>(Wo, (float*)d_out);
}

// round 7
// speedup vs baseline: 1.4294x; 1.1046x over previous
#include <cuda_runtime.h>
#include <math.h>

#define B_ 2
#define T_ 4096
#define C_ 192
#define NTOT (B_*T_*C_)

// ---------------- scratch ----------------
__device__ float g_Wf[384*576];      // tf32-pre-rounded fused [k|v|r] weights
__device__ float g_Wo[192*192];      // tf32-pre-rounded output weights
__device__ float g_Wp[192*32];       // exact fp32 conv-tap weights
__device__ float g_P[B_*T_*32];
__device__ float g_peak[NTOT];
__device__ float g_kT[NTOT];
__device__ float g_vT[NTOT];
__device__ float g_yT[NTOT];
__device__ float g_sr[NTOT];

__constant__ float c_prfx[16] = {-2,-2,-2,-2, -2,-1,0,1,  2,2,2,2,  -1,0,1,2};
__constant__ float c_prfy[16] = {-2,-1,0,1,   2,2,2,2,  -1,0,1,2,  -2,-2,-2,-2};

__device__ __forceinline__ unsigned f2tf32(float x) {
    unsigned r;
    asm("cvt.rna.tf32.f32 %0, %1;" : "=r"(r) : "f"(x));
    return r;
}

__device__ __forceinline__ void mma8(float* d, unsigned a0, unsigned a1, unsigned a2, unsigned a3,
                                     unsigned b0, unsigned b1) {
    asm volatile(
        "mma.sync.aligned.m16n8k8.row.col.f32.tf32.tf32.f32 "
        "{%0,%1,%2,%3}, {%4,%5,%6,%7}, {%8,%9}, {%0,%1,%2,%3};\n"
        : "+f"(d[0]), "+f"(d[1]), "+f"(d[2]), "+f"(d[3])
        : "r"(a0), "r"(a1), "r"(a2), "r"(a3), "r"(b0), "r"(b1));
}

// ---------------- weight prep ----------------
__global__ void wprep_kernel(const float* __restrict__ mk, const float* __restrict__ mv,
                             const float* __restrict__ mr,
                             const float* __restrict__ Wk, const float* __restrict__ Wv,
                             const float* __restrict__ Wr, const float* __restrict__ Wo,
                             const float* __restrict__ cvw, const float* __restrict__ chw) {
    int i = blockIdx.x * 256 + threadIdx.x;
    if (i < 384*576) {
        int row = i / 576, n = i % 576;
        int c = row % 192;
        bool second = row >= 192;
        const float* W; float m; int nn;
        if (n < 192)      { W = Wk; m = mk[c]; nn = n; }
        else if (n < 384) { W = Wv; m = mv[c]; nn = n - 192; }
        else              { W = Wr; m = mr[c]; nn = n - 384; }
        float v = (second ? (1.f - m) : m) * W[c*192 + nn];
        g_Wf[i] = __uint_as_float(f2tf32(v));
        return;
    }
    int j = i - 384*576;
    if (j < 192*32) {
        int c = j / 32, n = j % 32;
        float v = 0.f;
        if (n < 14)      v = cvw[(n/7)*C_*7 + c*7 + (n%7)];
        else if (n < 28) { int n2 = n - 14; v = chw[(n2/7)*C_*7 + c*7 + (n2%7)]; }
        g_Wp[j] = v;   // exact fp32
        return;
    }
    int jj = j - 192*32;
    if (jj < 192*192)
        g_Wo[jj] = __uint_as_float(f2tf32(Wo[jj]));
}

// ---------------- conv taps fp32 exact: P[8192][28] = x @ Wp ----------------
__global__ __launch_bounds__(256) void convP_kernel(const float* __restrict__ x) {
    __shared__ float xs[8][193];
    int tid = threadIdx.x;
    int tok0 = blockIdx.x * 8;
    for (int i = tid; i < 8*192; i += 256) {
        int r = i / 192, c = i % 192;
        xs[r][c] = x[(size_t)(tok0 + r)*C_ + c];
    }
    __syncthreads();
    int r = tid >> 5, n = tid & 31;
    if (n < 28) {
        float acc = 0.f;
#pragma unroll 8
        for (int c = 0; c < 192; c++)
            acc = fmaf(xs[r][c], g_Wp[c*32 + n], acc);
        g_P[(size_t)(tok0 + r)*32 + n] = acc;
    }
}

// ---------------- adaptive peak (gb fused, 768 threads, 16 tokens/block) ----------------
__global__ __launch_bounds__(768) void peak_kernel(const float* __restrict__ x,
                                                   const float* __restrict__ cvb,
                                                   const float* __restrict__ bns_v,
                                                   const float* __restrict__ bnb_v,
                                                   const float* __restrict__ chb,
                                                   const float* __restrict__ bns_h,
                                                   const float* __restrict__ bnb_h) {
    int bi = blockIdx.x;                  // 512 blocks
    int b = bi >> 8;
    int tb = (bi & 255) * 16;
    int hh = tb >> 6, wwb = tb & 63;
    __shared__ float gbv[16][4];
    __shared__ int   s_lt[16][16], s_rb[16][16];
    __shared__ float s_wlt[16][16], s_wrb[16][16];
    int tid = threadIdx.x;

    // phase 0: band estimate (fp32-exact) for this block's 16 tokens
    if (tid < 64) {
        int j = tid >> 2, dir = tid & 3;
        int ww = wwb + j;
        const float* Pb = g_P + (size_t)b * T_ * 32;
        float s = 0.f;
        if (dir < 2) {
#pragma unroll
            for (int r = 0; r < 7; r++) {
                int hy = hh + r - 3;
                if (hy >= 0 && hy < 64) s += Pb[(size_t)(hy*64 + ww)*32 + dir*7 + r];
            }
        } else {
#pragma unroll
            for (int r = 0; r < 7; r++) {
                int wy = ww + r - 3;
                if (wy >= 0 && wy < 64) s += Pb[(size_t)(hh*64 + wy)*32 + (dir-2)*7 + 14 + r];
            }
        }
        const float inv = rsqrtf(1.f + 1e-5f);
        float bias, scale, shift;
        if (dir == 0)      { bias = cvb[0]; scale = bns_v[0]; shift = bnb_v[0]; }
        else if (dir == 1) { bias = cvb[1]; scale = bns_v[1]; shift = bnb_v[1]; }
        else if (dir == 2) { bias = chb[0]; scale = bns_h[0]; shift = bnb_h[0]; }
        else               { bias = chb[1]; scale = bns_h[1]; shift = bnb_h[1]; }
        float val = (s + bias) * (scale * inv) + shift;
        gbv[j][dir] = 2.f / (1.f + expf(-val));
    }
    __syncthreads();

    // phase 1: offsets + bilinear weights
    if (tid < 256) {
        int j = tid >> 4, o = tid & 15;
        int ww = wwb + j;
        int blk = o >> 2;
        float mx = 0.f, my = 0.f;
        if (blk == 0)      mx = -gbv[j][0];
        else if (blk == 1) my =  gbv[j][3];
        else if (blk == 2) mx =  gbv[j][1];
        else               my = -gbv[j][2];
        float px = (float)(hh + 2) + c_prfx[o] + mx;
        float py = (float)(ww + 2) + c_prfy[o] + my;
        float flx = floorf(px), fly = floorf(py);
        float qltx = fminf(fmaxf(flx,     0.f), 67.f);
        float qlty = fminf(fmaxf(fly,     0.f), 67.f);
        float qrbx = fminf(fmaxf(flx+1.f, 0.f), 67.f);
        float qrby = fminf(fmaxf(fly+1.f, 0.f), 67.f);
        float pxc  = fminf(fmaxf(px,      0.f), 67.f);
        float pyc  = fminf(fmaxf(py,      0.f), 67.f);
        float glt = (1.f + (qltx - pxc)) * (1.f + (qlty - pyc));
        float grb = (1.f - (qrbx - pxc)) * (1.f - (qrby - pyc));
        int rlt = min(max((int)qltx - 2, 0), 63);
        int clt = min(max((int)qlty - 2, 0), 63);
        int rrb = min(max((int)qrbx - 2, 0), 63);
        int crb = min(max((int)qrby - 2, 0), 63);
        s_lt[j][o] = rlt*64 + clt;  s_rb[j][o] = rrb*64 + crb;
        s_wlt[j][o] = glt;          s_wrb[j][o] = grb;
    }
    __syncthreads();

    // phase 2: gather, 1 token-slot per thread (16 tokens x 48 float4-lanes)
    const float* xb = x + (size_t)b * T_ * C_;
    int j = tid / 48;
    int c4 = (tid % 48) * 4;
    float a0 = 0.f, a1 = 0.f, a2 = 0.f, a3 = 0.f;
#pragma unroll
    for (int o = 0; o < 16; o++) {
        float4 a = *(const float4*)&xb[(size_t)s_lt[j][o]*C_ + c4];
        float4 bv = *(const float4*)&xb[(size_t)s_rb[j][o]*C_ + c4];
        float wl = s_wlt[j][o], wr = s_wrb[j][o];
        a0 += wl*a.x + wr*bv.x;
        a1 += wl*a.y + wr*bv.y;
        a2 += wl*a.z + wr*bv.z;
        a3 += wl*a.w + wr*bv.w;
    }
    size_t idx = ((size_t)b*T_ + tb + j)*C_ + c4;
    float4 xc = *(const float4*)&x[idx];
    float4 outv;
    outv.x = xc.x - a0*(1.f/16.f);
    outv.y = xc.y - a1*(1.f/16.f);
    outv.z = xc.z - a2*(1.f/16.f);
    outv.w = xc.w - a3*(1.f/16.f);
    *(float4*)&g_peak[idx] = outv;
}

// ---------------- fused front GEMM (1x tf32, 256 thr): [k|v|r] = [x|qshift(x)] @ Wf ----------------
#define AS_STRIDE 36
#define BS_STRIDE 72

__device__ __forceinline__ float4 loadAx(const float* __restrict__ x, int gt, int hh, int ww, int k) {
    if (k < 192) return *(const float4*)&x[(size_t)gt*C_ + k];
    int c = k - 192;
    int g = c / 48;
    int src; bool ok;
    if (g == 0)      { ok = (ww >= 1);  src = gt - 1; }
    else if (g == 1) { ok = (ww <= 62); src = gt + 1; }
    else if (g == 2) { ok = (hh >= 1);  src = gt - 64; }
    else             { ok = (hh <= 62); src = gt + 64; }
    if (!ok) return make_float4(0.f, 0.f, 0.f, 0.f);
    return *(const float4*)&x[(size_t)src*C_ + c];
}

__global__ __launch_bounds__(256) void gemm1_kernel(const float* __restrict__ x) {
    __shared__ unsigned As[2][64 * AS_STRIDE];
    __shared__ unsigned Bs[2][32 * BS_STRIDE];

    int tid = threadIdx.x;
    int warp = tid >> 5, lane = tid & 31;
    int bm = blockIdx.x * 64;
    int bny = blockIdx.y;
    int bn = bny * 64;
    int cls = bny / 3;            // 0:k 1:v 2:r
    int nloc = bn - cls * 192;
    int wm = (warp & 3) * 16;
    int wn = (warp >> 2) * 32;
    int gid = lane >> 2, tig = lane & 3;

    // A: 2 rows/thread (ar, ar+32), 4 k each
    int ar = tid >> 3;
    int ac = (tid & 7) * 4;
    // B: 2 float4/thread
    int bk0 = tid >> 3;              // rows 0..31 (q=0), reuse mapping per q
    int bidx1 = tid + 256;

    int gtr[2], hr[2], wr2[2];
#pragma unroll
    for (int i = 0; i < 2; i++) {
        int gt = bm + ar + i*32;
        gtr[i] = gt;
        int tt = gt & 4095;
        hr[i] = tt >> 6; wr2[i] = tt & 63;
    }
    int bk[2], bc4[2];
    bk[0] = tid >> 4;  bc4[0] = (tid & 15) * 4;
    bk[1] = bidx1 >> 4; bc4[1] = (bidx1 & 15) * 4;
    (void)bk0;

    float acc[4][4] = {};

    float4 pa[2], pb[2];
#pragma unroll
    for (int i = 0; i < 2; i++) pa[i] = loadAx(x, gtr[i], hr[i], wr2[i], ac);
#pragma unroll
    for (int q = 0; q < 2; q++) pb[q] = *(const float4*)&g_Wf[(size_t)bk[q]*576 + bn + bc4[q]];

#pragma unroll
    for (int i = 0; i < 2; i++) {
        unsigned* p = &As[0][(ar + i*32)*AS_STRIDE + ac];
        p[0]=f2tf32(pa[i].x); p[1]=f2tf32(pa[i].y); p[2]=f2tf32(pa[i].z); p[3]=f2tf32(pa[i].w);
    }
#pragma unroll
    for (int q = 0; q < 2; q++)
        *(float4*)&Bs[0][bk[q]*BS_STRIDE + bc4[q]] = pb[q];   // pre-rounded, raw store
    __syncthreads();

    for (int kc = 0; kc < 12; kc++) {
        int cur = kc & 1;
        if (kc < 11) {
            int k0 = (kc + 1) * 32;
#pragma unroll
            for (int i = 0; i < 2; i++) pa[i] = loadAx(x, gtr[i], hr[i], wr2[i], k0 + ac);
#pragma unroll
            for (int q = 0; q < 2; q++)
                pb[q] = *(const float4*)&g_Wf[(size_t)(k0 + bk[q])*576 + bn + bc4[q]];
        }
        const unsigned* as = As[cur];
        const unsigned* bs = Bs[cur];
#pragma unroll
        for (int ks = 0; ks < 4; ks++) {
            int kk0 = ks * 8;
            int rbase = (wm + gid) * AS_STRIDE;
            unsigned a0 = as[rbase + kk0 + tig];
            unsigned a1 = as[rbase + 8*AS_STRIDE + kk0 + tig];
            unsigned a2 = as[rbase + kk0 + tig + 4];
            unsigned a3 = as[rbase + 8*AS_STRIDE + kk0 + tig + 4];
#pragma unroll
            for (int ni = 0; ni < 4; ni++) {
                int col = wn + ni*8 + gid;
                unsigned b0 = bs[(kk0 + tig)*BS_STRIDE + col];
                unsigned b1 = bs[(kk0 + tig + 4)*BS_STRIDE + col];
                mma8(acc[ni], a0, a1, a2, a3, b0, b1);
            }
        }
        if (kc < 11) {
            __syncthreads();
            int nxt = cur ^ 1;
#pragma unroll
            for (int i = 0; i < 2; i++) {
                unsigned* p = &As[nxt][(ar + i*32)*AS_STRIDE + ac];
                p[0]=f2tf32(pa[i].x); p[1]=f2tf32(pa[i].y); p[2]=f2tf32(pa[i].z); p[3]=f2tf32(pa[i].w);
            }
#pragma unroll
            for (int q = 0; q < 2; q++)
                *(float4*)&Bs[nxt][bk[q]*BS_STRIDE + bc4[q]] = pb[q];
            __syncthreads();
        }
    }

    if (cls == 2) {
        int r0 = bm + wm + gid;
#pragma unroll
        for (int ni = 0; ni < 4; ni++) {
            int c0 = nloc + wn + ni*8 + tig*2;
            float v0 = 1.f/(1.f+expf(-acc[ni][0]));
            float v1 = 1.f/(1.f+expf(-acc[ni][1]));
            float v2 = 1.f/(1.f+expf(-acc[ni][2]));
            float v3 = 1.f/(1.f+expf(-acc[ni][3]));
            *(float2*)&g_sr[(size_t)r0*C_ + c0]     = make_float2(v0, v1);
            *(float2*)&g_sr[(size_t)(r0+8)*C_ + c0] = make_float2(v2, v3);
        }
        return;
    }

    if (cls == 1) {
        int r0 = bm + wm + gid;
#pragma unroll
        for (int ni = 0; ni < 4; ni++) {
            int cg = nloc + wn + ni*8 + tig*2;
            float2 p0 = *(const float2*)&g_peak[(size_t)r0*C_ + cg];
            float2 p1 = *(const float2*)&g_peak[(size_t)(r0+8)*C_ + cg];
            acc[ni][0] += p0.x; acc[ni][1] += p0.y;
            acc[ni][2] += p1.x; acc[ni][3] += p1.y;
        }
    }

    // transpose-write to kT / vT
    __syncthreads();
    float* st = (float*)&As[0][0];    // 64 x 65 stage (4160 <= 4608 words)
    {
        int r = wm + gid;
#pragma unroll
        for (int ni = 0; ni < 4; ni++) {
            int cc = wn + ni*8 + tig*2;
            st[r*65 + cc]       = acc[ni][0];
            st[r*65 + cc + 1]   = acc[ni][1];
            st[(r+8)*65 + cc]   = acc[ni][2];
            st[(r+8)*65 + cc+1] = acc[ni][3];
        }
    }
    __syncthreads();
    float* dst = (cls == 0) ? g_kT : g_vT;
    int bb = bm >> 12, trow = bm & 4095;
#pragma unroll
    for (int q = 0; q < 4; q++) {
        int cr = q*16 + (tid >> 4);
        int t0 = (tid & 15) * 4;
        float4 v;
        v.x = st[(t0+0)*65 + cr];
        v.y = st[(t0+1)*65 + cr];
        v.z = st[(t0+2)*65 + cr];
        v.w = st[(t0+3)*65 + cr];
        *(float4*)&dst[((size_t)(bb*C_ + nloc + cr))*T_ + trow + t0] = v;
    }
}

// ---------------- bidirectional WKV scan (coalesced smem redistribution) ----------------
struct Agg { float a, b, dl; };
__device__ __forceinline__ Agg combine(Agg p, Agg s) {
    Agg r;
    r.a  = fmaf(s.dl, p.a, s.a);
    r.b  = fmaf(s.dl, p.b, s.b);
    r.dl = p.dl * s.dl;
    return r;
}
__device__ __forceinline__ Agg shfl_up_agg(Agg v, int off) {
    Agg r;
    r.a  = __shfl_up_sync(0xffffffffu, v.a,  off);
    r.b  = __shfl_up_sync(0xffffffffu, v.b,  off);
    r.dl = __shfl_up_sync(0xffffffffu, v.dl, off);
    return r;
}
__device__ __forceinline__ Agg shfl_dn_agg(Agg v, int off) {
    Agg r;
    r.a  = __shfl_down_sync(0xffffffffu, v.a,  off);
    r.b  = __shfl_down_sync(0xffffffffu, v.b,  off);
    r.dl = __shfl_down_sync(0xffffffffu, v.dl, off);
    return r;
}

__global__ __launch_bounds__(256) void wkv_kernel(const float* __restrict__ sd,
                                                  const float* __restrict__ sf) {
    __shared__ float eks[4352];    // addr(t) = t + (t>>4), conflict-free both phases
    __shared__ float vvs[4352];
    __shared__ Agg warpAgg[8];
    __shared__ Agg warpPre[8];
    int bc = blockIdx.x;
    int c = bc % C_;
    float w  = sd[c] * (1.0f / T_);
    float u  = sf[c] * (1.0f / T_);
    float d  = expf(-w);
    float eu = expf(u);
    float d2 = d*d, d4 = d2*d2, d8 = d4*d4, d16 = d8*d8;
    int tid = threadIdx.x;
    int lane = tid & 31, wid = tid >> 5;
    const float4* kp4 = (const float4*)(g_kT + (size_t)bc * T_);
    const float4* vp4 = (const float4*)(g_vT + (size_t)bc * T_);

    // coalesced load + exp, into padded smem
#pragma unroll
    for (int q = 0; q < 4; q++) {
        int idx = tid + q*256;
        float4 kv = kp4[idx];
        float4 v4 = vp4[idx];
        int t = idx * 4;
        int base = t + (t >> 4);
        eks[base+0] = expf(kv.x); eks[base+1] = expf(kv.y);
        eks[base+2] = expf(kv.z); eks[base+3] = expf(kv.w);
        vvs[base+0] = v4.x; vvs[base+1] = v4.y;
        vvs[base+2] = v4.z; vvs[base+3] = v4.w;
    }
    __syncthreads();

    float ek[16], vv[16];
    int rb = 17 * tid;
#pragma unroll
    for (int i = 0; i < 16; i++) { ek[i] = eks[rb + i]; vv[i] = vvs[rb + i]; }

    Agg ag; ag.a = 0.f; ag.b = 0.f; ag.dl = d16;
#pragma unroll
    for (int i = 0; i < 16; i++) {
        ag.a = fmaf(d, ag.a, ek[i]);
        ag.b = fmaf(d, ag.b, ek[i]*vv[i]);
    }
    Agg inc = ag;
#pragma unroll
    for (int off = 1; off < 32; off <<= 1) {
        Agg o = shfl_up_agg(inc, off);
        if (lane >= off) inc = combine(o, inc);
    }
    if (lane == 31) warpAgg[wid] = inc;
    __syncthreads();
    if (tid == 0) {
        Agg run; run.a = 0.f; run.b = 0.f; run.dl = 1.f;
        for (int i = 0; i < 8; i++) { warpPre[i] = run; run = combine(run, warpAgg[i]); }
    }
    __syncthreads();
    Agg pl = shfl_up_agg(inc, 1);
    Agg ex = warpPre[wid];
    if (lane > 0) ex = combine(ex, pl);

    float af = ex.a, bf = ex.b;
    float saf[16], sbf[16];
#pragma unroll
    for (int i = 0; i < 16; i++) {
        saf[i] = af; sbf[i] = bf;
        af = fmaf(d, af, ek[i]);
        bf = fmaf(d, bf, ek[i]*vv[i]);
    }
    __syncthreads();

    Agg bg; bg.a = 0.f; bg.b = 0.f; bg.dl = d16;
#pragma unroll
    for (int i = 15; i >= 0; i--) {
        bg.a = fmaf(d, bg.a, ek[i]);
        bg.b = fmaf(d, bg.b, ek[i]*vv[i]);
    }
    Agg binc = bg;
#pragma unroll
    for (int off = 1; off < 32; off <<= 1) {
        Agg o = shfl_dn_agg(binc, off);
        if (lane < 32 - off) binc = combine(o, binc);
    }
    if (lane == 0) warpAgg[wid] = binc;
    __syncthreads();
    if (tid == 0) {
        Agg run; run.a = 0.f; run.b = 0.f; run.dl = 1.f;
        for (int i = 7; i >= 0; i--) { warpPre[i] = run; run = combine(run, warpAgg[i]); }
    }
    __syncthreads();
    Agg bpl = shfl_dn_agg(binc, 1);
    Agg bex = warpPre[wid];
    if (lane < 31) bex = combine(bex, bpl);

    float ab = bex.a, bb = bex.b;
#pragma unroll
    for (int i = 15; i >= 0; i--) {
        float es  = eu * ek[i];
        float num = sbf[i] + bb + es * vv[i];
        float den = saf[i] + ab + es;
        vvs[rb + i] = num / den;            // stage y in padded smem
        ab = fmaf(d, ab, ek[i]);
        bb = fmaf(d, bb, ek[i]*vv[i]);
    }
    __syncthreads();

    // coalesced store
    float4* yp4 = (float4*)(g_yT + (size_t)bc * T_);
#pragma unroll
    for (int q = 0; q < 4; q++) {
        int idx = tid + q*256;
        int t = idx * 4;
        int base = t + (t >> 4);
        yp4[idx] = make_float4(vvs[base+0], vvs[base+1], vvs[base+2], vvs[base+3]);
    }
}

// ---------------- output GEMM (1x tf32): out = (sr .* y) @ Wo ----------------
#define A2_STRIDE 197

__global__ __launch_bounds__(128) void gemm2_kernel(float* __restrict__ out) {
    __shared__ unsigned As2[32 * A2_STRIDE];
    __shared__ unsigned Bs2[2][32 * BS_STRIDE];

    int tid = threadIdx.x;
    int warp = tid >> 5, lane = tid & 31;
    int gid = lane >> 2, tig = lane & 3;
    int bm = blockIdx.x * 32;
    int bn = blockIdx.y * 64;
    int wm = (warp >> 1) * 16;
    int wn = (warp & 1) * 32;
    int bb = bm >> 12, trow = bm & 4095;

#pragma unroll
    for (int q = 0; q < 12; q++) {
        int f = q*128 + tid;
        int row = f >> 3;
        int t4 = (f & 7) * 4;
        float4 v = *(const float4*)&g_yT[((size_t)(bb*C_ + row))*T_ + trow + t4];
        As2[(t4+0)*A2_STRIDE + row] = __float_as_uint(v.x);
        As2[(t4+1)*A2_STRIDE + row] = __float_as_uint(v.y);
        As2[(t4+2)*A2_STRIDE + row] = __float_as_uint(v.z);
        As2[(t4+3)*A2_STRIDE + row] = __float_as_uint(v.w);
    }
    __syncthreads();
#pragma unroll
    for (int q = 0; q < 12; q++) {
        int f = q*128 + tid;
        int t = f / 48, c4 = (f % 48) * 4;
        float4 s = *(const float4*)&g_sr[((size_t)(bm + t))*C_ + c4];
        unsigned* p = &As2[t*A2_STRIDE + c4];
        p[0] = f2tf32(__uint_as_float(p[0]) * s.x);
        p[1] = f2tf32(__uint_as_float(p[1]) * s.y);
        p[2] = f2tf32(__uint_as_float(p[2]) * s.z);
        p[3] = f2tf32(__uint_as_float(p[3]) * s.w);
    }

    int br = tid >> 4;
    int bc = (tid & 15) * 4;
    float acc[4][4] = {};

    float4 pb[4];
#pragma unroll
    for (int i = 0; i < 4; i++)
        pb[i] = *(const float4*)&g_Wo[(size_t)(br + i*8)*C_ + bn + bc];
#pragma unroll
    for (int i = 0; i < 4; i++)
        *(float4*)&Bs2[0][(br + i*8)*BS_STRIDE + bc] = pb[i];   // pre-rounded, raw
    __syncthreads();

    for (int kc = 0; kc < 6; kc++) {
        int cur = kc & 1;
        if (kc < 5) {
            int k0 = (kc + 1) * 32;
#pragma unroll
            for (int i = 0; i < 4; i++)
                pb[i] = *(const float4*)&g_Wo[(size_t)(k0 + br + i*8)*C_ + bn + bc];
        }
        const unsigned* bs = Bs2[cur];
        int k0 = kc * 32;
#pragma unroll
        for (int ks = 0; ks < 4; ks++) {
            int kk = k0 + ks*8;
            unsigned a0 = As2[(wm+gid)*A2_STRIDE + kk + tig];
            unsigned a1 = As2[(wm+gid+8)*A2_STRIDE + kk + tig];
            unsigned a2 = As2[(wm+gid)*A2_STRIDE + kk + tig + 4];
            unsigned a3 = As2[(wm+gid+8)*A2_STRIDE + kk + tig + 4];
#pragma unroll
            for (int ni = 0; ni < 4; ni++) {
                int col = wn + ni*8 + gid;
                unsigned b0 = bs[(ks*8 + tig)*BS_STRIDE + col];
                unsigned b1 = bs[(ks*8 + tig + 4)*BS_STRIDE + col];
                mma8(acc[ni], a0, a1, a2, a3, b0, b1);
            }
        }
        if (kc < 5) {
            __syncthreads();
            int nxt = cur ^ 1;
#pragma unroll
            for (int i = 0; i < 4; i++)
                *(float4*)&Bs2[nxt][(br + i*8)*BS_STRIDE + bc] = pb[i];
            __syncthreads();
        }
    }

    int r0 = bm + wm + gid;
#pragma unroll
    for (int ni = 0; ni < 4; ni++) {
        int c0 = bn + wn + ni*8 + tig*2;
        *(float2*)&out[(size_t)r0*C_ + c0]     = make_float2(acc[ni][0], acc[ni][1]);
        *(float2*)&out[(size_t)(r0+8)*C_ + c0] = make_float2(acc[ni][2], acc[ni][3]);
    }
}

// ---------------- launch ----------------
extern "C" void kernel_launch(void* const* d_in, const int* in_sizes, int n_in,
                              void* d_out, int out_size) {
    const float* x = (const float*)d_in[0];
    int base = (in_sizes[1] == 1) ? 3 : 1;
    const float* mk    = (const float*)d_in[base + 0];
    const float* mv    = (const float*)d_in[base + 1];
    const float* mr    = (const float*)d_in[base + 2];
    const float* Wk    = (const float*)d_in[base + 3];
    const float* Wv    = (const float*)d_in[base + 4];
    const float* Wr    = (const float*)d_in[base + 5];
    const float* Wo    = (const float*)d_in[base + 6];
    const float* sd    = (const float*)d_in[base + 7];
    const float* sf    = (const float*)d_in[base + 8];
    const float* cvw   = (const float*)d_in[base + 9];
    const float* cvb   = (const float*)d_in[base + 10];
    const float* bns_v = (const float*)d_in[base + 11];
    const float* bnb_v = (const float*)d_in[base + 12];
    const float* chw   = (const float*)d_in[base + 13];
    const float* chb   = (const float*)d_in[base + 14];
    const float* bns_h = (const float*)d_in[base + 15];
    const float* bnb_h = (const float*)d_in[base + 16];

    wprep_kernel<<<1032, 256>>>(mk, mv, mr, Wk, Wv, Wr, Wo, cvw, chw);
    convP_kernel<<<1024, 256>>>(x);
    peak_kernel<<<512, 768>>>(x, cvb, bns_v, bnb_v, chb, bns_h, bnb_h);
    gemm1_kernel<<<dim3(128, 9), 256>>>(x);
    wkv_kernel<<<B_*C_, 256>>>(sd, sf);
    gemm2_kernel<<<dim3(256, 3), 128>>>((float*)d_out);
}

// round 8
// speedup vs baseline: 1.4596x; 1.0211x over previous
#include <cuda_runtime.h>
#include <math.h>

#define B_ 2
#define T_ 4096
#define C_ 192
#define NTOT (B_*T_*C_)

// ---------------- scratch ----------------
__device__ float g_Wf[384*576];      // tf32-pre-rounded fused [k|v|r] weights
__device__ float g_Wo[192*192];      // tf32-pre-rounded output weights
__device__ float g_Wp[192*32];       // exact fp32 conv-tap weights
__device__ float g_A[B_*T_*384];     // tf32-pre-rounded [x | qshift(x)]
__device__ float g_P[B_*T_*32];
__device__ float g_peak[NTOT];
__device__ float g_kT[NTOT];
__device__ float g_vT[NTOT];
__device__ float g_yT[NTOT];
__device__ float g_sr[NTOT];

__constant__ float c_prfx[16] = {-2,-2,-2,-2, -2,-1,0,1,  2,2,2,2,  -1,0,1,2};
__constant__ float c_prfy[16] = {-2,-1,0,1,   2,2,2,2,  -1,0,1,2,  -2,-2,-2,-2};

__device__ __forceinline__ unsigned f2tf32(float x) {
    unsigned r;
    asm("cvt.rna.tf32.f32 %0, %1;" : "=r"(r) : "f"(x));
    return r;
}

__device__ __forceinline__ void mma8(float* d, unsigned a0, unsigned a1, unsigned a2, unsigned a3,
                                     unsigned b0, unsigned b1) {
    asm volatile(
        "mma.sync.aligned.m16n8k8.row.col.f32.tf32.tf32.f32 "
        "{%0,%1,%2,%3}, {%4,%5,%6,%7}, {%8,%9}, {%0,%1,%2,%3};\n"
        : "+f"(d[0]), "+f"(d[1]), "+f"(d[2]), "+f"(d[3])
        : "r"(a0), "r"(a1), "r"(a2), "r"(a3), "r"(b0), "r"(b1));
}

// ---------------- weight prep ----------------
__global__ void wprep_kernel(const float* __restrict__ mk, const float* __restrict__ mv,
                             const float* __restrict__ mr,
                             const float* __restrict__ Wk, const float* __restrict__ Wv,
                             const float* __restrict__ Wr, const float* __restrict__ Wo,
                             const float* __restrict__ cvw, const float* __restrict__ chw) {
    int i = blockIdx.x * 256 + threadIdx.x;
    if (i < 384*576) {
        int row = i / 576, n = i % 576;
        int c = row % 192;
        bool second = row >= 192;
        const float* W; float m; int nn;
        if (n < 192)      { W = Wk; m = mk[c]; nn = n; }
        else if (n < 384) { W = Wv; m = mv[c]; nn = n - 192; }
        else              { W = Wr; m = mr[c]; nn = n - 384; }
        float v = (second ? (1.f - m) : m) * W[c*192 + nn];
        g_Wf[i] = __uint_as_float(f2tf32(v));
        return;
    }
    int j = i - 384*576;
    if (j < 192*32) {
        int c = j / 32, n = j % 32;
        float v = 0.f;
        if (n < 14)      v = cvw[(n/7)*C_*7 + c*7 + (n%7)];
        else if (n < 28) { int n2 = n - 14; v = chw[(n2/7)*C_*7 + c*7 + (n2%7)]; }
        g_Wp[j] = v;   // exact fp32
        return;
    }
    int jj = j - 192*32;
    if (jj < 192*192)
        g_Wo[jj] = __uint_as_float(f2tf32(Wo[jj]));
}

// ---------------- A prep: g_A = tf32([x | qshift(x)]), (t, 384) layout ----------------
__global__ __launch_bounds__(384) void aprep_kernel(const float* __restrict__ x) {
    int tb = blockIdx.x * 8;
    int k = threadIdx.x;
#pragma unroll
    for (int j = 0; j < 8; j++) {
        int gt = tb + j;
        float v;
        if (k < 192) {
            v = x[(size_t)gt*C_ + k];
        } else {
            int c = k - 192;
            int tt = gt & 4095;
            int hh = tt >> 6, ww = tt & 63;
            int g = c / 48;
            int src; bool ok;
            if (g == 0)      { ok = (ww >= 1);  src = gt - 1; }
            else if (g == 1) { ok = (ww <= 62); src = gt + 1; }
            else if (g == 2) { ok = (hh >= 1);  src = gt - 64; }
            else             { ok = (hh <= 62); src = gt + 64; }
            v = ok ? x[(size_t)src*C_ + c] : 0.f;
        }
        g_A[(size_t)gt*384 + k] = __uint_as_float(f2tf32(v));
    }
}

// ---------------- conv taps fp32 exact: P[8192][28] = x @ Wp ----------------
__global__ __launch_bounds__(256) void convP_kernel(const float* __restrict__ x) {
    __shared__ float xs[8][193];
    int tid = threadIdx.x;
    int tok0 = blockIdx.x * 8;
    for (int i = tid; i < 8*192; i += 256) {
        int r = i / 192, c = i % 192;
        xs[r][c] = x[(size_t)(tok0 + r)*C_ + c];
    }
    __syncthreads();
    int r = tid >> 5, n = tid & 31;
    if (n < 28) {
        float acc = 0.f;
#pragma unroll 8
        for (int c = 0; c < 192; c++)
            acc = fmaf(xs[r][c], g_Wp[c*32 + n], acc);
        g_P[(size_t)(tok0 + r)*32 + n] = acc;
    }
}

// ---------------- adaptive peak (gb fused, 768 threads, 16 tokens/block) ----------------
__global__ __launch_bounds__(768) void peak_kernel(const float* __restrict__ x,
                                                   const float* __restrict__ cvb,
                                                   const float* __restrict__ bns_v,
                                                   const float* __restrict__ bnb_v,
                                                   const float* __restrict__ chb,
                                                   const float* __restrict__ bns_h,
                                                   const float* __restrict__ bnb_h) {
    int bi = blockIdx.x;                  // 512 blocks
    int b = bi >> 8;
    int tb = (bi & 255) * 16;
    int hh = tb >> 6, wwb = tb & 63;
    __shared__ float gbv[16][4];
    __shared__ int   s_lt[16][16], s_rb[16][16];
    __shared__ float s_wlt[16][16], s_wrb[16][16];
    int tid = threadIdx.x;

    if (tid < 64) {
        int j = tid >> 2, dir = tid & 3;
        int ww = wwb + j;
        const float* Pb = g_P + (size_t)b * T_ * 32;
        float s = 0.f;
        if (dir < 2) {
#pragma unroll
            for (int r = 0; r < 7; r++) {
                int hy = hh + r - 3;
                if (hy >= 0 && hy < 64) s += Pb[(size_t)(hy*64 + ww)*32 + dir*7 + r];
            }
        } else {
#pragma unroll
            for (int r = 0; r < 7; r++) {
                int wy = ww + r - 3;
                if (wy >= 0 && wy < 64) s += Pb[(size_t)(hh*64 + wy)*32 + (dir-2)*7 + 14 + r];
            }
        }
        const float inv = rsqrtf(1.f + 1e-5f);
        float bias, scale, shift;
        if (dir == 0)      { bias = cvb[0]; scale = bns_v[0]; shift = bnb_v[0]; }
        else if (dir == 1) { bias = cvb[1]; scale = bns_v[1]; shift = bnb_v[1]; }
        else if (dir == 2) { bias = chb[0]; scale = bns_h[0]; shift = bnb_h[0]; }
        else               { bias = chb[1]; scale = bns_h[1]; shift = bnb_h[1]; }
        float val = (s + bias) * (scale * inv) + shift;
        gbv[j][dir] = 2.f / (1.f + expf(-val));
    }
    __syncthreads();

    if (tid < 256) {
        int j = tid >> 4, o = tid & 15;
        int ww = wwb + j;
        int blk = o >> 2;
        float mx = 0.f, my = 0.f;
        if (blk == 0)      mx = -gbv[j][0];
        else if (blk == 1) my =  gbv[j][3];
        else if (blk == 2) mx =  gbv[j][1];
        else               my = -gbv[j][2];
        float px = (float)(hh + 2) + c_prfx[o] + mx;
        float py = (float)(ww + 2) + c_prfy[o] + my;
        float flx = floorf(px), fly = floorf(py);
        float qltx = fminf(fmaxf(flx,     0.f), 67.f);
        float qlty = fminf(fmaxf(fly,     0.f), 67.f);
        float qrbx = fminf(fmaxf(flx+1.f, 0.f), 67.f);
        float qrby = fminf(fmaxf(fly+1.f, 0.f), 67.f);
        float pxc  = fminf(fmaxf(px,      0.f), 67.f);
        float pyc  = fminf(fmaxf(py,      0.f), 67.f);
        float glt = (1.f + (qltx - pxc)) * (1.f + (qlty - pyc));
        float grb = (1.f - (qrbx - pxc)) * (1.f - (qrby - pyc));
        int rlt = min(max((int)qltx - 2, 0), 63);
        int clt = min(max((int)qlty - 2, 0), 63);
        int rrb = min(max((int)qrbx - 2, 0), 63);
        int crb = min(max((int)qrby - 2, 0), 63);
        s_lt[j][o] = rlt*64 + clt;  s_rb[j][o] = rrb*64 + crb;
        s_wlt[j][o] = glt;          s_wrb[j][o] = grb;
    }
    __syncthreads();

    const float* xb = x + (size_t)b * T_ * C_;
    int j = tid / 48;
    int c4 = (tid % 48) * 4;
    float a0 = 0.f, a1 = 0.f, a2 = 0.f, a3 = 0.f;
#pragma unroll
    for (int o = 0; o < 16; o++) {
        float4 a = *(const float4*)&xb[(size_t)s_lt[j][o]*C_ + c4];
        float4 bv = *(const float4*)&xb[(size_t)s_rb[j][o]*C_ + c4];
        float wl = s_wlt[j][o], wr = s_wrb[j][o];
        a0 += wl*a.x + wr*bv.x;
        a1 += wl*a.y + wr*bv.y;
        a2 += wl*a.z + wr*bv.z;
        a3 += wl*a.w + wr*bv.w;
    }
    size_t idx = ((size_t)b*T_ + tb + j)*C_ + c4;
    float4 xc = *(const float4*)&x[idx];
    float4 outv;
    outv.x = xc.x - a0*(1.f/16.f);
    outv.y = xc.y - a1*(1.f/16.f);
    outv.z = xc.z - a2*(1.f/16.f);
    outv.w = xc.w - a3*(1.f/16.f);
    *(float4*)&g_peak[idx] = outv;
}

// ---------------- fused front GEMM (1x tf32, warp tile 32x32): [k|v|r] = g_A @ Wf ----------------
#define AS_STRIDE 36
#define BS_STRIDE 72

__global__ __launch_bounds__(128) void gemm1_kernel() {
    __shared__ float As[2][64 * AS_STRIDE];
    __shared__ float Bs[2][32 * BS_STRIDE];

    int tid = threadIdx.x;
    int warp = tid >> 5, lane = tid & 31;
    int bm = blockIdx.x * 64;
    int bny = blockIdx.y;
    int bn = bny * 64;
    int cls = bny / 3;            // 0:k 1:v 2:r
    int nloc = bn - cls * 192;
    int wm = (warp >> 1) * 32;
    int wn = (warp & 1) * 32;
    int gid = lane >> 2, tig = lane & 3;

    int ar = tid >> 3, ac = (tid & 7) * 4;     // A: 4 float4/thread
    int brr = tid >> 4, bcc = (tid & 15) * 4;  // B: 4 float4/thread

    const float* Abase = g_A + (size_t)bm * 384;
    float acc[2][4][4] = {};
    float4 pa[4], pb[4];
#pragma unroll
    for (int i = 0; i < 4; i++) pa[i] = *(const float4*)&Abase[(size_t)(ar + i*16)*384 + ac];
#pragma unroll
    for (int q = 0; q < 4; q++) pb[q] = *(const float4*)&g_Wf[(size_t)(brr + q*8)*576 + bn + bcc];
#pragma unroll
    for (int i = 0; i < 4; i++) *(float4*)&As[0][(ar + i*16)*AS_STRIDE + ac] = pa[i];
#pragma unroll
    for (int q = 0; q < 4; q++) *(float4*)&Bs[0][(brr + q*8)*BS_STRIDE + bcc] = pb[q];
    __syncthreads();

    for (int kc = 0; kc < 12; kc++) {
        int cur = kc & 1;
        if (kc < 11) {
            int k0 = (kc + 1) * 32;
#pragma unroll
            for (int i = 0; i < 4; i++)
                pa[i] = *(const float4*)&Abase[(size_t)(ar + i*16)*384 + k0 + ac];
#pragma unroll
            for (int q = 0; q < 4; q++)
                pb[q] = *(const float4*)&g_Wf[(size_t)(k0 + brr + q*8)*576 + bn + bcc];
        }
        const float* as = As[cur];
        const float* bs = Bs[cur];
#pragma unroll
        for (int ks = 0; ks < 4; ks++) {
            int kk0 = ks * 8;
            unsigned afr[2][4], bfr[4][2];
#pragma unroll
            for (int mi = 0; mi < 2; mi++) {
                int rbase = (wm + mi*16 + gid) * AS_STRIDE;
                afr[mi][0] = __float_as_uint(as[rbase + kk0 + tig]);
                afr[mi][1] = __float_as_uint(as[rbase + 8*AS_STRIDE + kk0 + tig]);
                afr[mi][2] = __float_as_uint(as[rbase + kk0 + tig + 4]);
                afr[mi][3] = __float_as_uint(as[rbase + 8*AS_STRIDE + kk0 + tig + 4]);
            }
#pragma unroll
            for (int ni = 0; ni < 4; ni++) {
                int col = wn + ni*8 + gid;
                bfr[ni][0] = __float_as_uint(bs[(kk0 + tig)*BS_STRIDE + col]);
                bfr[ni][1] = __float_as_uint(bs[(kk0 + tig + 4)*BS_STRIDE + col]);
            }
#pragma unroll
            for (int mi = 0; mi < 2; mi++)
#pragma unroll
                for (int ni = 0; ni < 4; ni++)
                    mma8(acc[mi][ni], afr[mi][0], afr[mi][1], afr[mi][2], afr[mi][3],
                         bfr[ni][0], bfr[ni][1]);
        }
        if (kc < 11) {
            __syncthreads();
            int nxt = cur ^ 1;
#pragma unroll
            for (int i = 0; i < 4; i++) *(float4*)&As[nxt][(ar + i*16)*AS_STRIDE + ac] = pa[i];
#pragma unroll
            for (int q = 0; q < 4; q++) *(float4*)&Bs[nxt][(brr + q*8)*BS_STRIDE + bcc] = pb[q];
            __syncthreads();
        }
    }

    if (cls == 2) {
#pragma unroll
        for (int mi = 0; mi < 2; mi++) {
            int r0 = bm + wm + mi*16 + gid;
#pragma unroll
            for (int ni = 0; ni < 4; ni++) {
                int c0 = nloc + wn + ni*8 + tig*2;
                float v0 = 1.f/(1.f+expf(-acc[mi][ni][0]));
                float v1 = 1.f/(1.f+expf(-acc[mi][ni][1]));
                float v2 = 1.f/(1.f+expf(-acc[mi][ni][2]));
                float v3 = 1.f/(1.f+expf(-acc[mi][ni][3]));
                *(float2*)&g_sr[(size_t)r0*C_ + c0]     = make_float2(v0, v1);
                *(float2*)&g_sr[(size_t)(r0+8)*C_ + c0] = make_float2(v2, v3);
            }
        }
        return;
    }

    if (cls == 1) {
#pragma unroll
        for (int mi = 0; mi < 2; mi++) {
            int r0 = bm + wm + mi*16 + gid;
#pragma unroll
            for (int ni = 0; ni < 4; ni++) {
                int cg = nloc + wn + ni*8 + tig*2;
                float2 p0 = *(const float2*)&g_peak[(size_t)r0*C_ + cg];
                float2 p1 = *(const float2*)&g_peak[(size_t)(r0+8)*C_ + cg];
                acc[mi][ni][0] += p0.x; acc[mi][ni][1] += p0.y;
                acc[mi][ni][2] += p1.x; acc[mi][ni][3] += p1.y;
            }
        }
    }

    // transpose-write to kT / vT via st[c][t], stride 68
    __syncthreads();
    float* st = (float*)&As[0][0];    // 64*68 = 4352 words <= 4608
#pragma unroll
    for (int mi = 0; mi < 2; mi++) {
        int r = wm + mi*16 + gid;
#pragma unroll
        for (int ni = 0; ni < 4; ni++) {
            int cc = wn + ni*8 + tig*2;
            st[cc*68 + r]          = acc[mi][ni][0];
            st[(cc+1)*68 + r]      = acc[mi][ni][1];
            st[cc*68 + r + 8]      = acc[mi][ni][2];
            st[(cc+1)*68 + r + 8]  = acc[mi][ni][3];
        }
    }
    __syncthreads();
    float* dst = (cls == 0) ? g_kT : g_vT;
    int bb = bm >> 12, trow = bm & 4095;
#pragma unroll
    for (int q = 0; q < 8; q++) {
        int f = q*128 + tid;
        int cr = f >> 4;
        int t4 = (f & 15) * 4;
        float4 v = *(const float4*)&st[cr*68 + t4];
        *(float4*)&dst[((size_t)(bb*C_ + nloc + cr))*T_ + trow + t4] = v;
    }
}

// ---------------- bidirectional WKV scan (coalesced smem redistribution) ----------------
struct Agg { float a, b, dl; };
__device__ __forceinline__ Agg combine(Agg p, Agg s) {
    Agg r;
    r.a  = fmaf(s.dl, p.a, s.a);
    r.b  = fmaf(s.dl, p.b, s.b);
    r.dl = p.dl * s.dl;
    return r;
}
__device__ __forceinline__ Agg shfl_up_agg(Agg v, int off) {
    Agg r;
    r.a  = __shfl_up_sync(0xffffffffu, v.a,  off);
    r.b  = __shfl_up_sync(0xffffffffu, v.b,  off);
    r.dl = __shfl_up_sync(0xffffffffu, v.dl, off);
    return r;
}
__device__ __forceinline__ Agg shfl_dn_agg(Agg v, int off) {
    Agg r;
    r.a  = __shfl_down_sync(0xffffffffu, v.a,  off);
    r.b  = __shfl_down_sync(0xffffffffu, v.b,  off);
    r.dl = __shfl_down_sync(0xffffffffu, v.dl, off);
    return r;
}

__global__ __launch_bounds__(256) void wkv_kernel(const float* __restrict__ sd,
                                                  const float* __restrict__ sf) {
    __shared__ float eks[4352];
    __shared__ float vvs[4352];
    __shared__ Agg warpAgg[8];
    __shared__ Agg warpPre[8];
    int bc = blockIdx.x;
    int c = bc % C_;
    float w  = sd[c] * (1.0f / T_);
    float u  = sf[c] * (1.0f / T_);
    float d  = expf(-w);
    float eu = expf(u);
    float d2 = d*d, d4 = d2*d2, d8 = d4*d4, d16 = d8*d8;
    int tid = threadIdx.x;
    int lane = tid & 31, wid = tid >> 5;
    const float4* kp4 = (const float4*)(g_kT + (size_t)bc * T_);
    const float4* vp4 = (const float4*)(g_vT + (size_t)bc * T_);

#pragma unroll
    for (int q = 0; q < 4; q++) {
        int idx = tid + q*256;
        float4 kv = kp4[idx];
        float4 v4 = vp4[idx];
        int t = idx * 4;
        int base = t + (t >> 4);
        eks[base+0] = expf(kv.x); eks[base+1] = expf(kv.y);
        eks[base+2] = expf(kv.z); eks[base+3] = expf(kv.w);
        vvs[base+0] = v4.x; vvs[base+1] = v4.y;
        vvs[base+2] = v4.z; vvs[base+3] = v4.w;
    }
    __syncthreads();

    float ek[16], vv[16];
    int rb = 17 * tid;
#pragma unroll
    for (int i = 0; i < 16; i++) { ek[i] = eks[rb + i]; vv[i] = vvs[rb + i]; }

    Agg ag; ag.a = 0.f; ag.b = 0.f; ag.dl = d16;
#pragma unroll
    for (int i = 0; i < 16; i++) {
        ag.a = fmaf(d, ag.a, ek[i]);
        ag.b = fmaf(d, ag.b, ek[i]*vv[i]);
    }
    Agg inc = ag;
#pragma unroll
    for (int off = 1; off < 32; off <<= 1) {
        Agg o = shfl_up_agg(inc, off);
        if (lane >= off) inc = combine(o, inc);
    }
    if (lane == 31) warpAgg[wid] = inc;
    __syncthreads();
    if (tid == 0) {
        Agg run; run.a = 0.f; run.b = 0.f; run.dl = 1.f;
        for (int i = 0; i < 8; i++) { warpPre[i] = run; run = combine(run, warpAgg[i]); }
    }
    __syncthreads();
    Agg pl = shfl_up_agg(inc, 1);
    Agg ex = warpPre[wid];
    if (lane > 0) ex = combine(ex, pl);

    float af = ex.a, bf = ex.b;
    float saf[16], sbf[16];
#pragma unroll
    for (int i = 0; i < 16; i++) {
        saf[i] = af; sbf[i] = bf;
        af = fmaf(d, af, ek[i]);
        bf = fmaf(d, bf, ek[i]*vv[i]);
    }
    __syncthreads();

    Agg bg; bg.a = 0.f; bg.b = 0.f; bg.dl = d16;
#pragma unroll
    for (int i = 15; i >= 0; i--) {
        bg.a = fmaf(d, bg.a, ek[i]);
        bg.b = fmaf(d, bg.b, ek[i]*vv[i]);
    }
    Agg binc = bg;
#pragma unroll
    for (int off = 1; off < 32; off <<= 1) {
        Agg o = shfl_dn_agg(binc, off);
        if (lane < 32 - off) binc = combine(o, binc);
    }
    if (lane == 0) warpAgg[wid] = binc;
    __syncthreads();
    if (tid == 0) {
        Agg run; run.a = 0.f; run.b = 0.f; run.dl = 1.f;
        for (int i = 7; i >= 0; i--) { warpPre[i] = run; run = combine(run, warpAgg[i]); }
    }
    __syncthreads();
    Agg bpl = shfl_dn_agg(binc, 1);
    Agg bex = warpPre[wid];
    if (lane < 31) bex = combine(bex, bpl);

    float ab = bex.a, bb = bex.b;
#pragma unroll
    for (int i = 15; i >= 0; i--) {
        float es  = eu * ek[i];
        float num = sbf[i] + bb + es * vv[i];
        float den = saf[i] + ab + es;
        vvs[rb + i] = num / den;
        ab = fmaf(d, ab, ek[i]);
        bb = fmaf(d, bb, ek[i]*vv[i]);
    }
    __syncthreads();

    float4* yp4 = (float4*)(g_yT + (size_t)bc * T_);
#pragma unroll
    for (int q = 0; q < 4; q++) {
        int idx = tid + q*256;
        int t = idx * 4;
        int base = t + (t >> 4);
        yp4[idx] = make_float4(vvs[base+0], vvs[base+1], vvs[base+2], vvs[base+3]);
    }
}

// ---------------- output GEMM (1x tf32): out = (sr .* y) @ Wo ----------------
#define A2_STRIDE 197

__global__ __launch_bounds__(128) void gemm2_kernel(float* __restrict__ out) {
    __shared__ unsigned As2[32 * A2_STRIDE];
    __shared__ unsigned Bs2[2][32 * BS_STRIDE];

    int tid = threadIdx.x;
    int warp = tid >> 5, lane = tid & 31;
    int gid = lane >> 2, tig = lane & 3;
    int bm = blockIdx.x * 32;
    int bn = blockIdx.y * 64;
    int wm = (warp >> 1) * 16;
    int wn = (warp & 1) * 32;
    int bb = bm >> 12, trow = bm & 4095;

#pragma unroll
    for (int q = 0; q < 12; q++) {
        int f = q*128 + tid;
        int row = f >> 3;
        int t4 = (f & 7) * 4;
        float4 v = *(const float4*)&g_yT[((size_t)(bb*C_ + row))*T_ + trow + t4];
        As2[(t4+0)*A2_STRIDE + row] = __float_as_uint(v.x);
        As2[(t4+1)*A2_STRIDE + row] = __float_as_uint(v.y);
        As2[(t4+2)*A2_STRIDE + row] = __float_as_uint(v.z);
        As2[(t4+3)*A2_STRIDE + row] = __float_as_uint(v.w);
    }
    __syncthreads();
#pragma unroll
    for (int q = 0; q < 12; q++) {
        int f = q*128 + tid;
        int t = f / 48, c4 = (f % 48) * 4;
        float4 s = *(const float4*)&g_sr[((size_t)(bm + t))*C_ + c4];
        unsigned* p = &As2[t*A2_STRIDE + c4];
        p[0] = f2tf32(__uint_as_float(p[0]) * s.x);
        p[1] = f2tf32(__uint_as_float(p[1]) * s.y);
        p[2] = f2tf32(__uint_as_float(p[2]) * s.z);
        p[3] = f2tf32(__uint_as_float(p[3]) * s.w);
    }

    int br = tid >> 4;
    int bc = (tid & 15) * 4;
    float acc[4][4] = {};

    float4 pb[4];
#pragma unroll
    for (int i = 0; i < 4; i++)
        pb[i] = *(const float4*)&g_Wo[(size_t)(br + i*8)*C_ + bn + bc];
#pragma unroll
    for (int i = 0; i < 4; i++)
        *(float4*)&Bs2[0][(br + i*8)*BS_STRIDE + bc] = pb[i];
    __syncthreads();

    for (int kc = 0; kc < 6; kc++) {
        int cur = kc & 1;
        if (kc < 5) {
            int k0 = (kc + 1) * 32;
#pragma unroll
            for (int i = 0; i < 4; i++)
                pb[i] = *(const float4*)&g_Wo[(size_t)(k0 + br + i*8)*C_ + bn + bc];
        }
        const unsigned* bs = Bs2[cur];
        int k0 = kc * 32;
#pragma unroll
        for (int ks = 0; ks < 4; ks++) {
            int kk = k0 + ks*8;
            unsigned a0 = As2[(wm+gid)*A2_STRIDE + kk + tig];
            unsigned a1 = As2[(wm+gid+8)*A2_STRIDE + kk + tig];
            unsigned a2 = As2[(wm+gid)*A2_STRIDE + kk + tig + 4];
            unsigned a3 = As2[(wm+gid+8)*A2_STRIDE + kk + tig + 4];
#pragma unroll
            for (int ni = 0; ni < 4; ni++) {
                int col = wn + ni*8 + gid;
                unsigned b0 = bs[(ks*8 + tig)*BS_STRIDE + col];
                unsigned b1 = bs[(ks*8 + tig + 4)*BS_STRIDE + col];
                mma8(acc[ni], a0, a1, a2, a3, b0, b1);
            }
        }
        if (kc < 5) {
            __syncthreads();
            int nxt = cur ^ 1;
#pragma unroll
            for (int i = 0; i < 4; i++)
                *(float4*)&Bs2[nxt][(br + i*8)*BS_STRIDE + bc] = pb[i];
            __syncthreads();
        }
    }

    int r0 = bm + wm + gid;
#pragma unroll
    for (int ni = 0; ni < 4; ni++) {
        int c0 = bn + wn + ni*8 + tig*2;
        *(float2*)&out[(size_t)r0*C_ + c0]     = make_float2(acc[ni][0], acc[ni][1]);
        *(float2*)&out[(size_t)(r0+8)*C_ + c0] = make_float2(acc[ni][2], acc[ni][3]);
    }
}

// ---------------- launch ----------------
extern "C" void kernel_launch(void* const* d_in, const int* in_sizes, int n_in,
                              void* d_out, int out_size) {
    const float* x = (const float*)d_in[0];
    int base = (in_sizes[1] == 1) ? 3 : 1;
    const float* mk    = (const float*)d_in[base + 0];
    const float* mv    = (const float*)d_in[base + 1];
    const float* mr    = (const float*)d_in[base + 2];
    const float* Wk    = (const float*)d_in[base + 3];
    const float* Wv    = (const float*)d_in[base + 4];
    const float* Wr    = (const float*)d_in[base + 5];
    const float* Wo    = (const float*)d_in[base + 6];
    const float* sd    = (const float*)d_in[base + 7];
    const float* sf    = (const float*)d_in[base + 8];
    const float* cvw   = (const float*)d_in[base + 9];
    const float* cvb   = (const float*)d_in[base + 10];
    const float* bns_v = (const float*)d_in[base + 11];
    const float* bnb_v = (const float*)d_in[base + 12];
    const float* chw   = (const float*)d_in[base + 13];
    const float* chb   = (const float*)d_in[base + 14];
    const float* bns_h = (const float*)d_in[base + 15];
    const float* bnb_h = (const float*)d_in[base + 16];

    wprep_kernel<<<1032, 256>>>(mk, mv, mr, Wk, Wv, Wr, Wo, cvw, chw);
    aprep_kernel<<<1024, 384>>>(x);
    convP_kernel<<<1024, 256>>>(x);
    peak_kernel<<<512, 768>>>(x, cvb, bns_v, bnb_v, chb, bns_h, bnb_h);
    gemm1_kernel<<<dim3(128, 9), 128>>>();
    wkv_kernel<<<B_*C_, 256>>>(sd, sf);
    gemm2_kernel<<<dim3(256, 3), 128>>>((float*)d_out);
}

// round 9
// speedup vs baseline: 1.5387x; 1.0541x over previous
#include <cuda_runtime.h>
#include <math.h>

#define B_ 2
#define T_ 4096
#define C_ 192
#define NTOT (B_*T_*C_)

// ---------------- scratch ----------------
__device__ float g_Wf[384*576];      // tf32-pre-rounded fused [k|v|r] weights
__device__ float g_Wo[192*192];      // tf32-pre-rounded output weights
__device__ float g_Wp[192*32];       // exact fp32 conv-tap weights
__device__ float g_A[B_*T_*384];     // tf32-pre-rounded [x | qshift(x)]
__device__ float g_P[B_*T_*32];
__device__ float g_peak[NTOT];
__device__ float g_kT[NTOT];
__device__ float g_vT[NTOT];
__device__ float g_yT[NTOT];
__device__ float g_sr[NTOT];

__constant__ float c_prfx[16] = {-2,-2,-2,-2, -2,-1,0,1,  2,2,2,2,  -1,0,1,2};
__constant__ float c_prfy[16] = {-2,-1,0,1,   2,2,2,2,  -1,0,1,2,  -2,-2,-2,-2};

__device__ __forceinline__ unsigned f2tf32(float x) {
    unsigned r;
    asm("cvt.rna.tf32.f32 %0, %1;" : "=r"(r) : "f"(x));
    return r;
}

__device__ __forceinline__ void mma8(float* d, unsigned a0, unsigned a1, unsigned a2, unsigned a3,
                                     unsigned b0, unsigned b1) {
    asm volatile(
        "mma.sync.aligned.m16n8k8.row.col.f32.tf32.tf32.f32 "
        "{%0,%1,%2,%3}, {%4,%5,%6,%7}, {%8,%9}, {%0,%1,%2,%3};\n"
        : "+f"(d[0]), "+f"(d[1]), "+f"(d[2]), "+f"(d[3])
        : "r"(a0), "r"(a1), "r"(a2), "r"(a3), "r"(b0), "r"(b1));
}

// ---------------- merged prep: weights + A-matrix + conv taps ----------------
// blocks [0,688)        : weight prep (Wf tf32, Wp fp32, Wo tf32)
// blocks [688,1712)     : g_A = tf32([x | qshift(x)])
// blocks [1712,2736)    : g_P = x @ Wp (fp32 exact)
__global__ __launch_bounds__(384) void prep_kernel(const float* __restrict__ x,
                                                   const float* __restrict__ mk,
                                                   const float* __restrict__ mv,
                                                   const float* __restrict__ mr,
                                                   const float* __restrict__ Wk,
                                                   const float* __restrict__ Wv,
                                                   const float* __restrict__ Wr,
                                                   const float* __restrict__ Wo,
                                                   const float* __restrict__ cvw,
                                                   const float* __restrict__ chw) {
    __shared__ float sh[8*193];
    int blk = blockIdx.x;
    int tid = threadIdx.x;

    if (blk < 688) {
        int i = blk * 384 + tid;
        if (i < 384*576) {
            int row = i / 576, n = i % 576;
            int c = row % 192;
            bool second = row >= 192;
            const float* W; float m; int nn;
            if (n < 192)      { W = Wk; m = mk[c]; nn = n; }
            else if (n < 384) { W = Wv; m = mv[c]; nn = n - 192; }
            else              { W = Wr; m = mr[c]; nn = n - 384; }
            float v = (second ? (1.f - m) : m) * W[c*192 + nn];
            g_Wf[i] = __uint_as_float(f2tf32(v));
            return;
        }
        int j = i - 384*576;
        if (j < 192*32) {
            int c = j / 32, n = j % 32;
            float v = 0.f;
            if (n < 14)      v = cvw[(n/7)*C_*7 + c*7 + (n%7)];
            else if (n < 28) { int n2 = n - 14; v = chw[(n2/7)*C_*7 + c*7 + (n2%7)]; }
            g_Wp[j] = v;
            return;
        }
        int jj = j - 192*32;
        g_Wo[jj] = __uint_as_float(f2tf32(Wo[jj]));
        return;
    }

    if (blk < 1712) {
        int tb = (blk - 688) * 8;
        int k = tid;
#pragma unroll
        for (int j = 0; j < 8; j++) {
            int gt = tb + j;
            float v;
            if (k < 192) {
                v = x[(size_t)gt*C_ + k];
            } else {
                int c = k - 192;
                int tt = gt & 4095;
                int hh = tt >> 6, ww = tt & 63;
                int g = c / 48;
                int src; bool ok;
                if (g == 0)      { ok = (ww >= 1);  src = gt - 1; }
                else if (g == 1) { ok = (ww <= 62); src = gt + 1; }
                else if (g == 2) { ok = (hh >= 1);  src = gt - 64; }
                else             { ok = (hh <= 62); src = gt + 64; }
                v = ok ? x[(size_t)src*C_ + c] : 0.f;
            }
            g_A[(size_t)gt*384 + k] = __uint_as_float(f2tf32(v));
        }
        return;
    }

    // convP
    int tok0 = (blk - 1712) * 8;
    for (int i = tid; i < 8*192; i += 384) {
        int r = i / 192, c = i % 192;
        sh[r*193 + c] = x[(size_t)(tok0 + r)*C_ + c];
    }
    __syncthreads();
    if (tid < 256) {
        int r = tid >> 5, n = tid & 31;
        if (n < 28) {
            float acc = 0.f;
#pragma unroll 8
            for (int c = 0; c < 192; c++)
                acc = fmaf(sh[r*193 + c], g_Wp[c*32 + n], acc);
            g_P[(size_t)(tok0 + r)*32 + n] = acc;
        }
    }
}

// ---------------- adaptive peak (gb fused, 384 threads, 16 tokens/block, 2 reps) ----------------
__global__ __launch_bounds__(384) void peak_kernel(const float* __restrict__ x,
                                                   const float* __restrict__ cvb,
                                                   const float* __restrict__ bns_v,
                                                   const float* __restrict__ bnb_v,
                                                   const float* __restrict__ chb,
                                                   const float* __restrict__ bns_h,
                                                   const float* __restrict__ bnb_h) {
    int bi = blockIdx.x;                  // 512 blocks
    int b = bi >> 8;
    int tb = (bi & 255) * 16;
    int hh = tb >> 6, wwb = tb & 63;
    __shared__ float gbv[16][4];
    __shared__ int   s_lt[16][16], s_rb[16][16];
    __shared__ float s_wlt[16][16], s_wrb[16][16];
    int tid = threadIdx.x;

    if (tid < 64) {
        int j = tid >> 2, dir = tid & 3;
        int ww = wwb + j;
        const float* Pb = g_P + (size_t)b * T_ * 32;
        float s = 0.f;
        if (dir < 2) {
#pragma unroll
            for (int r = 0; r < 7; r++) {
                int hy = hh + r - 3;
                if (hy >= 0 && hy < 64) s += Pb[(size_t)(hy*64 + ww)*32 + dir*7 + r];
            }
        } else {
#pragma unroll
            for (int r = 0; r < 7; r++) {
                int wy = ww + r - 3;
                if (wy >= 0 && wy < 64) s += Pb[(size_t)(hh*64 + wy)*32 + (dir-2)*7 + 14 + r];
            }
        }
        const float inv = rsqrtf(1.f + 1e-5f);
        float bias, scale, shift;
        if (dir == 0)      { bias = cvb[0]; scale = bns_v[0]; shift = bnb_v[0]; }
        else if (dir == 1) { bias = cvb[1]; scale = bns_v[1]; shift = bnb_v[1]; }
        else if (dir == 2) { bias = chb[0]; scale = bns_h[0]; shift = bnb_h[0]; }
        else               { bias = chb[1]; scale = bns_h[1]; shift = bnb_h[1]; }
        float val = (s + bias) * (scale * inv) + shift;
        gbv[j][dir] = 2.f / (1.f + expf(-val));
    }
    __syncthreads();

    if (tid < 256) {
        int j = tid >> 4, o = tid & 15;
        int ww = wwb + j;
        int blk = o >> 2;
        float mx = 0.f, my = 0.f;
        if (blk == 0)      mx = -gbv[j][0];
        else if (blk == 1) my =  gbv[j][3];
        else if (blk == 2) mx =  gbv[j][1];
        else               my = -gbv[j][2];
        float px = (float)(hh + 2) + c_prfx[o] + mx;
        float py = (float)(ww + 2) + c_prfy[o] + my;
        float flx = floorf(px), fly = floorf(py);
        float qltx = fminf(fmaxf(flx,     0.f), 67.f);
        float qlty = fminf(fmaxf(fly,     0.f), 67.f);
        float qrbx = fminf(fmaxf(flx+1.f, 0.f), 67.f);
        float qrby = fminf(fmaxf(fly+1.f, 0.f), 67.f);
        float pxc  = fminf(fmaxf(px,      0.f), 67.f);
        float pyc  = fminf(fmaxf(py,      0.f), 67.f);
        float glt = (1.f + (qltx - pxc)) * (1.f + (qlty - pyc));
        float grb = (1.f - (qrbx - pxc)) * (1.f - (qrby - pyc));
        int rlt = min(max((int)qltx - 2, 0), 63);
        int clt = min(max((int)qlty - 2, 0), 63);
        int rrb = min(max((int)qrbx - 2, 0), 63);
        int crb = min(max((int)qrby - 2, 0), 63);
        s_lt[j][o] = rlt*64 + clt;  s_rb[j][o] = rrb*64 + crb;
        s_wlt[j][o] = glt;          s_wrb[j][o] = grb;
    }
    __syncthreads();

    const float* xb = x + (size_t)b * T_ * C_;
    int slot = tid / 48;
    int c4 = (tid % 48) * 4;
#pragma unroll
    for (int rep = 0; rep < 2; rep++) {
        int j = slot + rep*8;
        float a0 = 0.f, a1 = 0.f, a2 = 0.f, a3 = 0.f;
#pragma unroll
        for (int o = 0; o < 16; o++) {
            float4 a = *(const float4*)&xb[(size_t)s_lt[j][o]*C_ + c4];
            float4 bv = *(const float4*)&xb[(size_t)s_rb[j][o]*C_ + c4];
            float wl = s_wlt[j][o], wr = s_wrb[j][o];
            a0 += wl*a.x + wr*bv.x;
            a1 += wl*a.y + wr*bv.y;
            a2 += wl*a.z + wr*bv.z;
            a3 += wl*a.w + wr*bv.w;
        }
        size_t idx = ((size_t)b*T_ + tb + j)*C_ + c4;
        float4 xc = *(const float4*)&x[idx];
        float4 outv;
        outv.x = xc.x - a0*(1.f/16.f);
        outv.y = xc.y - a1*(1.f/16.f);
        outv.z = xc.z - a2*(1.f/16.f);
        outv.w = xc.w - a3*(1.f/16.f);
        *(float4*)&g_peak[idx] = outv;
    }
}

// ---------------- fused front GEMM: block 128x96, 8 warps (4Mx2N), warp 32x48 ----------------
#define AS1 36      // A smem stride
#define BS1 104     // B smem stride (104 % 32 == 8 -> conflict-free frag loads)
#define A_BUF (128*AS1)
#define B_BUF (32*BS1)

__global__ __launch_bounds__(256) void gemm1_kernel() {
    extern __shared__ float smem[];
    float* AsBuf = smem;                 // 2 x 128*36
    float* BsBuf = smem + 2*A_BUF;       // 2 x 32*104

    int tid = threadIdx.x;
    int warp = tid >> 5, lane = tid & 31;
    int bm = blockIdx.x * 128;
    int bny = blockIdx.y;                // 0..5
    int bn = bny * 96;
    int cls = bny >> 1;                  // 0:k 1:v 2:r
    int nloc = (bny & 1) * 96;
    int wm = (warp >> 1) * 32;
    int wn = (warp & 1) * 48;
    int gid = lane >> 2, tig = lane & 3;

    const float* Abase = g_A + (size_t)bm * 384;
    float acc[2][6][4] = {};

    float4 pa[4], pb[3];
    // prefetch k0 = 0
#pragma unroll
    for (int q = 0; q < 4; q++) {
        int f = tid + q*256;
        pa[q] = *(const float4*)&Abase[(size_t)(f >> 3)*384 + (f & 7)*4];
    }
#pragma unroll
    for (int q = 0; q < 3; q++) {
        int f = tid + q*256;
        pb[q] = *(const float4*)&g_Wf[(size_t)(f/24)*576 + bn + (f%24)*4];
    }
#pragma unroll
    for (int q = 0; q < 4; q++) {
        int f = tid + q*256;
        *(float4*)&AsBuf[(f >> 3)*AS1 + (f & 7)*4] = pa[q];
    }
#pragma unroll
    for (int q = 0; q < 3; q++) {
        int f = tid + q*256;
        *(float4*)&BsBuf[(f/24)*BS1 + (f%24)*4] = pb[q];
    }
    __syncthreads();

    for (int kc = 0; kc < 12; kc++) {
        int cur = kc & 1;
        if (kc < 11) {
            int k0 = (kc + 1) * 32;
#pragma unroll
            for (int q = 0; q < 4; q++) {
                int f = tid + q*256;
                pa[q] = *(const float4*)&Abase[(size_t)(f >> 3)*384 + k0 + (f & 7)*4];
            }
#pragma unroll
            for (int q = 0; q < 3; q++) {
                int f = tid + q*256;
                pb[q] = *(const float4*)&g_Wf[(size_t)(k0 + f/24)*576 + bn + (f%24)*4];
            }
        }
        const float* as = AsBuf + cur*A_BUF;
        const float* bs = BsBuf + cur*B_BUF;
#pragma unroll
        for (int ks = 0; ks < 4; ks++) {
            int kk0 = ks * 8;
            unsigned afr[2][4], bfr[6][2];
#pragma unroll
            for (int mi = 0; mi < 2; mi++) {
                int rbase = (wm + mi*16 + gid) * AS1;
                afr[mi][0] = __float_as_uint(as[rbase + kk0 + tig]);
                afr[mi][1] = __float_as_uint(as[rbase + 8*AS1 + kk0 + tig]);
                afr[mi][2] = __float_as_uint(as[rbase + kk0 + tig + 4]);
                afr[mi][3] = __float_as_uint(as[rbase + 8*AS1 + kk0 + tig + 4]);
            }
#pragma unroll
            for (int ni = 0; ni < 6; ni++) {
                int col = wn + ni*8 + gid;
                bfr[ni][0] = __float_as_uint(bs[(kk0 + tig)*BS1 + col]);
                bfr[ni][1] = __float_as_uint(bs[(kk0 + tig + 4)*BS1 + col]);
            }
#pragma unroll
            for (int mi = 0; mi < 2; mi++)
#pragma unroll
                for (int ni = 0; ni < 6; ni++)
                    mma8(acc[mi][ni], afr[mi][0], afr[mi][1], afr[mi][2], afr[mi][3],
                         bfr[ni][0], bfr[ni][1]);
        }
        if (kc < 11) {
            __syncthreads();
            int nxt = cur ^ 1;
#pragma unroll
            for (int q = 0; q < 4; q++) {
                int f = tid + q*256;
                *(float4*)&AsBuf[nxt*A_BUF + (f >> 3)*AS1 + (f & 7)*4] = pa[q];
            }
#pragma unroll
            for (int q = 0; q < 3; q++) {
                int f = tid + q*256;
                *(float4*)&BsBuf[nxt*B_BUF + (f/24)*BS1 + (f%24)*4] = pb[q];
            }
            __syncthreads();
        }
    }

    if (cls == 2) {
#pragma unroll
        for (int mi = 0; mi < 2; mi++) {
            int r0 = bm + wm + mi*16 + gid;
#pragma unroll
            for (int ni = 0; ni < 6; ni++) {
                int c0 = nloc + wn + ni*8 + tig*2;
                float v0 = 1.f/(1.f+expf(-acc[mi][ni][0]));
                float v1 = 1.f/(1.f+expf(-acc[mi][ni][1]));
                float v2 = 1.f/(1.f+expf(-acc[mi][ni][2]));
                float v3 = 1.f/(1.f+expf(-acc[mi][ni][3]));
                *(float2*)&g_sr[(size_t)r0*C_ + c0]     = make_float2(v0, v1);
                *(float2*)&g_sr[(size_t)(r0+8)*C_ + c0] = make_float2(v2, v3);
            }
        }
        return;
    }

    if (cls == 1) {
#pragma unroll
        for (int mi = 0; mi < 2; mi++) {
            int r0 = bm + wm + mi*16 + gid;
#pragma unroll
            for (int ni = 0; ni < 6; ni++) {
                int cg = nloc + wn + ni*8 + tig*2;
                float2 p0 = *(const float2*)&g_peak[(size_t)r0*C_ + cg];
                float2 p1 = *(const float2*)&g_peak[(size_t)(r0+8)*C_ + cg];
                acc[mi][ni][0] += p0.x; acc[mi][ni][1] += p0.y;
                acc[mi][ni][2] += p1.x; acc[mi][ni][3] += p1.y;
            }
        }
    }

    // transpose stage: st[channel][token], stride 132 (96 x 132 floats = 50.7KB)
    __syncthreads();
    float* st = smem;
#pragma unroll
    for (int mi = 0; mi < 2; mi++) {
        int r = wm + mi*16 + gid;
#pragma unroll
        for (int ni = 0; ni < 6; ni++) {
            int cc = wn + ni*8 + tig*2;
            st[cc*132 + r]         = acc[mi][ni][0];
            st[(cc+1)*132 + r]     = acc[mi][ni][1];
            st[cc*132 + r + 8]     = acc[mi][ni][2];
            st[(cc+1)*132 + r + 8] = acc[mi][ni][3];
        }
    }
    __syncthreads();
    float* dst = (cls == 0) ? g_kT : g_vT;
    int bb = bm >> 12, trow = bm & 4095;
#pragma unroll
    for (int q = 0; q < 12; q++) {
        int f = q*256 + tid;
        int cr = f >> 5;
        int t4 = (f & 31) * 4;
        float4 v = *(const float4*)&st[cr*132 + t4];
        *(float4*)&dst[((size_t)(bb*C_ + nloc + cr))*T_ + trow + t4] = v;
    }
}

// ---------------- bidirectional WKV scan (coalesced smem redistribution) ----------------
struct Agg { float a, b, dl; };
__device__ __forceinline__ Agg combine(Agg p, Agg s) {
    Agg r;
    r.a  = fmaf(s.dl, p.a, s.a);
    r.b  = fmaf(s.dl, p.b, s.b);
    r.dl = p.dl * s.dl;
    return r;
}
__device__ __forceinline__ Agg shfl_up_agg(Agg v, int off) {
    Agg r;
    r.a  = __shfl_up_sync(0xffffffffu, v.a,  off);
    r.b  = __shfl_up_sync(0xffffffffu, v.b,  off);
    r.dl = __shfl_up_sync(0xffffffffu, v.dl, off);
    return r;
}
__device__ __forceinline__ Agg shfl_dn_agg(Agg v, int off) {
    Agg r;
    r.a  = __shfl_down_sync(0xffffffffu, v.a,  off);
    r.b  = __shfl_down_sync(0xffffffffu, v.b,  off);
    r.dl = __shfl_down_sync(0xffffffffu, v.dl, off);
    return r;
}

__global__ __launch_bounds__(256) void wkv_kernel(const float* __restrict__ sd,
                                                  const float* __restrict__ sf) {
    __shared__ float eks[4352];
    __shared__ float vvs[4352];
    __shared__ Agg warpAgg[8];
    __shared__ Agg warpPre[8];
    int bc = blockIdx.x;
    int c = bc % C_;
    float w  = sd[c] * (1.0f / T_);
    float u  = sf[c] * (1.0f / T_);
    float d  = expf(-w);
    float eu = expf(u);
    float d2 = d*d, d4 = d2*d2, d8 = d4*d4, d16 = d8*d8;
    int tid = threadIdx.x;
    int lane = tid & 31, wid = tid >> 5;
    const float4* kp4 = (const float4*)(g_kT + (size_t)bc * T_);
    const float4* vp4 = (const float4*)(g_vT + (size_t)bc * T_);

#pragma unroll
    for (int q = 0; q < 4; q++) {
        int idx = tid + q*256;
        float4 kv = kp4[idx];
        float4 v4 = vp4[idx];
        int t = idx * 4;
        int base = t + (t >> 4);
        eks[base+0] = expf(kv.x); eks[base+1] = expf(kv.y);
        eks[base+2] = expf(kv.z); eks[base+3] = expf(kv.w);
        vvs[base+0] = v4.x; vvs[base+1] = v4.y;
        vvs[base+2] = v4.z; vvs[base+3] = v4.w;
    }
    __syncthreads();

    float ek[16], vv[16];
    int rb = 17 * tid;
#pragma unroll
    for (int i = 0; i < 16; i++) { ek[i] = eks[rb + i]; vv[i] = vvs[rb + i]; }

    Agg ag; ag.a = 0.f; ag.b = 0.f; ag.dl = d16;
#pragma unroll
    for (int i = 0; i < 16; i++) {
        ag.a = fmaf(d, ag.a, ek[i]);
        ag.b = fmaf(d, ag.b, ek[i]*vv[i]);
    }
    Agg inc = ag;
#pragma unroll
    for (int off = 1; off < 32; off <<= 1) {
        Agg o = shfl_up_agg(inc, off);
        if (lane >= off) inc = combine(o, inc);
    }
    if (lane == 31) warpAgg[wid] = inc;
    __syncthreads();
    if (tid == 0) {
        Agg run; run.a = 0.f; run.b = 0.f; run.dl = 1.f;
        for (int i = 0; i < 8; i++) { warpPre[i] = run; run = combine(run, warpAgg[i]); }
    }
    __syncthreads();
    Agg pl = shfl_up_agg(inc, 1);
    Agg ex = warpPre[wid];
    if (lane > 0) ex = combine(ex, pl);

    float af = ex.a, bf = ex.b;
    float saf[16], sbf[16];
#pragma unroll
    for (int i = 0; i < 16; i++) {
        saf[i] = af; sbf[i] = bf;
        af = fmaf(d, af, ek[i]);
        bf = fmaf(d, bf, ek[i]*vv[i]);
    }
    __syncthreads();

    Agg bg; bg.a = 0.f; bg.b = 0.f; bg.dl = d16;
#pragma unroll
    for (int i = 15; i >= 0; i--) {
        bg.a = fmaf(d, bg.a, ek[i]);
        bg.b = fmaf(d, bg.b, ek[i]*vv[i]);
    }
    Agg binc = bg;
#pragma unroll
    for (int off = 1; off < 32; off <<= 1) {
        Agg o = shfl_dn_agg(binc, off);
        if (lane < 32 - off) binc = combine(o, binc);
    }
    if (lane == 0) warpAgg[wid] = binc;
    __syncthreads();
    if (tid == 0) {
        Agg run; run.a = 0.f; run.b = 0.f; run.dl = 1.f;
        for (int i = 7; i >= 0; i--) { warpPre[i] = run; run = combine(run, warpAgg[i]); }
    }
    __syncthreads();
    Agg bpl = shfl_dn_agg(binc, 1);
    Agg bex = warpPre[wid];
    if (lane < 31) bex = combine(bex, bpl);

    float ab = bex.a, bb = bex.b;
#pragma unroll
    for (int i = 15; i >= 0; i--) {
        float es  = eu * ek[i];
        float num = sbf[i] + bb + es * vv[i];
        float den = saf[i] + ab + es;
        vvs[rb + i] = num / den;
        ab = fmaf(d, ab, ek[i]);
        bb = fmaf(d, bb, ek[i]*vv[i]);
    }
    __syncthreads();

    float4* yp4 = (float4*)(g_yT + (size_t)bc * T_);
#pragma unroll
    for (int q = 0; q < 4; q++) {
        int idx = tid + q*256;
        int t = idx * 4;
        int base = t + (t >> 4);
        yp4[idx] = make_float4(vvs[base+0], vvs[base+1], vvs[base+2], vvs[base+3]);
    }
}

// ---------------- output GEMM (1x tf32): out = (sr .* y) @ Wo ----------------
#define A2_STRIDE 197
#define BS_STRIDE 72

__global__ __launch_bounds__(128) void gemm2_kernel(float* __restrict__ out) {
    __shared__ unsigned As2[32 * A2_STRIDE];
    __shared__ unsigned Bs2[2][32 * BS_STRIDE];

    int tid = threadIdx.x;
    int warp = tid >> 5, lane = tid & 31;
    int gid = lane >> 2, tig = lane & 3;
    int bm = blockIdx.x * 32;
    int bn = blockIdx.y * 64;
    int wm = (warp >> 1) * 16;
    int wn = (warp & 1) * 32;
    int bb = bm >> 12, trow = bm & 4095;

#pragma unroll
    for (int q = 0; q < 12; q++) {
        int f = q*128 + tid;
        int row = f >> 3;
        int t4 = (f & 7) * 4;
        float4 v = *(const float4*)&g_yT[((size_t)(bb*C_ + row))*T_ + trow + t4];
        As2[(t4+0)*A2_STRIDE + row] = __float_as_uint(v.x);
        As2[(t4+1)*A2_STRIDE + row] = __float_as_uint(v.y);
        As2[(t4+2)*A2_STRIDE + row] = __float_as_uint(v.z);
        As2[(t4+3)*A2_STRIDE + row] = __float_as_uint(v.w);
    }
    __syncthreads();
#pragma unroll
    for (int q = 0; q < 12; q++) {
        int f = q*128 + tid;
        int t = f / 48, c4 = (f % 48) * 4;
        float4 s = *(const float4*)&g_sr[((size_t)(bm + t))*C_ + c4];
        unsigned* p = &As2[t*A2_STRIDE + c4];
        p[0] = f2tf32(__uint_as_float(p[0]) * s.x);
        p[1] = f2tf32(__uint_as_float(p[1]) * s.y);
        p[2] = f2tf32(__uint_as_float(p[2]) * s.z);
        p[3] = f2tf32(__uint_as_float(p[3]) * s.w);
    }

    int br = tid >> 4;
    int bc = (tid & 15) * 4;
    float acc[4][4] = {};

    float4 pb[4];
#pragma unroll
    for (int i = 0; i < 4; i++)
        pb[i] = *(const float4*)&g_Wo[(size_t)(br + i*8)*C_ + bn + bc];
#pragma unroll
    for (int i = 0; i < 4; i++)
        *(float4*)&Bs2[0][(br + i*8)*BS_STRIDE + bc] = pb[i];
    __syncthreads();

    for (int kc = 0; kc < 6; kc++) {
        int cur = kc & 1;
        if (kc < 5) {
            int k0 = (kc + 1) * 32;
#pragma unroll
            for (int i = 0; i < 4; i++)
                pb[i] = *(const float4*)&g_Wo[(size_t)(k0 + br + i*8)*C_ + bn + bc];
        }
        const unsigned* bs = Bs2[cur];
        int k0 = kc * 32;
#pragma unroll
        for (int ks = 0; ks < 4; ks++) {
            int kk = k0 + ks*8;
            unsigned a0 = As2[(wm+gid)*A2_STRIDE + kk + tig];
            unsigned a1 = As2[(wm+gid+8)*A2_STRIDE + kk + tig];
            unsigned a2 = As2[(wm+gid)*A2_STRIDE + kk + tig + 4];
            unsigned a3 = As2[(wm+gid+8)*A2_STRIDE + kk + tig + 4];
#pragma unroll
            for (int ni = 0; ni < 4; ni++) {
                int col = wn + ni*8 + gid;
                unsigned b0 = bs[(ks*8 + tig)*BS_STRIDE + col];
                unsigned b1 = bs[(ks*8 + tig + 4)*BS_STRIDE + col];
                mma8(acc[ni], a0, a1, a2, a3, b0, b1);
            }
        }
        if (kc < 5) {
            __syncthreads();
            int nxt = cur ^ 1;
#pragma unroll
            for (int i = 0; i < 4; i++)
                *(float4*)&Bs2[nxt][(br + i*8)*BS_STRIDE + bc] = pb[i];
            __syncthreads();
        }
    }

    int r0 = bm + wm + gid;
#pragma unroll
    for (int ni = 0; ni < 4; ni++) {
        int c0 = bn + wn + ni*8 + tig*2;
        *(float2*)&out[(size_t)r0*C_ + c0]     = make_float2(acc[ni][0], acc[ni][1]);
        *(float2*)&out[(size_t)(r0+8)*C_ + c0] = make_float2(acc[ni][2], acc[ni][3]);
    }
}

// ---------------- launch ----------------
#define GEMM1_SMEM ((2*A_BUF + 2*B_BUF) * 4)

extern "C" void kernel_launch(void* const* d_in, const int* in_sizes, int n_in,
                              void* d_out, int out_size) {
    const float* x = (const float*)d_in[0];
    int base = (in_sizes[1] == 1) ? 3 : 1;
    const float* mk    = (const float*)d_in[base + 0];
    const float* mv    = (const float*)d_in[base + 1];
    const float* mr    = (const float*)d_in[base + 2];
    const float* Wk    = (const float*)d_in[base + 3];
    const float* Wv    = (const float*)d_in[base + 4];
    const float* Wr    = (const float*)d_in[base + 5];
    const float* Wo    = (const float*)d_in[base + 6];
    const float* sd    = (const float*)d_in[base + 7];
    const float* sf    = (const float*)d_in[base + 8];
    const float* cvw   = (const float*)d_in[base + 9];
    const float* cvb   = (const float*)d_in[base + 10];
    const float* bns_v = (const float*)d_in[base + 11];
    const float* bnb_v = (const float*)d_in[base + 12];
    const float* chw   = (const float*)d_in[base + 13];
    const float* chb   = (const float*)d_in[base + 14];
    const float* bns_h = (const float*)d_in[base + 15];
    const float* bnb_h = (const float*)d_in[base + 16];

    cudaFuncSetAttribute(gemm1_kernel, cudaFuncAttributeMaxDynamicSharedMemorySize, GEMM1_SMEM);

    prep_kernel<<<2736, 384>>>(x, mk, mv, mr, Wk, Wv, Wr, Wo, cvw, chw);
    peak_kernel<<<512, 384>>>(x, cvb, bns_v, bnb_v, chb, bns_h, bnb_h);
    gemm1_kernel<<<dim3(64, 6), 256, GEMM1_SMEM>>>();
    wkv_kernel<<<B_*C_, 256>>>(sd, sf);
    gemm2_kernel<<<dim3(256, 3), 128>>>((float*)d_out);
}

// round 10
// speedup vs baseline: 1.5406x; 1.0012x over previous
#include <cuda_runtime.h>
#include <math.h>

#define B_ 2
#define T_ 4096
#define C_ 192
#define NTOT (B_*T_*C_)

// ---------------- scratch ----------------
__device__ float g_Wf[384*576];      // tf32-pre-rounded fused [k|v|r] weights
__device__ float g_Wo[192*192];      // tf32-pre-rounded output weights
__device__ float g_Wp[192*32];       // exact fp32 conv-tap weights
__device__ float g_A[B_*T_*384];     // tf32-pre-rounded [x | qshift(x)]
__device__ float g_P[B_*T_*32];
__device__ float g_peak[NTOT];
__device__ float g_kT[NTOT];
__device__ float g_vT[NTOT];
__device__ float g_yT[NTOT];
__device__ float g_sr[NTOT];

__constant__ float c_prfx[16] = {-2,-2,-2,-2, -2,-1,0,1,  2,2,2,2,  -1,0,1,2};
__constant__ float c_prfy[16] = {-2,-1,0,1,   2,2,2,2,  -1,0,1,2,  -2,-2,-2,-2};

__device__ __forceinline__ unsigned f2tf32(float x) {
    unsigned r;
    asm("cvt.rna.tf32.f32 %0, %1;" : "=r"(r) : "f"(x));
    return r;
}

__device__ __forceinline__ void mma8(float* d, unsigned a0, unsigned a1, unsigned a2, unsigned a3,
                                     unsigned b0, unsigned b1) {
    asm volatile(
        "mma.sync.aligned.m16n8k8.row.col.f32.tf32.tf32.f32 "
        "{%0,%1,%2,%3}, {%4,%5,%6,%7}, {%8,%9}, {%0,%1,%2,%3};\n"
        : "+f"(d[0]), "+f"(d[1]), "+f"(d[2]), "+f"(d[3])
        : "r"(a0), "r"(a1), "r"(a2), "r"(a3), "r"(b0), "r"(b1));
}

// ---------------- merged prep: weights + A-matrix + conv taps ----------------
__global__ __launch_bounds__(384) void prep_kernel(const float* __restrict__ x,
                                                   const float* __restrict__ mk,
                                                   const float* __restrict__ mv,
                                                   const float* __restrict__ mr,
                                                   const float* __restrict__ Wk,
                                                   const float* __restrict__ Wv,
                                                   const float* __restrict__ Wr,
                                                   const float* __restrict__ Wo,
                                                   const float* __restrict__ cvw,
                                                   const float* __restrict__ chw) {
    __shared__ float sh[8*193];
    int blk = blockIdx.x;
    int tid = threadIdx.x;

    if (blk < 688) {
        int i = blk * 384 + tid;
        if (i < 384*576) {
            int row = i / 576, n = i % 576;
            int c = row % 192;
            bool second = row >= 192;
            const float* W; float m; int nn;
            if (n < 192)      { W = Wk; m = mk[c]; nn = n; }
            else if (n < 384) { W = Wv; m = mv[c]; nn = n - 192; }
            else              { W = Wr; m = mr[c]; nn = n - 384; }
            float v = (second ? (1.f - m) : m) * W[c*192 + nn];
            g_Wf[i] = __uint_as_float(f2tf32(v));
            return;
        }
        int j = i - 384*576;
        if (j < 192*32) {
            int c = j / 32, n = j % 32;
            float v = 0.f;
            if (n < 14)      v = cvw[(n/7)*C_*7 + c*7 + (n%7)];
            else if (n < 28) { int n2 = n - 14; v = chw[(n2/7)*C_*7 + c*7 + (n2%7)]; }
            g_Wp[j] = v;
            return;
        }
        int jj = j - 192*32;
        g_Wo[jj] = __uint_as_float(f2tf32(Wo[jj]));
        return;
    }

    if (blk < 1712) {
        int tb = (blk - 688) * 8;
        int k = tid;
#pragma unroll
        for (int j = 0; j < 8; j++) {
            int gt = tb + j;
            float v;
            if (k < 192) {
                v = x[(size_t)gt*C_ + k];
            } else {
                int c = k - 192;
                int tt = gt & 4095;
                int hh = tt >> 6, ww = tt & 63;
                int g = c / 48;
                int src; bool ok;
                if (g == 0)      { ok = (ww >= 1);  src = gt - 1; }
                else if (g == 1) { ok = (ww <= 62); src = gt + 1; }
                else if (g == 2) { ok = (hh >= 1);  src = gt - 64; }
                else             { ok = (hh <= 62); src = gt + 64; }
                v = ok ? x[(size_t)src*C_ + c] : 0.f;
            }
            g_A[(size_t)gt*384 + k] = __uint_as_float(f2tf32(v));
        }
        return;
    }

    // convP
    int tok0 = (blk - 1712) * 8;
    for (int i = tid; i < 8*192; i += 384) {
        int r = i / 192, c = i % 192;
        sh[r*193 + c] = x[(size_t)(tok0 + r)*C_ + c];
    }
    __syncthreads();
    if (tid < 256) {
        int r = tid >> 5, n = tid & 31;
        if (n < 28) {
            float acc = 0.f;
#pragma unroll 8
            for (int c = 0; c < 192; c++)
                acc = fmaf(sh[r*193 + c], g_Wp[c*32 + n], acc);
            g_P[(size_t)(tok0 + r)*32 + n] = acc;
        }
    }
}

// ---------------- adaptive peak (gb fused, 384 threads, 16 tokens/block, 2 reps) ----------------
__global__ __launch_bounds__(384) void peak_kernel(const float* __restrict__ x,
                                                   const float* __restrict__ cvb,
                                                   const float* __restrict__ bns_v,
                                                   const float* __restrict__ bnb_v,
                                                   const float* __restrict__ chb,
                                                   const float* __restrict__ bns_h,
                                                   const float* __restrict__ bnb_h) {
    int bi = blockIdx.x;                  // 512 blocks
    int b = bi >> 8;
    int tb = (bi & 255) * 16;
    int hh = tb >> 6, wwb = tb & 63;
    __shared__ float gbv[16][4];
    __shared__ int   s_lt[16][16], s_rb[16][16];
    __shared__ float s_wlt[16][16], s_wrb[16][16];
    int tid = threadIdx.x;

    if (tid < 64) {
        int j = tid >> 2, dir = tid & 3;
        int ww = wwb + j;
        const float* Pb = g_P + (size_t)b * T_ * 32;
        float s = 0.f;
        if (dir < 2) {
#pragma unroll
            for (int r = 0; r < 7; r++) {
                int hy = hh + r - 3;
                if (hy >= 0 && hy < 64) s += Pb[(size_t)(hy*64 + ww)*32 + dir*7 + r];
            }
        } else {
#pragma unroll
            for (int r = 0; r < 7; r++) {
                int wy = ww + r - 3;
                if (wy >= 0 && wy < 64) s += Pb[(size_t)(hh*64 + wy)*32 + (dir-2)*7 + 14 + r];
            }
        }
        const float inv = rsqrtf(1.f + 1e-5f);
        float bias, scale, shift;
        if (dir == 0)      { bias = cvb[0]; scale = bns_v[0]; shift = bnb_v[0]; }
        else if (dir == 1) { bias = cvb[1]; scale = bns_v[1]; shift = bnb_v[1]; }
        else if (dir == 2) { bias = chb[0]; scale = bns_h[0]; shift = bnb_h[0]; }
        else               { bias = chb[1]; scale = bns_h[1]; shift = bnb_h[1]; }
        float val = (s + bias) * (scale * inv) + shift;
        gbv[j][dir] = 2.f / (1.f + expf(-val));
    }
    __syncthreads();

    if (tid < 256) {
        int j = tid >> 4, o = tid & 15;
        int ww = wwb + j;
        int blk = o >> 2;
        float mx = 0.f, my = 0.f;
        if (blk == 0)      mx = -gbv[j][0];
        else if (blk == 1) my =  gbv[j][3];
        else if (blk == 2) mx =  gbv[j][1];
        else               my = -gbv[j][2];
        float px = (float)(hh + 2) + c_prfx[o] + mx;
        float py = (float)(ww + 2) + c_prfy[o] + my;
        float flx = floorf(px), fly = floorf(py);
        float qltx = fminf(fmaxf(flx,     0.f), 67.f);
        float qlty = fminf(fmaxf(fly,     0.f), 67.f);
        float qrbx = fminf(fmaxf(flx+1.f, 0.f), 67.f);
        float qrby = fminf(fmaxf(fly+1.f, 0.f), 67.f);
        float pxc  = fminf(fmaxf(px,      0.f), 67.f);
        float pyc  = fminf(fmaxf(py,      0.f), 67.f);
        float glt = (1.f + (qltx - pxc)) * (1.f + (qlty - pyc));
        float grb = (1.f - (qrbx - pxc)) * (1.f - (qrby - pyc));
        int rlt = min(max((int)qltx - 2, 0), 63);
        int clt = min(max((int)qlty - 2, 0), 63);
        int rrb = min(max((int)qrbx - 2, 0), 63);
        int crb = min(max((int)qrby - 2, 0), 63);
        s_lt[j][o] = rlt*64 + clt;  s_rb[j][o] = rrb*64 + crb;
        s_wlt[j][o] = glt;          s_wrb[j][o] = grb;
    }
    __syncthreads();

    const float* xb = x + (size_t)b * T_ * C_;
    int slot = tid / 48;
    int c4 = (tid % 48) * 4;
#pragma unroll
    for (int rep = 0; rep < 2; rep++) {
        int j = slot + rep*8;
        float a0 = 0.f, a1 = 0.f, a2 = 0.f, a3 = 0.f;
#pragma unroll
        for (int o = 0; o < 16; o++) {
            float4 a = *(const float4*)&xb[(size_t)s_lt[j][o]*C_ + c4];
            float4 bv = *(const float4*)&xb[(size_t)s_rb[j][o]*C_ + c4];
            float wl = s_wlt[j][o], wr = s_wrb[j][o];
            a0 += wl*a.x + wr*bv.x;
            a1 += wl*a.y + wr*bv.y;
            a2 += wl*a.z + wr*bv.z;
            a3 += wl*a.w + wr*bv.w;
        }
        size_t idx = ((size_t)b*T_ + tb + j)*C_ + c4;
        float4 xc = *(const float4*)&x[idx];
        float4 outv;
        outv.x = xc.x - a0*(1.f/16.f);
        outv.y = xc.y - a1*(1.f/16.f);
        outv.z = xc.z - a2*(1.f/16.f);
        outv.w = xc.w - a3*(1.f/16.f);
        *(float4*)&g_peak[idx] = outv;
    }
}

// ---------------- fused front GEMM: block 128x96, 8 warps (4Mx2N), warp 32x48 ----------------
// mode 0: k,r classes (blockIdx.y -> bny {0,1,4,5}); mode 1: v class (bny {2,3})
#define AS1 36
#define BS1 104
#define A_BUF (128*AS1)
#define B_BUF (32*BS1)

__global__ __launch_bounds__(256) void gemm1_kernel(int mode) {
    extern __shared__ float smem[];
    float* AsBuf = smem;
    float* BsBuf = smem + 2*A_BUF;

    int tid = threadIdx.x;
    int warp = tid >> 5, lane = tid & 31;
    int bm = blockIdx.x * 128;
    int bny = mode ? (blockIdx.y + 2)
                   : (blockIdx.y < 2 ? blockIdx.y : blockIdx.y + 2);
    int bn = bny * 96;
    int cls = bny >> 1;                  // 0:k 1:v 2:r
    int nloc = (bny & 1) * 96;
    int wm = (warp >> 1) * 32;
    int wn = (warp & 1) * 48;
    int gid = lane >> 2, tig = lane & 3;

    const float* Abase = g_A + (size_t)bm * 384;
    float acc[2][6][4] = {};

    float4 pa[4], pb[3];
#pragma unroll
    for (int q = 0; q < 4; q++) {
        int f = tid + q*256;
        pa[q] = *(const float4*)&Abase[(size_t)(f >> 3)*384 + (f & 7)*4];
    }
#pragma unroll
    for (int q = 0; q < 3; q++) {
        int f = tid + q*256;
        pb[q] = *(const float4*)&g_Wf[(size_t)(f/24)*576 + bn + (f%24)*4];
    }
#pragma unroll
    for (int q = 0; q < 4; q++) {
        int f = tid + q*256;
        *(float4*)&AsBuf[(f >> 3)*AS1 + (f & 7)*4] = pa[q];
    }
#pragma unroll
    for (int q = 0; q < 3; q++) {
        int f = tid + q*256;
        *(float4*)&BsBuf[(f/24)*BS1 + (f%24)*4] = pb[q];
    }
    __syncthreads();

    for (int kc = 0; kc < 12; kc++) {
        int cur = kc & 1;
        if (kc < 11) {
            int k0 = (kc + 1) * 32;
#pragma unroll
            for (int q = 0; q < 4; q++) {
                int f = tid + q*256;
                pa[q] = *(const float4*)&Abase[(size_t)(f >> 3)*384 + k0 + (f & 7)*4];
            }
#pragma unroll
            for (int q = 0; q < 3; q++) {
                int f = tid + q*256;
                pb[q] = *(const float4*)&g_Wf[(size_t)(k0 + f/24)*576 + bn + (f%24)*4];
            }
        }
        const float* as = AsBuf + cur*A_BUF;
        const float* bs = BsBuf + cur*B_BUF;
#pragma unroll
        for (int ks = 0; ks < 4; ks++) {
            int kk0 = ks * 8;
            unsigned afr[2][4], bfr[6][2];
#pragma unroll
            for (int mi = 0; mi < 2; mi++) {
                int rbase = (wm + mi*16 + gid) * AS1;
                afr[mi][0] = __float_as_uint(as[rbase + kk0 + tig]);
                afr[mi][1] = __float_as_uint(as[rbase + 8*AS1 + kk0 + tig]);
                afr[mi][2] = __float_as_uint(as[rbase + kk0 + tig + 4]);
                afr[mi][3] = __float_as_uint(as[rbase + 8*AS1 + kk0 + tig + 4]);
            }
#pragma unroll
            for (int ni = 0; ni < 6; ni++) {
                int col = wn + ni*8 + gid;
                bfr[ni][0] = __float_as_uint(bs[(kk0 + tig)*BS1 + col]);
                bfr[ni][1] = __float_as_uint(bs[(kk0 + tig + 4)*BS1 + col]);
            }
#pragma unroll
            for (int mi = 0; mi < 2; mi++)
#pragma unroll
                for (int ni = 0; ni < 6; ni++)
                    mma8(acc[mi][ni], afr[mi][0], afr[mi][1], afr[mi][2], afr[mi][3],
                         bfr[ni][0], bfr[ni][1]);
        }
        if (kc < 11) {
            __syncthreads();
            int nxt = cur ^ 1;
#pragma unroll
            for (int q = 0; q < 4; q++) {
                int f = tid + q*256;
                *(float4*)&AsBuf[nxt*A_BUF + (f >> 3)*AS1 + (f & 7)*4] = pa[q];
            }
#pragma unroll
            for (int q = 0; q < 3; q++) {
                int f = tid + q*256;
                *(float4*)&BsBuf[nxt*B_BUF + (f/24)*BS1 + (f%24)*4] = pb[q];
            }
            __syncthreads();
        }
    }

    if (cls == 2) {
#pragma unroll
        for (int mi = 0; mi < 2; mi++) {
            int r0 = bm + wm + mi*16 + gid;
#pragma unroll
            for (int ni = 0; ni < 6; ni++) {
                int c0 = nloc + wn + ni*8 + tig*2;
                float v0 = 1.f/(1.f+expf(-acc[mi][ni][0]));
                float v1 = 1.f/(1.f+expf(-acc[mi][ni][1]));
                float v2 = 1.f/(1.f+expf(-acc[mi][ni][2]));
                float v3 = 1.f/(1.f+expf(-acc[mi][ni][3]));
                *(float2*)&g_sr[(size_t)r0*C_ + c0]     = make_float2(v0, v1);
                *(float2*)&g_sr[(size_t)(r0+8)*C_ + c0] = make_float2(v2, v3);
            }
        }
        return;
    }

    if (cls == 1) {
#pragma unroll
        for (int mi = 0; mi < 2; mi++) {
            int r0 = bm + wm + mi*16 + gid;
#pragma unroll
            for (int ni = 0; ni < 6; ni++) {
                int cg = nloc + wn + ni*8 + tig*2;
                float2 p0 = *(const float2*)&g_peak[(size_t)r0*C_ + cg];
                float2 p1 = *(const float2*)&g_peak[(size_t)(r0+8)*C_ + cg];
                acc[mi][ni][0] += p0.x; acc[mi][ni][1] += p0.y;
                acc[mi][ni][2] += p1.x; acc[mi][ni][3] += p1.y;
            }
        }
    }

    // transpose stage: st[channel][token], stride 132
    __syncthreads();
    float* st = smem;
#pragma unroll
    for (int mi = 0; mi < 2; mi++) {
        int r = wm + mi*16 + gid;
#pragma unroll
        for (int ni = 0; ni < 6; ni++) {
            int cc = wn + ni*8 + tig*2;
            st[cc*132 + r]         = acc[mi][ni][0];
            st[(cc+1)*132 + r]     = acc[mi][ni][1];
            st[cc*132 + r + 8]     = acc[mi][ni][2];
            st[(cc+1)*132 + r + 8] = acc[mi][ni][3];
        }
    }
    __syncthreads();
    float* dst = (cls == 0) ? g_kT : g_vT;
    int bb = bm >> 12, trow = bm & 4095;
#pragma unroll
    for (int q = 0; q < 12; q++) {
        int f = q*256 + tid;
        int cr = f >> 5;
        int t4 = (f & 31) * 4;
        float4 v = *(const float4*)&st[cr*132 + t4];
        *(float4*)&dst[((size_t)(bb*C_ + nloc + cr))*T_ + trow + t4] = v;
    }
}

// ---------------- bidirectional WKV scan (coalesced smem redistribution) ----------------
struct Agg { float a, b, dl; };
__device__ __forceinline__ Agg combine(Agg p, Agg s) {
    Agg r;
    r.a  = fmaf(s.dl, p.a, s.a);
    r.b  = fmaf(s.dl, p.b, s.b);
    r.dl = p.dl * s.dl;
    return r;
}
__device__ __forceinline__ Agg shfl_up_agg(Agg v, int off) {
    Agg r;
    r.a  = __shfl_up_sync(0xffffffffu, v.a,  off);
    r.b  = __shfl_up_sync(0xffffffffu, v.b,  off);
    r.dl = __shfl_up_sync(0xffffffffu, v.dl, off);
    return r;
}
__device__ __forceinline__ Agg shfl_dn_agg(Agg v, int off) {
    Agg r;
    r.a  = __shfl_down_sync(0xffffffffu, v.a,  off);
    r.b  = __shfl_down_sync(0xffffffffu, v.b,  off);
    r.dl = __shfl_down_sync(0xffffffffu, v.dl, off);
    return r;
}

__global__ __launch_bounds__(256) void wkv_kernel(const float* __restrict__ sd,
                                                  const float* __restrict__ sf) {
    __shared__ float eks[4352];
    __shared__ float vvs[4352];
    __shared__ Agg warpAgg[8];
    __shared__ Agg warpPre[8];
    int bc = blockIdx.x;
    int c = bc % C_;
    float w  = sd[c] * (1.0f / T_);
    float u  = sf[c] * (1.0f / T_);
    float d  = expf(-w);
    float eu = expf(u);
    float d2 = d*d, d4 = d2*d2, d8 = d4*d4, d16 = d8*d8;
    int tid = threadIdx.x;
    int lane = tid & 31, wid = tid >> 5;
    const float4* kp4 = (const float4*)(g_kT + (size_t)bc * T_);
    const float4* vp4 = (const float4*)(g_vT + (size_t)bc * T_);

#pragma unroll
    for (int q = 0; q < 4; q++) {
        int idx = tid + q*256;
        float4 kv = kp4[idx];
        float4 v4 = vp4[idx];
        int t = idx * 4;
        int base = t + (t >> 4);
        eks[base+0] = expf(kv.x); eks[base+1] = expf(kv.y);
        eks[base+2] = expf(kv.z); eks[base+3] = expf(kv.w);
        vvs[base+0] = v4.x; vvs[base+1] = v4.y;
        vvs[base+2] = v4.z; vvs[base+3] = v4.w;
    }
    __syncthreads();

    float ek[16], vv[16];
    int rb = 17 * tid;
#pragma unroll
    for (int i = 0; i < 16; i++) { ek[i] = eks[rb + i]; vv[i] = vvs[rb + i]; }

    Agg ag; ag.a = 0.f; ag.b = 0.f; ag.dl = d16;
#pragma unroll
    for (int i = 0; i < 16; i++) {
        ag.a = fmaf(d, ag.a, ek[i]);
        ag.b = fmaf(d, ag.b, ek[i]*vv[i]);
    }
    Agg inc = ag;
#pragma unroll
    for (int off = 1; off < 32; off <<= 1) {
        Agg o = shfl_up_agg(inc, off);
        if (lane >= off) inc = combine(o, inc);
    }
    if (lane == 31) warpAgg[wid] = inc;
    __syncthreads();
    if (tid == 0) {
        Agg run; run.a = 0.f; run.b = 0.f; run.dl = 1.f;
        for (int i = 0; i < 8; i++) { warpPre[i] = run; run = combine(run, warpAgg[i]); }
    }
    __syncthreads();
    Agg pl = shfl_up_agg(inc, 1);
    Agg ex = warpPre[wid];
    if (lane > 0) ex = combine(ex, pl);

    float af = ex.a, bf = ex.b;
    float saf[16], sbf[16];
#pragma unroll
    for (int i = 0; i < 16; i++) {
        saf[i] = af; sbf[i] = bf;
        af = fmaf(d, af, ek[i]);
        bf = fmaf(d, bf, ek[i]*vv[i]);
    }
    __syncthreads();

    Agg bg; bg.a = 0.f; bg.b = 0.f; bg.dl = d16;
#pragma unroll
    for (int i = 15; i >= 0; i--) {
        bg.a = fmaf(d, bg.a, ek[i]);
        bg.b = fmaf(d, bg.b, ek[i]*vv[i]);
    }
    Agg binc = bg;
#pragma unroll
    for (int off = 1; off < 32; off <<= 1) {
        Agg o = shfl_dn_agg(binc, off);
        if (lane < 32 - off) binc = combine(o, binc);
    }
    if (lane == 0) warpAgg[wid] = binc;
    __syncthreads();
    if (tid == 0) {
        Agg run; run.a = 0.f; run.b = 0.f; run.dl = 1.f;
        for (int i = 7; i >= 0; i--) { warpPre[i] = run; run = combine(run, warpAgg[i]); }
    }
    __syncthreads();
    Agg bpl = shfl_dn_agg(binc, 1);
    Agg bex = warpPre[wid];
    if (lane < 31) bex = combine(bex, bpl);

    float ab = bex.a, bb = bex.b;
#pragma unroll
    for (int i = 15; i >= 0; i--) {
        float es  = eu * ek[i];
        float num = sbf[i] + bb + es * vv[i];
        float den = saf[i] + ab + es;
        vvs[rb + i] = num / den;
        ab = fmaf(d, ab, ek[i]);
        bb = fmaf(d, bb, ek[i]*vv[i]);
    }
    __syncthreads();

    float4* yp4 = (float4*)(g_yT + (size_t)bc * T_);
#pragma unroll
    for (int q = 0; q < 4; q++) {
        int idx = tid + q*256;
        int t = idx * 4;
        int base = t + (t >> 4);
        yp4[idx] = make_float4(vvs[base+0], vvs[base+1], vvs[base+2], vvs[base+3]);
    }
}

// ---------------- output GEMM (1x tf32): out = (sr .* y) @ Wo ----------------
#define A2_STRIDE 197
#define BS_STRIDE 72

__global__ __launch_bounds__(128) void gemm2_kernel(float* __restrict__ out) {
    __shared__ unsigned As2[32 * A2_STRIDE];
    __shared__ unsigned Bs2[2][32 * BS_STRIDE];

    int tid = threadIdx.x;
    int warp = tid >> 5, lane = tid & 31;
    int gid = lane >> 2, tig = lane & 3;
    int bm = blockIdx.x * 32;
    int bn = blockIdx.y * 64;
    int wm = (warp >> 1) * 16;
    int wn = (warp & 1) * 32;
    int bb = bm >> 12, trow = bm & 4095;

#pragma unroll
    for (int q = 0; q < 12; q++) {
        int f = q*128 + tid;
        int row = f >> 3;
        int t4 = (f & 7) * 4;
        float4 v = *(const float4*)&g_yT[((size_t)(bb*C_ + row))*T_ + trow + t4];
        As2[(t4+0)*A2_STRIDE + row] = __float_as_uint(v.x);
        As2[(t4+1)*A2_STRIDE + row] = __float_as_uint(v.y);
        As2[(t4+2)*A2_STRIDE + row] = __float_as_uint(v.z);
        As2[(t4+3)*A2_STRIDE + row] = __float_as_uint(v.w);
    }
    __syncthreads();
#pragma unroll
    for (int q = 0; q < 12; q++) {
        int f = q*128 + tid;
        int t = f / 48, c4 = (f % 48) * 4;
        float4 s = *(const float4*)&g_sr[((size_t)(bm + t))*C_ + c4];
        unsigned* p = &As2[t*A2_STRIDE + c4];
        p[0] = f2tf32(__uint_as_float(p[0]) * s.x);
        p[1] = f2tf32(__uint_as_float(p[1]) * s.y);
        p[2] = f2tf32(__uint_as_float(p[2]) * s.z);
        p[3] = f2tf32(__uint_as_float(p[3]) * s.w);
    }

    int br = tid >> 4;
    int bc = (tid & 15) * 4;
    float acc[4][4] = {};

    float4 pb[4];
#pragma unroll
    for (int i = 0; i < 4; i++)
        pb[i] = *(const float4*)&g_Wo[(size_t)(br + i*8)*C_ + bn + bc];
#pragma unroll
    for (int i = 0; i < 4; i++)
        *(float4*)&Bs2[0][(br + i*8)*BS_STRIDE + bc] = pb[i];
    __syncthreads();

    for (int kc = 0; kc < 6; kc++) {
        int cur = kc & 1;
        if (kc < 5) {
            int k0 = (kc + 1) * 32;
#pragma unroll
            for (int i = 0; i < 4; i++)
                pb[i] = *(const float4*)&g_Wo[(size_t)(k0 + br + i*8)*C_ + bn + bc];
        }
        const unsigned* bs = Bs2[cur];
        int k0 = kc * 32;
#pragma unroll
        for (int ks = 0; ks < 4; ks++) {
            int kk = k0 + ks*8;
            unsigned a0 = As2[(wm+gid)*A2_STRIDE + kk + tig];
            unsigned a1 = As2[(wm+gid+8)*A2_STRIDE + kk + tig];
            unsigned a2 = As2[(wm+gid)*A2_STRIDE + kk + tig + 4];
            unsigned a3 = As2[(wm+gid+8)*A2_STRIDE + kk + tig + 4];
#pragma unroll
            for (int ni = 0; ni < 4; ni++) {
                int col = wn + ni*8 + gid;
                unsigned b0 = bs[(ks*8 + tig)*BS_STRIDE + col];
                unsigned b1 = bs[(ks*8 + tig + 4)*BS_STRIDE + col];
                mma8(acc[ni], a0, a1, a2, a3, b0, b1);
            }
        }
        if (kc < 5) {
            __syncthreads();
            int nxt = cur ^ 1;
#pragma unroll
            for (int i = 0; i < 4; i++)
                *(float4*)&Bs2[nxt][(br + i*8)*BS_STRIDE + bc] = pb[i];
            __syncthreads();
        }
    }

    int r0 = bm + wm + gid;
#pragma unroll
    for (int ni = 0; ni < 4; ni++) {
        int c0 = bn + wn + ni*8 + tig*2;
        *(float2*)&out[(size_t)r0*C_ + c0]     = make_float2(acc[ni][0], acc[ni][1]);
        *(float2*)&out[(size_t)(r0+8)*C_ + c0] = make_float2(acc[ni][2], acc[ni][3]);
    }
}

// ---------------- launch (fork-join: peak || gemm1 k/r) ----------------
#define GEMM1_SMEM ((2*A_BUF + 2*B_BUF) * 4)

namespace {
struct SideStream {
    cudaStream_t s1;
    cudaEvent_t evFork, evJoin;
    SideStream() {
        cudaStreamCreateWithFlags(&s1, cudaStreamNonBlocking);
        cudaEventCreateWithFlags(&evFork, cudaEventDisableTiming);
        cudaEventCreateWithFlags(&evJoin, cudaEventDisableTiming);
    }
};
SideStream g_ss;   // created at static init, before harness mem checkpoints
}

extern "C" void kernel_launch(void* const* d_in, const int* in_sizes, int n_in,
                              void* d_out, int out_size) {
    const float* x = (const float*)d_in[0];
    int base = (in_sizes[1] == 1) ? 3 : 1;
    const float* mk    = (const float*)d_in[base + 0];
    const float* mv    = (const float*)d_in[base + 1];
    const float* mr    = (const float*)d_in[base + 2];
    const float* Wk    = (const float*)d_in[base + 3];
    const float* Wv    = (const float*)d_in[base + 4];
    const float* Wr    = (const float*)d_in[base + 5];
    const float* Wo    = (const float*)d_in[base + 6];
    const float* sd    = (const float*)d_in[base + 7];
    const float* sf    = (const float*)d_in[base + 8];
    const float* cvw   = (const float*)d_in[base + 9];
    const float* cvb   = (const float*)d_in[base + 10];
    const float* bns_v = (const float*)d_in[base + 11];
    const float* bnb_v = (const float*)d_in[base + 12];
    const float* chw   = (const float*)d_in[base + 13];
    const float* chb   = (const float*)d_in[base + 14];
    const float* bns_h = (const float*)d_in[base + 15];
    const float* bnb_h = (const float*)d_in[base + 16];

    cudaFuncSetAttribute(gemm1_kernel, cudaFuncAttributeMaxDynamicSharedMemorySize, GEMM1_SMEM);

    // main stream: prep
    prep_kernel<<<2736, 384>>>(x, mk, mv, mr, Wk, Wv, Wr, Wo, cvw, chw);

    // fork: peak on side stream, concurrent with gemm1 k/r on main stream
    cudaEventRecord(g_ss.evFork, 0);
    cudaStreamWaitEvent(g_ss.s1, g_ss.evFork, 0);
    peak_kernel<<<512, 384, 0, g_ss.s1>>>(x, cvb, bns_v, bnb_v, chb, bns_h, bnb_h);
    cudaEventRecord(g_ss.evJoin, g_ss.s1);

    gemm1_kernel<<<dim3(64, 4), 256, GEMM1_SMEM>>>(0);   // k, r classes

    // join: v class needs g_peak
    cudaStreamWaitEvent(0, g_ss.evJoin, 0);
    gemm1_kernel<<<dim3(64, 2), 256, GEMM1_SMEM>>>(1);   // v class

    wkv_kernel<<<B_*C_, 256>>>(sd, sf);
    gemm2_kernel<<<dim3(256, 3), 128>>>((float*)d_out);
}

// round 11
// speedup vs baseline: 1.6909x; 1.0976x over previous
#include <cuda_runtime.h>
#include <math.h>

#define B_ 2
#define T_ 4096
#define C_ 192
#define NTOT (B_*T_*C_)

// ---------------- scratch ----------------
__device__ float g_Wf[384*576];      // tf32-pre-rounded fused [k|v|r] weights
__device__ float g_Wo[192*192];      // tf32-pre-rounded output weights
__device__ float g_Wp[192*32];       // exact fp32 conv-tap weights
__device__ float g_A[B_*T_*384];     // tf32-pre-rounded [x | qshift(x)]
__device__ float g_P[B_*T_*32];
__device__ float g_peakT[NTOT];      // peak, (B,C,T) layout
__device__ float g_kT[NTOT];
__device__ float g_vT[NTOT];
__device__ float g_yT[NTOT];
__device__ float g_sr[NTOT];

__constant__ float c_prfx[16] = {-2,-2,-2,-2, -2,-1,0,1,  2,2,2,2,  -1,0,1,2};
__constant__ float c_prfy[16] = {-2,-1,0,1,   2,2,2,2,  -1,0,1,2,  -2,-2,-2,-2};

__device__ __forceinline__ unsigned f2tf32(float x) {
    unsigned r;
    asm("cvt.rna.tf32.f32 %0, %1;" : "=r"(r) : "f"(x));
    return r;
}

__device__ __forceinline__ void mma8(float* d, unsigned a0, unsigned a1, unsigned a2, unsigned a3,
                                     unsigned b0, unsigned b1) {
    asm volatile(
        "mma.sync.aligned.m16n8k8.row.col.f32.tf32.tf32.f32 "
        "{%0,%1,%2,%3}, {%4,%5,%6,%7}, {%8,%9}, {%0,%1,%2,%3};\n"
        : "+f"(d[0]), "+f"(d[1]), "+f"(d[2]), "+f"(d[3])
        : "r"(a0), "r"(a1), "r"(a2), "r"(a3), "r"(b0), "r"(b1));
}

// ---------------- prep_w: weights only ----------------
__global__ __launch_bounds__(384) void prepw_kernel(const float* __restrict__ mk,
                                                    const float* __restrict__ mv,
                                                    const float* __restrict__ mr,
                                                    const float* __restrict__ Wk,
                                                    const float* __restrict__ Wv,
                                                    const float* __restrict__ Wr,
                                                    const float* __restrict__ Wo,
                                                    const float* __restrict__ cvw,
                                                    const float* __restrict__ chw) {
    int i = blockIdx.x * 384 + threadIdx.x;
    if (i < 384*576) {
        int row = i / 576, n = i % 576;
        int c = row % 192;
        bool second = row >= 192;
        const float* W; float m; int nn;
        if (n < 192)      { W = Wk; m = mk[c]; nn = n; }
        else if (n < 384) { W = Wv; m = mv[c]; nn = n - 192; }
        else              { W = Wr; m = mr[c]; nn = n - 384; }
        float v = (second ? (1.f - m) : m) * W[c*192 + nn];
        g_Wf[i] = __uint_as_float(f2tf32(v));
        return;
    }
    int j = i - 384*576;
    if (j < 192*32) {
        int c = j / 32, n = j % 32;
        float v = 0.f;
        if (n < 14)      v = cvw[(n/7)*C_*7 + c*7 + (n%7)];
        else if (n < 28) { int n2 = n - 14; v = chw[(n2/7)*C_*7 + c*7 + (n2%7)]; }
        g_Wp[j] = v;
        return;
    }
    int jj = j - 192*32;
    if (jj < 192*192)
        g_Wo[jj] = __uint_as_float(f2tf32(Wo[jj]));
}

// ---------------- prep_A: g_A = tf32([x | qshift(x)]) ----------------
__global__ __launch_bounds__(384) void prepa_kernel(const float* __restrict__ x) {
    int tb = blockIdx.x * 8;
    int k = threadIdx.x;
#pragma unroll
    for (int j = 0; j < 8; j++) {
        int gt = tb + j;
        float v;
        if (k < 192) {
            v = x[(size_t)gt*C_ + k];
        } else {
            int c = k - 192;
            int tt = gt & 4095;
            int hh = tt >> 6, ww = tt & 63;
            int g = c / 48;
            int src; bool ok;
            if (g == 0)      { ok = (ww >= 1);  src = gt - 1; }
            else if (g == 1) { ok = (ww <= 62); src = gt + 1; }
            else if (g == 2) { ok = (hh >= 1);  src = gt - 64; }
            else             { ok = (hh <= 62); src = gt + 64; }
            v = ok ? x[(size_t)src*C_ + c] : 0.f;
        }
        g_A[(size_t)gt*384 + k] = __uint_as_float(f2tf32(v));
    }
}

// ---------------- convP: g_P = x @ Wp (fp32 exact) ----------------
__global__ __launch_bounds__(256) void convP_kernel(const float* __restrict__ x) {
    __shared__ float xs[8][193];
    int tid = threadIdx.x;
    int tok0 = blockIdx.x * 8;
    for (int i = tid; i < 8*192; i += 256) {
        int r = i / 192, c = i % 192;
        xs[r][c] = x[(size_t)(tok0 + r)*C_ + c];
    }
    __syncthreads();
    int r = tid >> 5, n = tid & 31;
    if (n < 28) {
        float acc = 0.f;
#pragma unroll 8
        for (int c = 0; c < 192; c++)
            acc = fmaf(xs[r][c], g_Wp[c*32 + n], acc);
        g_P[(size_t)(tok0 + r)*32 + n] = acc;
    }
}

// ---------------- adaptive peak -> transposed output (B,C,T) ----------------
__global__ __launch_bounds__(384) void peak_kernel(const float* __restrict__ x,
                                                   const float* __restrict__ cvb,
                                                   const float* __restrict__ bns_v,
                                                   const float* __restrict__ bnb_v,
                                                   const float* __restrict__ chb,
                                                   const float* __restrict__ bns_h,
                                                   const float* __restrict__ bnb_h) {
    int bi = blockIdx.x;                  // 512 blocks
    int b = bi >> 8;
    int tb = (bi & 255) * 16;
    int hh = tb >> 6, wwb = tb & 63;
    __shared__ float gbv[16][4];
    __shared__ int   s_lt[16][16], s_rb[16][16];
    __shared__ float s_wlt[16][16], s_wrb[16][16];
    __shared__ float st[192*17];          // [channel][token] stage, pad 17
    int tid = threadIdx.x;

    if (tid < 64) {
        int j = tid >> 2, dir = tid & 3;
        int ww = wwb + j;
        const float* Pb = g_P + (size_t)b * T_ * 32;
        float s = 0.f;
        if (dir < 2) {
#pragma unroll
            for (int r = 0; r < 7; r++) {
                int hy = hh + r - 3;
                if (hy >= 0 && hy < 64) s += Pb[(size_t)(hy*64 + ww)*32 + dir*7 + r];
            }
        } else {
#pragma unroll
            for (int r = 0; r < 7; r++) {
                int wy = ww + r - 3;
                if (wy >= 0 && wy < 64) s += Pb[(size_t)(hh*64 + wy)*32 + (dir-2)*7 + 14 + r];
            }
        }
        const float inv = rsqrtf(1.f + 1e-5f);
        float bias, scale, shift;
        if (dir == 0)      { bias = cvb[0]; scale = bns_v[0]; shift = bnb_v[0]; }
        else if (dir == 1) { bias = cvb[1]; scale = bns_v[1]; shift = bnb_v[1]; }
        else if (dir == 2) { bias = chb[0]; scale = bns_h[0]; shift = bnb_h[0]; }
        else               { bias = chb[1]; scale = bns_h[1]; shift = bnb_h[1]; }
        float val = (s + bias) * (scale * inv) + shift;
        gbv[j][dir] = 2.f / (1.f + expf(-val));
    }
    __syncthreads();

    if (tid < 256) {
        int j = tid >> 4, o = tid & 15;
        int ww = wwb + j;
        int blk = o >> 2;
        float mx = 0.f, my = 0.f;
        if (blk == 0)      mx = -gbv[j][0];
        else if (blk == 1) my =  gbv[j][3];
        else if (blk == 2) mx =  gbv[j][1];
        else               my = -gbv[j][2];
        float px = (float)(hh + 2) + c_prfx[o] + mx;
        float py = (float)(ww + 2) + c_prfy[o] + my;
        float flx = floorf(px), fly = floorf(py);
        float qltx = fminf(fmaxf(flx,     0.f), 67.f);
        float qlty = fminf(fmaxf(fly,     0.f), 67.f);
        float qrbx = fminf(fmaxf(flx+1.f, 0.f), 67.f);
        float qrby = fminf(fmaxf(fly+1.f, 0.f), 67.f);
        float pxc  = fminf(fmaxf(px,      0.f), 67.f);
        float pyc  = fminf(fmaxf(py,      0.f), 67.f);
        float glt = (1.f + (qltx - pxc)) * (1.f + (qlty - pyc));
        float grb = (1.f - (qrbx - pxc)) * (1.f - (qrby - pyc));
        int rlt = min(max((int)qltx - 2, 0), 63);
        int clt = min(max((int)qlty - 2, 0), 63);
        int rrb = min(max((int)qrbx - 2, 0), 63);
        int crb = min(max((int)qrby - 2, 0), 63);
        s_lt[j][o] = rlt*64 + clt;  s_rb[j][o] = rrb*64 + crb;
        s_wlt[j][o] = glt;          s_wrb[j][o] = grb;
    }
    __syncthreads();

    const float* xb = x + (size_t)b * T_ * C_;
    int slot = tid / 48;
    int c4 = (tid % 48) * 4;
#pragma unroll
    for (int rep = 0; rep < 2; rep++) {
        int j = slot + rep*8;
        float a0 = 0.f, a1 = 0.f, a2 = 0.f, a3 = 0.f;
#pragma unroll
        for (int o = 0; o < 16; o++) {
            float4 a = *(const float4*)&xb[(size_t)s_lt[j][o]*C_ + c4];
            float4 bv = *(const float4*)&xb[(size_t)s_rb[j][o]*C_ + c4];
            float wl = s_wlt[j][o], wr = s_wrb[j][o];
            a0 += wl*a.x + wr*bv.x;
            a1 += wl*a.y + wr*bv.y;
            a2 += wl*a.z + wr*bv.z;
            a3 += wl*a.w + wr*bv.w;
        }
        size_t idx = ((size_t)b*T_ + tb + j)*C_ + c4;
        float4 xc = *(const float4*)&x[idx];
        st[(c4+0)*17 + j] = xc.x - a0*(1.f/16.f);
        st[(c4+1)*17 + j] = xc.y - a1*(1.f/16.f);
        st[(c4+2)*17 + j] = xc.z - a2*(1.f/16.f);
        st[(c4+3)*17 + j] = xc.w - a3*(1.f/16.f);
    }
    __syncthreads();

    // write transposed: peakT[(b*C + c)*T + tb + t]
#pragma unroll
    for (int q = 0; q < 2; q++) {
        int f = tid + q*384;              // 0..767 = 192 ch x 4 float4
        int cr = f >> 2;
        int t4 = (f & 3) * 4;
        float4 v;
        v.x = st[cr*17 + t4 + 0];
        v.y = st[cr*17 + t4 + 1];
        v.z = st[cr*17 + t4 + 2];
        v.w = st[cr*17 + t4 + 3];
        *(float4*)&g_peakT[((size_t)(b*C_ + cr))*T_ + tb + t4] = v;
    }
}

// ---------------- fused front GEMM: block 128x96, 8 warps, warp 32x48 ----------------
#define AS1 36
#define BS1 104
#define A_BUF (128*AS1)
#define B_BUF (32*BS1)

__global__ __launch_bounds__(256) void gemm1_kernel() {
    extern __shared__ float smem[];
    float* AsBuf = smem;
    float* BsBuf = smem + 2*A_BUF;

    int tid = threadIdx.x;
    int warp = tid >> 5, lane = tid & 31;
    int bm = blockIdx.x * 128;
    int bny = blockIdx.y;                // 0..5
    int bn = bny * 96;
    int cls = bny >> 1;                  // 0:k 1:v 2:r
    int nloc = (bny & 1) * 96;
    int wm = (warp >> 1) * 32;
    int wn = (warp & 1) * 48;
    int gid = lane >> 2, tig = lane & 3;

    const float* Abase = g_A + (size_t)bm * 384;
    float acc[2][6][4] = {};

    float4 pa[4], pb[3];
#pragma unroll
    for (int q = 0; q < 4; q++) {
        int f = tid + q*256;
        pa[q] = *(const float4*)&Abase[(size_t)(f >> 3)*384 + (f & 7)*4];
    }
#pragma unroll
    for (int q = 0; q < 3; q++) {
        int f = tid + q*256;
        pb[q] = *(const float4*)&g_Wf[(size_t)(f/24)*576 + bn + (f%24)*4];
    }
#pragma unroll
    for (int q = 0; q < 4; q++) {
        int f = tid + q*256;
        *(float4*)&AsBuf[(f >> 3)*AS1 + (f & 7)*4] = pa[q];
    }
#pragma unroll
    for (int q = 0; q < 3; q++) {
        int f = tid + q*256;
        *(float4*)&BsBuf[(f/24)*BS1 + (f%24)*4] = pb[q];
    }
    __syncthreads();

    for (int kc = 0; kc < 12; kc++) {
        int cur = kc & 1;
        if (kc < 11) {
            int k0 = (kc + 1) * 32;
#pragma unroll
            for (int q = 0; q < 4; q++) {
                int f = tid + q*256;
                pa[q] = *(const float4*)&Abase[(size_t)(f >> 3)*384 + k0 + (f & 7)*4];
            }
#pragma unroll
            for (int q = 0; q < 3; q++) {
                int f = tid + q*256;
                pb[q] = *(const float4*)&g_Wf[(size_t)(k0 + f/24)*576 + bn + (f%24)*4];
            }
        }
        const float* as = AsBuf + cur*A_BUF;
        const float* bs = BsBuf + cur*B_BUF;
#pragma unroll
        for (int ks = 0; ks < 4; ks++) {
            int kk0 = ks * 8;
            unsigned afr[2][4], bfr[6][2];
#pragma unroll
            for (int mi = 0; mi < 2; mi++) {
                int rbase = (wm + mi*16 + gid) * AS1;
                afr[mi][0] = __float_as_uint(as[rbase + kk0 + tig]);
                afr[mi][1] = __float_as_uint(as[rbase + 8*AS1 + kk0 + tig]);
                afr[mi][2] = __float_as_uint(as[rbase + kk0 + tig + 4]);
                afr[mi][3] = __float_as_uint(as[rbase + 8*AS1 + kk0 + tig + 4]);
            }
#pragma unroll
            for (int ni = 0; ni < 6; ni++) {
                int col = wn + ni*8 + gid;
                bfr[ni][0] = __float_as_uint(bs[(kk0 + tig)*BS1 + col]);
                bfr[ni][1] = __float_as_uint(bs[(kk0 + tig + 4)*BS1 + col]);
            }
#pragma unroll
            for (int mi = 0; mi < 2; mi++)
#pragma unroll
                for (int ni = 0; ni < 6; ni++)
                    mma8(acc[mi][ni], afr[mi][0], afr[mi][1], afr[mi][2], afr[mi][3],
                         bfr[ni][0], bfr[ni][1]);
        }
        if (kc < 11) {
            __syncthreads();
            int nxt = cur ^ 1;
#pragma unroll
            for (int q = 0; q < 4; q++) {
                int f = tid + q*256;
                *(float4*)&AsBuf[nxt*A_BUF + (f >> 3)*AS1 + (f & 7)*4] = pa[q];
            }
#pragma unroll
            for (int q = 0; q < 3; q++) {
                int f = tid + q*256;
                *(float4*)&BsBuf[nxt*B_BUF + (f/24)*BS1 + (f%24)*4] = pb[q];
            }
            __syncthreads();
        }
    }

    if (cls == 2) {
#pragma unroll
        for (int mi = 0; mi < 2; mi++) {
            int r0 = bm + wm + mi*16 + gid;
#pragma unroll
            for (int ni = 0; ni < 6; ni++) {
                int c0 = nloc + wn + ni*8 + tig*2;
                float v0 = 1.f/(1.f+expf(-acc[mi][ni][0]));
                float v1 = 1.f/(1.f+expf(-acc[mi][ni][1]));
                float v2 = 1.f/(1.f+expf(-acc[mi][ni][2]));
                float v3 = 1.f/(1.f+expf(-acc[mi][ni][3]));
                *(float2*)&g_sr[(size_t)r0*C_ + c0]     = make_float2(v0, v1);
                *(float2*)&g_sr[(size_t)(r0+8)*C_ + c0] = make_float2(v2, v3);
            }
        }
        return;
    }

    // k and v: transpose stage st[channel][token], stride 132
    __syncthreads();
    float* st = smem;
#pragma unroll
    for (int mi = 0; mi < 2; mi++) {
        int r = wm + mi*16 + gid;
#pragma unroll
        for (int ni = 0; ni < 6; ni++) {
            int cc = wn + ni*8 + tig*2;
            st[cc*132 + r]         = acc[mi][ni][0];
            st[(cc+1)*132 + r]     = acc[mi][ni][1];
            st[cc*132 + r + 8]     = acc[mi][ni][2];
            st[(cc+1)*132 + r + 8] = acc[mi][ni][3];
        }
    }
    __syncthreads();
    float* dst = (cls == 0) ? g_kT : g_vT;
    int bb = bm >> 12, trow = bm & 4095;
#pragma unroll
    for (int q = 0; q < 12; q++) {
        int f = q*256 + tid;
        int cr = f >> 5;
        int t4 = (f & 31) * 4;
        float4 v = *(const float4*)&st[cr*132 + t4];
        *(float4*)&dst[((size_t)(bb*C_ + nloc + cr))*T_ + trow + t4] = v;
    }
}

// ---------------- bidirectional WKV scan (v = vT + peakT on load) ----------------
struct Agg { float a, b, dl; };
__device__ __forceinline__ Agg combine(Agg p, Agg s) {
    Agg r;
    r.a  = fmaf(s.dl, p.a, s.a);
    r.b  = fmaf(s.dl, p.b, s.b);
    r.dl = p.dl * s.dl;
    return r;
}
__device__ __forceinline__ Agg shfl_up_agg(Agg v, int off) {
    Agg r;
    r.a  = __shfl_up_sync(0xffffffffu, v.a,  off);
    r.b  = __shfl_up_sync(0xffffffffu, v.b,  off);
    r.dl = __shfl_up_sync(0xffffffffu, v.dl, off);
    return r;
}
__device__ __forceinline__ Agg shfl_dn_agg(Agg v, int off) {
    Agg r;
    r.a  = __shfl_down_sync(0xffffffffu, v.a,  off);
    r.b  = __shfl_down_sync(0xffffffffu, v.b,  off);
    r.dl = __shfl_down_sync(0xffffffffu, v.dl, off);
    return r;
}

__global__ __launch_bounds__(256) void wkv_kernel(const float* __restrict__ sd,
                                                  const float* __restrict__ sf) {
    __shared__ float eks[4352];
    __shared__ float vvs[4352];
    __shared__ Agg warpAgg[8];
    __shared__ Agg warpPre[8];
    int bc = blockIdx.x;
    int c = bc % C_;
    float w  = sd[c] * (1.0f / T_);
    float u  = sf[c] * (1.0f / T_);
    float d  = expf(-w);
    float eu = expf(u);
    float d2 = d*d, d4 = d2*d2, d8 = d4*d4, d16 = d8*d8;
    int tid = threadIdx.x;
    int lane = tid & 31, wid = tid >> 5;
    const float4* kp4 = (const float4*)(g_kT + (size_t)bc * T_);
    const float4* vp4 = (const float4*)(g_vT + (size_t)bc * T_);
    const float4* pk4 = (const float4*)(g_peakT + (size_t)bc * T_);

#pragma unroll
    for (int q = 0; q < 4; q++) {
        int idx = tid + q*256;
        float4 kv = kp4[idx];
        float4 v4 = vp4[idx];
        float4 p4 = pk4[idx];
        v4.x += p4.x; v4.y += p4.y; v4.z += p4.z; v4.w += p4.w;
        int t = idx * 4;
        int base = t + (t >> 4);
        eks[base+0] = expf(kv.x); eks[base+1] = expf(kv.y);
        eks[base+2] = expf(kv.z); eks[base+3] = expf(kv.w);
        vvs[base+0] = v4.x; vvs[base+1] = v4.y;
        vvs[base+2] = v4.z; vvs[base+3] = v4.w;
    }
    __syncthreads();

    float ek[16], vv[16];
    int rb = 17 * tid;
#pragma unroll
    for (int i = 0; i < 16; i++) { ek[i] = eks[rb + i]; vv[i] = vvs[rb + i]; }

    Agg ag; ag.a = 0.f; ag.b = 0.f; ag.dl = d16;
#pragma unroll
    for (int i = 0; i < 16; i++) {
        ag.a = fmaf(d, ag.a, ek[i]);
        ag.b = fmaf(d, ag.b, ek[i]*vv[i]);
    }
    Agg inc = ag;
#pragma unroll
    for (int off = 1; off < 32; off <<= 1) {
        Agg o = shfl_up_agg(inc, off);
        if (lane >= off) inc = combine(o, inc);
    }
    if (lane == 31) warpAgg[wid] = inc;
    __syncthreads();
    if (tid == 0) {
        Agg run; run.a = 0.f; run.b = 0.f; run.dl = 1.f;
        for (int i = 0; i < 8; i++) { warpPre[i] = run; run = combine(run, warpAgg[i]); }
    }
    __syncthreads();
    Agg pl = shfl_up_agg(inc, 1);
    Agg ex = warpPre[wid];
    if (lane > 0) ex = combine(ex, pl);

    float af = ex.a, bf = ex.b;
    float saf[16], sbf[16];
#pragma unroll
    for (int i = 0; i < 16; i++) {
        saf[i] = af; sbf[i] = bf;
        af = fmaf(d, af, ek[i]);
        bf = fmaf(d, bf, ek[i]*vv[i]);
    }
    __syncthreads();

    Agg bg; bg.a = 0.f; bg.b = 0.f; bg.dl = d16;
#pragma unroll
    for (int i = 15; i >= 0; i--) {
        bg.a = fmaf(d, bg.a, ek[i]);
        bg.b = fmaf(d, bg.b, ek[i]*vv[i]);
    }
    Agg binc = bg;
#pragma unroll
    for (int off = 1; off < 32; off <<= 1) {
        Agg o = shfl_dn_agg(binc, off);
        if (lane < 32 - off) binc = combine(o, binc);
    }
    if (lane == 0) warpAgg[wid] = binc;
    __syncthreads();
    if (tid == 0) {
        Agg run; run.a = 0.f; run.b = 0.f; run.dl = 1.f;
        for (int i = 7; i >= 0; i--) { warpPre[i] = run; run = combine(run, warpAgg[i]); }
    }
    __syncthreads();
    Agg bpl = shfl_dn_agg(binc, 1);
    Agg bex = warpPre[wid];
    if (lane < 31) bex = combine(bex, bpl);

    float ab = bex.a, bb = bex.b;
#pragma unroll
    for (int i = 15; i >= 0; i--) {
        float es  = eu * ek[i];
        float num = sbf[i] + bb + es * vv[i];
        float den = saf[i] + ab + es;
        vvs[rb + i] = num / den;
        ab = fmaf(d, ab, ek[i]);
        bb = fmaf(d, bb, ek[i]*vv[i]);
    }
    __syncthreads();

    float4* yp4 = (float4*)(g_yT + (size_t)bc * T_);
#pragma unroll
    for (int q = 0; q < 4; q++) {
        int idx = tid + q*256;
        int t = idx * 4;
        int base = t + (t >> 4);
        yp4[idx] = make_float4(vvs[base+0], vvs[base+1], vvs[base+2], vvs[base+3]);
    }
}

// ---------------- output GEMM (1x tf32): out = (sr .* y) @ Wo ----------------
#define A2_STRIDE 197
#define BS_STRIDE 72

__global__ __launch_bounds__(128) void gemm2_kernel(float* __restrict__ out) {
    __shared__ unsigned As2[32 * A2_STRIDE];
    __shared__ unsigned Bs2[2][32 * BS_STRIDE];

    int tid = threadIdx.x;
    int warp = tid >> 5, lane = tid & 31;
    int gid = lane >> 2, tig = lane & 3;
    int bm = blockIdx.x * 32;
    int bn = blockIdx.y * 64;
    int wm = (warp >> 1) * 16;
    int wn = (warp & 1) * 32;
    int bb = bm >> 12, trow = bm & 4095;

#pragma unroll
    for (int q = 0; q < 12; q++) {
        int f = q*128 + tid;
        int row = f >> 3;
        int t4 = (f & 7) * 4;
        float4 v = *(const float4*)&g_yT[((size_t)(bb*C_ + row))*T_ + trow + t4];
        As2[(t4+0)*A2_STRIDE + row] = __float_as_uint(v.x);
        As2[(t4+1)*A2_STRIDE + row] = __float_as_uint(v.y);
        As2[(t4+2)*A2_STRIDE + row] = __float_as_uint(v.z);
        As2[(t4+3)*A2_STRIDE + row] = __float_as_uint(v.w);
    }
    __syncthreads();
#pragma unroll
    for (int q = 0; q < 12; q++) {
        int f = q*128 + tid;
        int t = f / 48, c4 = (f % 48) * 4;
        float4 s = *(const float4*)&g_sr[((size_t)(bm + t))*C_ + c4];
        unsigned* p = &As2[t*A2_STRIDE + c4];
        p[0] = f2tf32(__uint_as_float(p[0]) * s.x);
        p[1] = f2tf32(__uint_as_float(p[1]) * s.y);
        p[2] = f2tf32(__uint_as_float(p[2]) * s.z);
        p[3] = f2tf32(__uint_as_float(p[3]) * s.w);
    }

    int br = tid >> 4;
    int bc = (tid & 15) * 4;
    float acc[4][4] = {};

    float4 pb[4];
#pragma unroll
    for (int i = 0; i < 4; i++)
        pb[i] = *(const float4*)&g_Wo[(size_t)(br + i*8)*C_ + bn + bc];
#pragma unroll
    for (int i = 0; i < 4; i++)
        *(float4*)&Bs2[0][(br + i*8)*BS_STRIDE + bc] = pb[i];
    __syncthreads();

    for (int kc = 0; kc < 6; kc++) {
        int cur = kc & 1;
        if (kc < 5) {
            int k0 = (kc + 1) * 32;
#pragma unroll
            for (int i = 0; i < 4; i++)
                pb[i] = *(const float4*)&g_Wo[(size_t)(k0 + br + i*8)*C_ + bn + bc];
        }
        const unsigned* bs = Bs2[cur];
        int k0 = kc * 32;
#pragma unroll
        for (int ks = 0; ks < 4; ks++) {
            int kk = k0 + ks*8;
            unsigned a0 = As2[(wm+gid)*A2_STRIDE + kk + tig];
            unsigned a1 = As2[(wm+gid+8)*A2_STRIDE + kk + tig];
            unsigned a2 = As2[(wm+gid)*A2_STRIDE + kk + tig + 4];
            unsigned a3 = As2[(wm+gid+8)*A2_STRIDE + kk + tig + 4];
#pragma unroll
            for (int ni = 0; ni < 4; ni++) {
                int col = wn + ni*8 + gid;
                unsigned b0 = bs[(ks*8 + tig)*BS_STRIDE + col];
                unsigned b1 = bs[(ks*8 + tig + 4)*BS_STRIDE + col];
                mma8(acc[ni], a0, a1, a2, a3, b0, b1);
            }
        }
        if (kc < 5) {
            __syncthreads();
            int nxt = cur ^ 1;
#pragma unroll
            for (int i = 0; i < 4; i++)
                *(float4*)&Bs2[nxt][(br + i*8)*BS_STRIDE + bc] = pb[i];
            __syncthreads();
        }
    }

    int r0 = bm + wm + gid;
#pragma unroll
    for (int ni = 0; ni < 4; ni++) {
        int c0 = bn + wn + ni*8 + tig*2;
        *(float2*)&out[(size_t)r0*C_ + c0]     = make_float2(acc[ni][0], acc[ni][1]);
        *(float2*)&out[(size_t)(r0+8)*C_ + c0] = make_float2(acc[ni][2], acc[ni][3]);
    }
}

// ---------------- launch: prep_w -> { prep_A -> gemm1 } || { convP -> peak } -> wkv -> gemm2
#define GEMM1_SMEM ((2*A_BUF + 2*B_BUF) * 4)

namespace {
struct SideStream {
    cudaStream_t s1;
    cudaEvent_t evFork, evJoin;
    SideStream() {
        cudaStreamCreateWithFlags(&s1, cudaStreamNonBlocking);
        cudaEventCreateWithFlags(&evFork, cudaEventDisableTiming);
        cudaEventCreateWithFlags(&evJoin, cudaEventDisableTiming);
    }
};
SideStream g_ss;
}

extern "C" void kernel_launch(void* const* d_in, const int* in_sizes, int n_in,
                              void* d_out, int out_size) {
    const float* x = (const float*)d_in[0];
    int base = (in_sizes[1] == 1) ? 3 : 1;
    const float* mk    = (const float*)d_in[base + 0];
    const float* mv    = (const float*)d_in[base + 1];
    const float* mr    = (const float*)d_in[base + 2];
    const float* Wk    = (const float*)d_in[base + 3];
    const float* Wv    = (const float*)d_in[base + 4];
    const float* Wr    = (const float*)d_in[base + 5];
    const float* Wo    = (const float*)d_in[base + 6];
    const float* sd    = (const float*)d_in[base + 7];
    const float* sf    = (const float*)d_in[base + 8];
    const float* cvw   = (const float*)d_in[base + 9];
    const float* cvb   = (const float*)d_in[base + 10];
    const float* bns_v = (const float*)d_in[base + 11];
    const float* bnb_v = (const float*)d_in[base + 12];
    const float* chw   = (const float*)d_in[base + 13];
    const float* chb   = (const float*)d_in[base + 14];
    const float* bns_h = (const float*)d_in[base + 15];
    const float* bnb_h = (const float*)d_in[base + 16];

    cudaFuncSetAttribute(gemm1_kernel, cudaFuncAttributeMaxDynamicSharedMemorySize, GEMM1_SMEM);

    // weights (needed by both branches)
    prepw_kernel<<<688, 384>>>(mk, mv, mr, Wk, Wv, Wr, Wo, cvw, chw);

    // fork
    cudaEventRecord(g_ss.evFork, 0);
    cudaStreamWaitEvent(g_ss.s1, g_ss.evFork, 0);

    // side: convP -> peak (produces g_peakT, needed only by wkv)
    convP_kernel<<<1024, 256, 0, g_ss.s1>>>(x);
    peak_kernel<<<512, 384, 0, g_ss.s1>>>(x, cvb, bns_v, bnb_v, chb, bns_h, bnb_h);
    cudaEventRecord(g_ss.evJoin, g_ss.s1);

    // main: prep_A -> gemm1 (single full launch, no peak dependency)
    prepa_kernel<<<1024, 384>>>(x);
    gemm1_kernel<<<dim3(64, 6), 256, GEMM1_SMEM>>>();

    // join before wkv (needs peakT + kT + vT)
    cudaStreamWaitEvent(0, g_ss.evJoin, 0);
    wkv_kernel<<<B_*C_, 256>>>(sd, sf);
    gemm2_kernel<<<dim3(256, 3), 128>>>((float*)d_out);
}

// round 12
// speedup vs baseline: 1.7914x; 1.0594x over previous
#include <cuda_runtime.h>
#include <math.h>

#define B_ 2
#define T_ 4096
#define C_ 192
#define NTOT (B_*T_*C_)

// ---------------- scratch ----------------
__device__ float g_Wf[384*576];      // tf32-pre-rounded fused [k|v|r] weights
__device__ float g_Wo[192*192];      // tf32-pre-rounded output weights
__device__ float g_Wp[192*32];       // exact fp32 conv-tap weights
__device__ float g_A[B_*T_*384];     // tf32-pre-rounded [x | qshift(x)]
__device__ float g_P[B_*T_*32];
__device__ float g_peakT[NTOT];      // peak, (B,C,T) layout
__device__ float g_kT[NTOT];
__device__ float g_vT[NTOT];
__device__ float g_yT[NTOT];
__device__ float g_sr[NTOT];

__constant__ float c_prfx[16] = {-2,-2,-2,-2, -2,-1,0,1,  2,2,2,2,  -1,0,1,2};
__constant__ float c_prfy[16] = {-2,-1,0,1,   2,2,2,2,  -1,0,1,2,  -2,-2,-2,-2};

__device__ __forceinline__ unsigned f2tf32(float x) {
    unsigned r;
    asm("cvt.rna.tf32.f32 %0, %1;" : "=r"(r) : "f"(x));
    return r;
}

__device__ __forceinline__ void mma8(float* d, unsigned a0, unsigned a1, unsigned a2, unsigned a3,
                                     unsigned b0, unsigned b1) {
    asm volatile(
        "mma.sync.aligned.m16n8k8.row.col.f32.tf32.tf32.f32 "
        "{%0,%1,%2,%3}, {%4,%5,%6,%7}, {%8,%9}, {%0,%1,%2,%3};\n"
        : "+f"(d[0]), "+f"(d[1]), "+f"(d[2]), "+f"(d[3])
        : "r"(a0), "r"(a1), "r"(a2), "r"(a3), "r"(b0), "r"(b1));
}

// ---------------- prep_w: weights only ----------------
__global__ __launch_bounds__(384) void prepw_kernel(const float* __restrict__ mk,
                                                    const float* __restrict__ mv,
                                                    const float* __restrict__ mr,
                                                    const float* __restrict__ Wk,
                                                    const float* __restrict__ Wv,
                                                    const float* __restrict__ Wr,
                                                    const float* __restrict__ Wo,
                                                    const float* __restrict__ cvw,
                                                    const float* __restrict__ chw) {
    int i = blockIdx.x * 384 + threadIdx.x;
    if (i < 384*576) {
        int row = i / 576, n = i % 576;
        int c = row % 192;
        bool second = row >= 192;
        const float* W; float m; int nn;
        if (n < 192)      { W = Wk; m = mk[c]; nn = n; }
        else if (n < 384) { W = Wv; m = mv[c]; nn = n - 192; }
        else              { W = Wr; m = mr[c]; nn = n - 384; }
        float v = (second ? (1.f - m) : m) * W[c*192 + nn];
        g_Wf[i] = __uint_as_float(f2tf32(v));
        return;
    }
    int j = i - 384*576;
    if (j < 192*32) {
        int c = j / 32, n = j % 32;
        float v = 0.f;
        if (n < 14)      v = cvw[(n/7)*C_*7 + c*7 + (n%7)];
        else if (n < 28) { int n2 = n - 14; v = chw[(n2/7)*C_*7 + c*7 + (n2%7)]; }
        g_Wp[j] = v;
        return;
    }
    int jj = j - 192*32;
    if (jj < 192*192)
        g_Wo[jj] = __uint_as_float(f2tf32(Wo[jj]));
}

// ---------------- prep_A (vectorized): g_A = tf32([x | qshift(x)]) ----------------
// 384 channels = 96 float4 per token; mix groups are 48-channel (12-float4) aligned,
// and shifts are whole tokens -> every float4 load is aligned and group-uniform.
__global__ __launch_bounds__(384) void prepa_kernel(const float* __restrict__ x) {
    const float4* x4 = (const float4*)x;
    float4* A4 = (float4*)g_A;
    int tb = blockIdx.x * 16;                 // 512 blocks x 16 tokens
    int j0 = threadIdx.x / 96;                // 0..3
    int f4 = threadIdx.x % 96;                // float4 index within 384-ch row
    bool shifted = f4 >= 48;
    int c4f = shifted ? (f4 - 48) : f4;       // 0..47 float4 within 192 ch
    int g = c4f / 12;                         // 48-ch group
#pragma unroll
    for (int rep = 0; rep < 4; rep++) {
        int gt = tb + j0 + rep*4;
        float4 v;
        if (!shifted) {
            v = x4[(size_t)gt*48 + c4f];
        } else {
            int tt = gt & 4095;
            int hh = tt >> 6, ww = tt & 63;
            int src; bool ok;
            if (g == 0)      { ok = (ww >= 1);  src = gt - 1; }
            else if (g == 1) { ok = (ww <= 62); src = gt + 1; }
            else if (g == 2) { ok = (hh >= 1);  src = gt - 64; }
            else             { ok = (hh <= 62); src = gt + 64; }
            v = ok ? x4[(size_t)src*48 + c4f] : make_float4(0.f, 0.f, 0.f, 0.f);
        }
        float4 o;
        o.x = __uint_as_float(f2tf32(v.x));
        o.y = __uint_as_float(f2tf32(v.y));
        o.z = __uint_as_float(f2tf32(v.z));
        o.w = __uint_as_float(f2tf32(v.w));
        A4[(size_t)gt*96 + f4] = o;
    }
}

// ---------------- convP: g_P = x @ Wp (fp32 exact) ----------------
__global__ __launch_bounds__(256) void convP_kernel(const float* __restrict__ x) {
    __shared__ float xs[8][193];
    int tid = threadIdx.x;
    int tok0 = blockIdx.x * 8;
    for (int i = tid; i < 8*192; i += 256) {
        int r = i / 192, c = i % 192;
        xs[r][c] = x[(size_t)(tok0 + r)*C_ + c];
    }
    __syncthreads();
    int r = tid >> 5, n = tid & 31;
    if (n < 28) {
        float acc = 0.f;
#pragma unroll 8
        for (int c = 0; c < 192; c++)
            acc = fmaf(xs[r][c], g_Wp[c*32 + n], acc);
        g_P[(size_t)(tok0 + r)*32 + n] = acc;
    }
}

// ---------------- adaptive peak -> transposed output (B,C,T) ----------------
__global__ __launch_bounds__(384) void peak_kernel(const float* __restrict__ x,
                                                   const float* __restrict__ cvb,
                                                   const float* __restrict__ bns_v,
                                                   const float* __restrict__ bnb_v,
                                                   const float* __restrict__ chb,
                                                   const float* __restrict__ bns_h,
                                                   const float* __restrict__ bnb_h) {
    int bi = blockIdx.x;                  // 512 blocks
    int b = bi >> 8;
    int tb = (bi & 255) * 16;
    int hh = tb >> 6, wwb = tb & 63;
    __shared__ float gbv[16][4];
    __shared__ int   s_lt[16][16], s_rb[16][16];
    __shared__ float s_wlt[16][16], s_wrb[16][16];
    __shared__ float st[192*17];          // [channel][token] stage, pad 17
    int tid = threadIdx.x;

    if (tid < 64) {
        int j = tid >> 2, dir = tid & 3;
        int ww = wwb + j;
        const float* Pb = g_P + (size_t)b * T_ * 32;
        float s = 0.f;
        if (dir < 2) {
#pragma unroll
            for (int r = 0; r < 7; r++) {
                int hy = hh + r - 3;
                if (hy >= 0 && hy < 64) s += Pb[(size_t)(hy*64 + ww)*32 + dir*7 + r];
            }
        } else {
#pragma unroll
            for (int r = 0; r < 7; r++) {
                int wy = ww + r - 3;
                if (wy >= 0 && wy < 64) s += Pb[(size_t)(hh*64 + wy)*32 + (dir-2)*7 + 14 + r];
            }
        }
        const float inv = rsqrtf(1.f + 1e-5f);
        float bias, scale, shift;
        if (dir == 0)      { bias = cvb[0]; scale = bns_v[0]; shift = bnb_v[0]; }
        else if (dir == 1) { bias = cvb[1]; scale = bns_v[1]; shift = bnb_v[1]; }
        else if (dir == 2) { bias = chb[0]; scale = bns_h[0]; shift = bnb_h[0]; }
        else               { bias = chb[1]; scale = bns_h[1]; shift = bnb_h[1]; }
        float val = (s + bias) * (scale * inv) + shift;
        gbv[j][dir] = 2.f / (1.f + expf(-val));
    }
    __syncthreads();

    if (tid < 256) {
        int j = tid >> 4, o = tid & 15;
        int ww = wwb + j;
        int blk = o >> 2;
        float mx = 0.f, my = 0.f;
        if (blk == 0)      mx = -gbv[j][0];
        else if (blk == 1) my =  gbv[j][3];
        else if (blk == 2) mx =  gbv[j][1];
        else               my = -gbv[j][2];
        float px = (float)(hh + 2) + c_prfx[o] + mx;
        float py = (float)(ww + 2) + c_prfy[o] + my;
        float flx = floorf(px), fly = floorf(py);
        float qltx = fminf(fmaxf(flx,     0.f), 67.f);
        float qlty = fminf(fmaxf(fly,     0.f), 67.f);
        float qrbx = fminf(fmaxf(flx+1.f, 0.f), 67.f);
        float qrby = fminf(fmaxf(fly+1.f, 0.f), 67.f);
        float pxc  = fminf(fmaxf(px,      0.f), 67.f);
        float pyc  = fminf(fmaxf(py,      0.f), 67.f);
        float glt = (1.f + (qltx - pxc)) * (1.f + (qlty - pyc));
        float grb = (1.f - (qrbx - pxc)) * (1.f - (qrby - pyc));
        int rlt = min(max((int)qltx - 2, 0), 63);
        int clt = min(max((int)qlty - 2, 0), 63);
        int rrb = min(max((int)qrbx - 2, 0), 63);
        int crb = min(max((int)qrby - 2, 0), 63);
        s_lt[j][o] = rlt*64 + clt;  s_rb[j][o] = rrb*64 + crb;
        s_wlt[j][o] = glt;          s_wrb[j][o] = grb;
    }
    __syncthreads();

    const float* xb = x + (size_t)b * T_ * C_;
    int slot = tid / 48;
    int c4 = (tid % 48) * 4;
#pragma unroll
    for (int rep = 0; rep < 2; rep++) {
        int j = slot + rep*8;
        float a0 = 0.f, a1 = 0.f, a2 = 0.f, a3 = 0.f;
#pragma unroll
        for (int o = 0; o < 16; o++) {
            float4 a = *(const float4*)&xb[(size_t)s_lt[j][o]*C_ + c4];
            float4 bv = *(const float4*)&xb[(size_t)s_rb[j][o]*C_ + c4];
            float wl = s_wlt[j][o], wr = s_wrb[j][o];
            a0 += wl*a.x + wr*bv.x;
            a1 += wl*a.y + wr*bv.y;
            a2 += wl*a.z + wr*bv.z;
            a3 += wl*a.w + wr*bv.w;
        }
        size_t idx = ((size_t)b*T_ + tb + j)*C_ + c4;
        float4 xc = *(const float4*)&x[idx];
        st[(c4+0)*17 + j] = xc.x - a0*(1.f/16.f);
        st[(c4+1)*17 + j] = xc.y - a1*(1.f/16.f);
        st[(c4+2)*17 + j] = xc.z - a2*(1.f/16.f);
        st[(c4+3)*17 + j] = xc.w - a3*(1.f/16.f);
    }
    __syncthreads();

#pragma unroll
    for (int q = 0; q < 2; q++) {
        int f = tid + q*384;
        int cr = f >> 2;
        int t4 = (f & 3) * 4;
        float4 v;
        v.x = st[cr*17 + t4 + 0];
        v.y = st[cr*17 + t4 + 1];
        v.z = st[cr*17 + t4 + 2];
        v.w = st[cr*17 + t4 + 3];
        *(float4*)&g_peakT[((size_t)(b*C_ + cr))*T_ + tb + t4] = v;
    }
}

// ---------------- fused front GEMM: block 128x96, 8 warps, warp 32x48 ----------------
#define AS1 36
#define BS1 104
#define A_BUF (128*AS1)
#define B_BUF (32*BS1)

__global__ __launch_bounds__(256) void gemm1_kernel() {
    extern __shared__ float smem[];
    float* AsBuf = smem;
    float* BsBuf = smem + 2*A_BUF;

    int tid = threadIdx.x;
    int warp = tid >> 5, lane = tid & 31;
    int bm = blockIdx.x * 128;
    int bny = blockIdx.y;                // 0..5
    int bn = bny * 96;
    int cls = bny >> 1;                  // 0:k 1:v 2:r
    int nloc = (bny & 1) * 96;
    int wm = (warp >> 1) * 32;
    int wn = (warp & 1) * 48;
    int gid = lane >> 2, tig = lane & 3;

    const float* Abase = g_A + (size_t)bm * 384;
    float acc[2][6][4] = {};

    float4 pa[4], pb[3];
#pragma unroll
    for (int q = 0; q < 4; q++) {
        int f = tid + q*256;
        pa[q] = *(const float4*)&Abase[(size_t)(f >> 3)*384 + (f & 7)*4];
    }
#pragma unroll
    for (int q = 0; q < 3; q++) {
        int f = tid + q*256;
        pb[q] = *(const float4*)&g_Wf[(size_t)(f/24)*576 + bn + (f%24)*4];
    }
#pragma unroll
    for (int q = 0; q < 4; q++) {
        int f = tid + q*256;
        *(float4*)&AsBuf[(f >> 3)*AS1 + (f & 7)*4] = pa[q];
    }
#pragma unroll
    for (int q = 0; q < 3; q++) {
        int f = tid + q*256;
        *(float4*)&BsBuf[(f/24)*BS1 + (f%24)*4] = pb[q];
    }
    __syncthreads();

    for (int kc = 0; kc < 12; kc++) {
        int cur = kc & 1;
        if (kc < 11) {
            int k0 = (kc + 1) * 32;
#pragma unroll
            for (int q = 0; q < 4; q++) {
                int f = tid + q*256;
                pa[q] = *(const float4*)&Abase[(size_t)(f >> 3)*384 + k0 + (f & 7)*4];
            }
#pragma unroll
            for (int q = 0; q < 3; q++) {
                int f = tid + q*256;
                pb[q] = *(const float4*)&g_Wf[(size_t)(k0 + f/24)*576 + bn + (f%24)*4];
            }
        }
        const float* as = AsBuf + cur*A_BUF;
        const float* bs = BsBuf + cur*B_BUF;
#pragma unroll
        for (int ks = 0; ks < 4; ks++) {
            int kk0 = ks * 8;
            unsigned afr[2][4], bfr[6][2];
#pragma unroll
            for (int mi = 0; mi < 2; mi++) {
                int rbase = (wm + mi*16 + gid) * AS1;
                afr[mi][0] = __float_as_uint(as[rbase + kk0 + tig]);
                afr[mi][1] = __float_as_uint(as[rbase + 8*AS1 + kk0 + tig]);
                afr[mi][2] = __float_as_uint(as[rbase + kk0 + tig + 4]);
                afr[mi][3] = __float_as_uint(as[rbase + 8*AS1 + kk0 + tig + 4]);
            }
#pragma unroll
            for (int ni = 0; ni < 6; ni++) {
                int col = wn + ni*8 + gid;
                bfr[ni][0] = __float_as_uint(bs[(kk0 + tig)*BS1 + col]);
                bfr[ni][1] = __float_as_uint(bs[(kk0 + tig + 4)*BS1 + col]);
            }
#pragma unroll
            for (int mi = 0; mi < 2; mi++)
#pragma unroll
                for (int ni = 0; ni < 6; ni++)
                    mma8(acc[mi][ni], afr[mi][0], afr[mi][1], afr[mi][2], afr[mi][3],
                         bfr[ni][0], bfr[ni][1]);
        }
        if (kc < 11) {
            __syncthreads();
            int nxt = cur ^ 1;
#pragma unroll
            for (int q = 0; q < 4; q++) {
                int f = tid + q*256;
                *(float4*)&AsBuf[nxt*A_BUF + (f >> 3)*AS1 + (f & 7)*4] = pa[q];
            }
#pragma unroll
            for (int q = 0; q < 3; q++) {
                int f = tid + q*256;
                *(float4*)&BsBuf[nxt*B_BUF + (f/24)*BS1 + (f%24)*4] = pb[q];
            }
            __syncthreads();
        }
    }

    if (cls == 2) {
#pragma unroll
        for (int mi = 0; mi < 2; mi++) {
            int r0 = bm + wm + mi*16 + gid;
#pragma unroll
            for (int ni = 0; ni < 6; ni++) {
                int c0 = nloc + wn + ni*8 + tig*2;
                float v0 = 1.f/(1.f+expf(-acc[mi][ni][0]));
                float v1 = 1.f/(1.f+expf(-acc[mi][ni][1]));
                float v2 = 1.f/(1.f+expf(-acc[mi][ni][2]));
                float v3 = 1.f/(1.f+expf(-acc[mi][ni][3]));
                *(float2*)&g_sr[(size_t)r0*C_ + c0]     = make_float2(v0, v1);
                *(float2*)&g_sr[(size_t)(r0+8)*C_ + c0] = make_float2(v2, v3);
            }
        }
        return;
    }

    // k and v: transpose stage st[channel][token], stride 132
    __syncthreads();
    float* st = smem;
#pragma unroll
    for (int mi = 0; mi < 2; mi++) {
        int r = wm + mi*16 + gid;
#pragma unroll
        for (int ni = 0; ni < 6; ni++) {
            int cc = wn + ni*8 + tig*2;
            st[cc*132 + r]         = acc[mi][ni][0];
            st[(cc+1)*132 + r]     = acc[mi][ni][1];
            st[cc*132 + r + 8]     = acc[mi][ni][2];
            st[(cc+1)*132 + r + 8] = acc[mi][ni][3];
        }
    }
    __syncthreads();
    float* dst = (cls == 0) ? g_kT : g_vT;
    int bb = bm >> 12, trow = bm & 4095;
#pragma unroll
    for (int q = 0; q < 12; q++) {
        int f = q*256 + tid;
        int cr = f >> 5;
        int t4 = (f & 31) * 4;
        float4 v = *(const float4*)&st[cr*132 + t4];
        *(float4*)&dst[((size_t)(bb*C_ + nloc + cr))*T_ + trow + t4] = v;
    }
}

// ---------------- bidirectional WKV scan (v = vT + peakT on load) ----------------
struct Agg { float a, b, dl; };
__device__ __forceinline__ Agg combine(Agg p, Agg s) {
    Agg r;
    r.a  = fmaf(s.dl, p.a, s.a);
    r.b  = fmaf(s.dl, p.b, s.b);
    r.dl = p.dl * s.dl;
    return r;
}
__device__ __forceinline__ Agg shfl_up_agg(Agg v, int off) {
    Agg r;
    r.a  = __shfl_up_sync(0xffffffffu, v.a,  off);
    r.b  = __shfl_up_sync(0xffffffffu, v.b,  off);
    r.dl = __shfl_up_sync(0xffffffffu, v.dl, off);
    return r;
}
__device__ __forceinline__ Agg shfl_dn_agg(Agg v, int off) {
    Agg r;
    r.a  = __shfl_down_sync(0xffffffffu, v.a,  off);
    r.b  = __shfl_down_sync(0xffffffffu, v.b,  off);
    r.dl = __shfl_down_sync(0xffffffffu, v.dl, off);
    return r;
}

__global__ __launch_bounds__(256) void wkv_kernel(const float* __restrict__ sd,
                                                  const float* __restrict__ sf) {
    __shared__ float eks[4352];
    __shared__ float vvs[4352];
    __shared__ Agg warpAgg[8];
    __shared__ Agg warpPre[8];
    int bc = blockIdx.x;
    int c = bc % C_;
    float w  = sd[c] * (1.0f / T_);
    float u  = sf[c] * (1.0f / T_);
    float d  = expf(-w);
    float eu = expf(u);
    float d2 = d*d, d4 = d2*d2, d8 = d4*d4, d16 = d8*d8;
    int tid = threadIdx.x;
    int lane = tid & 31, wid = tid >> 5;
    const float4* kp4 = (const float4*)(g_kT + (size_t)bc * T_);
    const float4* vp4 = (const float4*)(g_vT + (size_t)bc * T_);
    const float4* pk4 = (const float4*)(g_peakT + (size_t)bc * T_);

#pragma unroll
    for (int q = 0; q < 4; q++) {
        int idx = tid + q*256;
        float4 kv = kp4[idx];
        float4 v4 = vp4[idx];
        float4 p4 = pk4[idx];
        v4.x += p4.x; v4.y += p4.y; v4.z += p4.z; v4.w += p4.w;
        int t = idx * 4;
        int base = t + (t >> 4);
        eks[base+0] = expf(kv.x); eks[base+1] = expf(kv.y);
        eks[base+2] = expf(kv.z); eks[base+3] = expf(kv.w);
        vvs[base+0] = v4.x; vvs[base+1] = v4.y;
        vvs[base+2] = v4.z; vvs[base+3] = v4.w;
    }
    __syncthreads();

    float ek[16], vv[16];
    int rb = 17 * tid;
#pragma unroll
    for (int i = 0; i < 16; i++) { ek[i] = eks[rb + i]; vv[i] = vvs[rb + i]; }

    Agg ag; ag.a = 0.f; ag.b = 0.f; ag.dl = d16;
#pragma unroll
    for (int i = 0; i < 16; i++) {
        ag.a = fmaf(d, ag.a, ek[i]);
        ag.b = fmaf(d, ag.b, ek[i]*vv[i]);
    }
    Agg inc = ag;
#pragma unroll
    for (int off = 1; off < 32; off <<= 1) {
        Agg o = shfl_up_agg(inc, off);
        if (lane >= off) inc = combine(o, inc);
    }
    if (lane == 31) warpAgg[wid] = inc;
    __syncthreads();
    if (tid == 0) {
        Agg run; run.a = 0.f; run.b = 0.f; run.dl = 1.f;
        for (int i = 0; i < 8; i++) { warpPre[i] = run; run = combine(run, warpAgg[i]); }
    }
    __syncthreads();
    Agg pl = shfl_up_agg(inc, 1);
    Agg ex = warpPre[wid];
    if (lane > 0) ex = combine(ex, pl);

    float af = ex.a, bf = ex.b;
    float saf[16], sbf[16];
#pragma unroll
    for (int i = 0; i < 16; i++) {
        saf[i] = af; sbf[i] = bf;
        af = fmaf(d, af, ek[i]);
        bf = fmaf(d, bf, ek[i]*vv[i]);
    }
    __syncthreads();

    Agg bg; bg.a = 0.f; bg.b = 0.f; bg.dl = d16;
#pragma unroll
    for (int i = 15; i >= 0; i--) {
        bg.a = fmaf(d, bg.a, ek[i]);
        bg.b = fmaf(d, bg.b, ek[i]*vv[i]);
    }
    Agg binc = bg;
#pragma unroll
    for (int off = 1; off < 32; off <<= 1) {
        Agg o = shfl_dn_agg(binc, off);
        if (lane < 32 - off) binc = combine(o, binc);
    }
    if (lane == 0) warpAgg[wid] = binc;
    __syncthreads();
    if (tid == 0) {
        Agg run; run.a = 0.f; run.b = 0.f; run.dl = 1.f;
        for (int i = 7; i >= 0; i--) { warpPre[i] = run; run = combine(run, warpAgg[i]); }
    }
    __syncthreads();
    Agg bpl = shfl_dn_agg(binc, 1);
    Agg bex = warpPre[wid];
    if (lane < 31) bex = combine(bex, bpl);

    float ab = bex.a, bb = bex.b;
#pragma unroll
    for (int i = 15; i >= 0; i--) {
        float es  = eu * ek[i];
        float num = sbf[i] + bb + es * vv[i];
        float den = saf[i] + ab + es;
        vvs[rb + i] = num / den;
        ab = fmaf(d, ab, ek[i]);
        bb = fmaf(d, bb, ek[i]*vv[i]);
    }
    __syncthreads();

    float4* yp4 = (float4*)(g_yT + (size_t)bc * T_);
#pragma unroll
    for (int q = 0; q < 4; q++) {
        int idx = tid + q*256;
        int t = idx * 4;
        int base = t + (t >> 4);
        yp4[idx] = make_float4(vvs[base+0], vvs[base+1], vvs[base+2], vvs[base+3]);
    }
}

// ---------------- output GEMM (1x tf32): out = (sr .* y) @ Wo ----------------
#define A2_STRIDE 197
#define BS_STRIDE 72

__global__ __launch_bounds__(128) void gemm2_kernel(float* __restrict__ out) {
    __shared__ unsigned As2[32 * A2_STRIDE];
    __shared__ unsigned Bs2[2][32 * BS_STRIDE];

    int tid = threadIdx.x;
    int warp = tid >> 5, lane = tid & 31;
    int gid = lane >> 2, tig = lane & 3;
    int bm = blockIdx.x * 32;
    int bn = blockIdx.y * 64;
    int wm = (warp >> 1) * 16;
    int wn = (warp & 1) * 32;
    int bb = bm >> 12, trow = bm & 4095;

#pragma unroll
    for (int q = 0; q < 12; q++) {
        int f = q*128 + tid;
        int row = f >> 3;
        int t4 = (f & 7) * 4;
        float4 v = *(const float4*)&g_yT[((size_t)(bb*C_ + row))*T_ + trow + t4];
        As2[(t4+0)*A2_STRIDE + row] = __float_as_uint(v.x);
        As2[(t4+1)*A2_STRIDE + row] = __float_as_uint(v.y);
        As2[(t4+2)*A2_STRIDE + row] = __float_as_uint(v.z);
        As2[(t4+3)*A2_STRIDE + row] = __float_as_uint(v.w);
    }
    __syncthreads();
#pragma unroll
    for (int q = 0; q < 12; q++) {
        int f = q*128 + tid;
        int t = f / 48, c4 = (f % 48) * 4;
        float4 s = *(const float4*)&g_sr[((size_t)(bm + t))*C_ + c4];
        unsigned* p = &As2[t*A2_STRIDE + c4];
        p[0] = f2tf32(__uint_as_float(p[0]) * s.x);
        p[1] = f2tf32(__uint_as_float(p[1]) * s.y);
        p[2] = f2tf32(__uint_as_float(p[2]) * s.z);
        p[3] = f2tf32(__uint_as_float(p[3]) * s.w);
    }

    int br = tid >> 4;
    int bc = (tid & 15) * 4;
    float acc[4][4] = {};

    float4 pb[4];
#pragma unroll
    for (int i = 0; i < 4; i++)
        pb[i] = *(const float4*)&g_Wo[(size_t)(br + i*8)*C_ + bn + bc];
#pragma unroll
    for (int i = 0; i < 4; i++)
        *(float4*)&Bs2[0][(br + i*8)*BS_STRIDE + bc] = pb[i];
    __syncthreads();

    for (int kc = 0; kc < 6; kc++) {
        int cur = kc & 1;
        if (kc < 5) {
            int k0 = (kc + 1) * 32;
#pragma unroll
            for (int i = 0; i < 4; i++)
                pb[i] = *(const float4*)&g_Wo[(size_t)(k0 + br + i*8)*C_ + bn + bc];
        }
        const unsigned* bs = Bs2[cur];
        int k0 = kc * 32;
#pragma unroll
        for (int ks = 0; ks < 4; ks++) {
            int kk = k0 + ks*8;
            unsigned a0 = As2[(wm+gid)*A2_STRIDE + kk + tig];
            unsigned a1 = As2[(wm+gid+8)*A2_STRIDE + kk + tig];
            unsigned a2 = As2[(wm+gid)*A2_STRIDE + kk + tig + 4];
            unsigned a3 = As2[(wm+gid+8)*A2_STRIDE + kk + tig + 4];
#pragma unroll
            for (int ni = 0; ni < 4; ni++) {
                int col = wn + ni*8 + gid;
                unsigned b0 = bs[(ks*8 + tig)*BS_STRIDE + col];
                unsigned b1 = bs[(ks*8 + tig + 4)*BS_STRIDE + col];
                mma8(acc[ni], a0, a1, a2, a3, b0, b1);
            }
        }
        if (kc < 5) {
            __syncthreads();
            int nxt = cur ^ 1;
#pragma unroll
            for (int i = 0; i < 4; i++)
                *(float4*)&Bs2[nxt][(br + i*8)*BS_STRIDE + bc] = pb[i];
            __syncthreads();
        }
    }

    int r0 = bm + wm + gid;
#pragma unroll
    for (int ni = 0; ni < 4; ni++) {
        int c0 = bn + wn + ni*8 + tig*2;
        *(float2*)&out[(size_t)r0*C_ + c0]     = make_float2(acc[ni][0], acc[ni][1]);
        *(float2*)&out[(size_t)(r0+8)*C_ + c0] = make_float2(acc[ni][2], acc[ni][3]);
    }
}

// ---------------- launch: prep_w -> { prep_A -> gemm1 } || { convP -> peak } -> wkv -> gemm2
#define GEMM1_SMEM ((2*A_BUF + 2*B_BUF) * 4)

namespace {
struct SideStream {
    cudaStream_t s1;
    cudaEvent_t evFork, evJoin;
    SideStream() {
        cudaStreamCreateWithFlags(&s1, cudaStreamNonBlocking);
        cudaEventCreateWithFlags(&evFork, cudaEventDisableTiming);
        cudaEventCreateWithFlags(&evJoin, cudaEventDisableTiming);
    }
};
SideStream g_ss;
}

extern "C" void kernel_launch(void* const* d_in, const int* in_sizes, int n_in,
                              void* d_out, int out_size) {
    const float* x = (const float*)d_in[0];
    int base = (in_sizes[1] == 1) ? 3 : 1;
    const float* mk    = (const float*)d_in[base + 0];
    const float* mv    = (const float*)d_in[base + 1];
    const float* mr    = (const float*)d_in[base + 2];
    const float* Wk    = (const float*)d_in[base + 3];
    const float* Wv    = (const float*)d_in[base + 4];
    const float* Wr    = (const float*)d_in[base + 5];
    const float* Wo    = (const float*)d_in[base + 6];
    const float* sd    = (const float*)d_in[base + 7];
    const float* sf    = (const float*)d_in[base + 8];
    const float* cvw   = (const float*)d_in[base + 9];
    const float* cvb   = (const float*)d_in[base + 10];
    const float* bns_v = (const float*)d_in[base + 11];
    const float* bnb_v = (const float*)d_in[base + 12];
    const float* chw   = (const float*)d_in[base + 13];
    const float* chb   = (const float*)d_in[base + 14];
    const float* bns_h = (const float*)d_in[base + 15];
    const float* bnb_h = (const float*)d_in[base + 16];

    cudaFuncSetAttribute(gemm1_kernel, cudaFuncAttributeMaxDynamicSharedMemorySize, GEMM1_SMEM);

    // weights (needed by both branches)
    prepw_kernel<<<688, 384>>>(mk, mv, mr, Wk, Wv, Wr, Wo, cvw, chw);

    // fork
    cudaEventRecord(g_ss.evFork, 0);
    cudaStreamWaitEvent(g_ss.s1, g_ss.evFork, 0);

    // side: convP -> peak (produces g_peakT, needed only by wkv)
    convP_kernel<<<1024, 256, 0, g_ss.s1>>>(x);
    peak_kernel<<<512, 384, 0, g_ss.s1>>>(x, cvb, bns_v, bnb_v, chb, bns_h, bnb_h);
    cudaEventRecord(g_ss.evJoin, g_ss.s1);

    // main: prep_A -> gemm1 (single full launch, no peak dependency)
    prepa_kernel<<<512, 384>>>(x);
    gemm1_kernel<<<dim3(64, 6), 256, GEMM1_SMEM>>>();

    // join before wkv (needs peakT + kT + vT)
    cudaStreamWaitEvent(0, g_ss.evJoin, 0);
    wkv_kernel<<<B_*C_, 256>>>(sd, sf);
    gemm2_kernel<<<dim3(256, 3), 128>>>((float*)d_out);
}